// round 1
// baseline (speedup 1.0000x reference)
#include <cuda_runtime.h>
#include <math.h>

#define BB 2
#define SS 2048
#define EE 768
#define HH 12
#define DD 64
#define MM (BB*SS)      /* 4096 rows */
#define FF (4*EE)       /* 3072 */

// ---------------- scratch (device globals; no allocation allowed) ----------------
__device__ float g_y  [MM*EE];
__device__ float g_q  [MM*EE];
__device__ float g_k  [MM*EE];
__device__ float g_v  [MM*EE];
__device__ float g_ctx[MM*EE];
__device__ float g_y2 [MM*EE];
__device__ float g_z  [MM*EE];
__device__ float g_h  [MM*FF];

// ---------------- LayerNorm: one block per row, 256 threads, E=768=3*256 --------
__global__ void ln_kernel(const float* __restrict__ x, const float* __restrict__ gw,
                          const float* __restrict__ bw, float* __restrict__ out) {
    int row = blockIdx.x;
    int t = threadIdx.x;
    const float* xr = x + (size_t)row * EE;
    float v0 = xr[t], v1 = xr[t + 256], v2 = xr[t + 512];
    __shared__ float red[256];
    red[t] = v0 + v1 + v2;
    __syncthreads();
    #pragma unroll
    for (int o = 128; o > 0; o >>= 1) {
        if (t < o) red[t] += red[t + o];
        __syncthreads();
    }
    float mean = red[0] * (1.0f / EE);
    __syncthreads();
    float d0 = v0 - mean, d1 = v1 - mean, d2 = v2 - mean;
    red[t] = d0*d0 + d1*d1 + d2*d2;
    __syncthreads();
    #pragma unroll
    for (int o = 128; o > 0; o >>= 1) {
        if (t < o) red[t] += red[t + o];
        __syncthreads();
    }
    float rstd = rsqrtf(red[0] * (1.0f / EE) + 1e-5f);
    float* orow = out + (size_t)row * EE;
    orow[t]       = d0 * rstd * gw[t]       + bw[t];
    orow[t + 256] = d1 * rstd * gw[t + 256] + bw[t + 256];
    orow[t + 512] = d2 * rstd * gw[t + 512] + bw[t + 512];
}

// ---------------- SGEMM: C[M,N] = A[M,K] @ W[K,N] + bias (+res) (opt gelu) ------
// 128x128 tile, BK=8, 256 threads, 8x8 micro-tile per thread.
// All dims used here are multiples of the tile sizes (no bounds checks).
template<bool GELU, bool RES>
__global__ void __launch_bounds__(256)
sgemm_kernel(const float* __restrict__ A, const float* __restrict__ W,
             const float* __restrict__ bias, const float* __restrict__ res,
             float* __restrict__ C, int N, int K) {
    __shared__ float As[8][132];   // padded: avoids store bank conflicts
    __shared__ float Bs[8][128];

    int tid = threadIdx.x;
    int row0 = blockIdx.y * 128;
    int col0 = blockIdx.x * 128;

    // A tile loader: 128 rows x 8 cols; one float4 per thread
    int arow = tid >> 1;
    int acol = (tid & 1) * 4;
    // W tile loader: 8 rows x 128 cols; one float4 per thread
    int wrow = tid >> 5;
    int wcol = (tid & 31) * 4;

    int tx = tid & 15;     // 0..15 -> 8 cols each
    int ty = tid >> 4;     // 0..15 -> 8 rows each

    float acc[8][8];
    #pragma unroll
    for (int i = 0; i < 8; i++)
        #pragma unroll
        for (int j = 0; j < 8; j++) acc[i][j] = 0.0f;

    const float* Aptr = A + (size_t)(row0 + arow) * K + acol;
    const float* Wptr = W + (size_t)wrow * N + col0 + wcol;

    for (int k0 = 0; k0 < K; k0 += 8) {
        float4 a4 = *(const float4*)(Aptr + k0);
        As[acol + 0][arow] = a4.x;
        As[acol + 1][arow] = a4.y;
        As[acol + 2][arow] = a4.z;
        As[acol + 3][arow] = a4.w;
        float4 w4 = *(const float4*)(Wptr + (size_t)k0 * N);
        *(float4*)&Bs[wrow][wcol] = w4;
        __syncthreads();

        #pragma unroll
        for (int kk = 0; kk < 8; kk++) {
            float4 a0 = *(const float4*)&As[kk][ty * 8];
            float4 a1 = *(const float4*)&As[kk][ty * 8 + 4];
            float4 b0 = *(const float4*)&Bs[kk][tx * 8];
            float4 b1 = *(const float4*)&Bs[kk][tx * 8 + 4];
            float aa[8] = {a0.x, a0.y, a0.z, a0.w, a1.x, a1.y, a1.z, a1.w};
            float bb[8] = {b0.x, b0.y, b0.z, b0.w, b1.x, b1.y, b1.z, b1.w};
            #pragma unroll
            for (int i = 0; i < 8; i++)
                #pragma unroll
                for (int j = 0; j < 8; j++)
                    acc[i][j] += aa[i] * bb[j];
        }
        __syncthreads();
    }

    #pragma unroll
    for (int i = 0; i < 8; i++) {
        int row = row0 + ty * 8 + i;
        #pragma unroll
        for (int j = 0; j < 8; j++) {
            int col = col0 + tx * 8 + j;
            float v = acc[i][j] + bias[col];
            if (RES) v += res[(size_t)row * N + col];
            if (GELU) v = v * 0.5f * (1.0f + erff(v * 0.70710678118654752f));
            C[(size_t)row * N + col] = v;
        }
    }
}

// ---------------- Attention: one block per (b, h, q-row), 256 threads -----------
__global__ void attn_kernel(const float* __restrict__ q, const float* __restrict__ k,
                            const float* __restrict__ v, float* __restrict__ ctx) {
    int qi = blockIdx.x;
    int h  = blockIdx.y;
    int b  = blockIdx.z;
    int tid = threadIdx.x;

    __shared__ float sq[DD];
    __shared__ float sc[SS];
    __shared__ float red[256];

    const float* qrow = q + ((size_t)(b * SS + qi) * EE) + h * DD;
    if (tid < DD) sq[tid] = qrow[tid];
    __syncthreads();

    const float scale = rsqrtf((float)EE);
    const float* kbase = k + (size_t)b * SS * EE + h * DD;
    const float* vbase = v + (size_t)b * SS * EE + h * DD;

    // scores: each thread owns keys tid, tid+256, ... (8 keys), 8 parallel chains
    float sacc[8];
    #pragma unroll
    for (int r = 0; r < 8; r++) sacc[r] = 0.0f;
    #pragma unroll
    for (int d = 0; d < DD; d++) {
        float qd = sq[d];
        #pragma unroll
        for (int r = 0; r < 8; r++)
            sacc[r] += qd * kbase[(size_t)(tid + r * 256) * EE + d];
    }
    float lmax = -1e30f;
    #pragma unroll
    for (int r = 0; r < 8; r++) {
        float s = sacc[r] * scale;
        sc[tid + r * 256] = s;
        lmax = fmaxf(lmax, s);
    }

    red[tid] = lmax;
    __syncthreads();
    #pragma unroll
    for (int o = 128; o > 0; o >>= 1) {
        if (tid < o) red[tid] = fmaxf(red[tid], red[tid + o]);
        __syncthreads();
    }
    float mx = red[0];
    __syncthreads();

    float lsum = 0.0f;
    #pragma unroll
    for (int r = 0; r < 8; r++) {
        int j = tid + r * 256;
        float e = __expf(sc[j] - mx);
        sc[j] = e;
        lsum += e;
    }
    red[tid] = lsum;
    __syncthreads();
    #pragma unroll
    for (int o = 128; o > 0; o >>= 1) {
        if (tid < o) red[tid] += red[tid + o];
        __syncthreads();
    }
    float inv = 1.0f / red[0];
    __syncthreads();

    // ctx: 256 threads = 64 dims x 4 key-quarters; 4 ILP accumulator chains
    int d = tid & 63;
    int g = tid >> 6;
    const float* vd = vbase + d;
    float a0 = 0.f, a1 = 0.f, a2 = 0.f, a3 = 0.f;
    int j0 = g * 512;
    for (int j = j0; j < j0 + 512; j += 4) {
        a0 += sc[j + 0] * vd[(size_t)(j + 0) * EE];
        a1 += sc[j + 1] * vd[(size_t)(j + 1) * EE];
        a2 += sc[j + 2] * vd[(size_t)(j + 2) * EE];
        a3 += sc[j + 3] * vd[(size_t)(j + 3) * EE];
    }
    red[tid] = (a0 + a1) + (a2 + a3);
    __syncthreads();
    if (g == 0) {
        float r = red[d] + red[d + 64] + red[d + 128] + red[d + 192];
        ctx[((size_t)(b * SS + qi) * EE) + h * DD + d] = r * inv;
    }
}

// ---------------- launch ---------------------------------------------------------
extern "C" void kernel_launch(void* const* d_in, const int* in_sizes, int n_in,
                              void* d_out, int out_size) {
    (void)in_sizes; (void)n_in; (void)out_size;
    const float* x     = (const float*)d_in[0];
    const float* ln1_g = (const float*)d_in[1];
    const float* ln1_b = (const float*)d_in[2];
    const float* wq    = (const float*)d_in[3];
    const float* bq    = (const float*)d_in[4];
    const float* wk    = (const float*)d_in[5];
    const float* bk    = (const float*)d_in[6];
    const float* wv    = (const float*)d_in[7];
    const float* bv    = (const float*)d_in[8];
    const float* wo    = (const float*)d_in[9];
    const float* bo    = (const float*)d_in[10];
    const float* w1    = (const float*)d_in[11];
    const float* b1    = (const float*)d_in[12];
    const float* w2    = (const float*)d_in[13];
    const float* b2    = (const float*)d_in[14];
    const float* ln2_g = (const float*)d_in[15];
    const float* ln2_b = (const float*)d_in[16];
    float* out = (float*)d_out;

    float *y, *q, *k, *v, *ctx, *y2, *z, *hbuf;
    cudaGetSymbolAddress((void**)&y,    g_y);
    cudaGetSymbolAddress((void**)&q,    g_q);
    cudaGetSymbolAddress((void**)&k,    g_k);
    cudaGetSymbolAddress((void**)&v,    g_v);
    cudaGetSymbolAddress((void**)&ctx,  g_ctx);
    cudaGetSymbolAddress((void**)&y2,   g_y2);
    cudaGetSymbolAddress((void**)&z,    g_z);
    cudaGetSymbolAddress((void**)&hbuf, g_h);

    dim3 blk(256);

    // 1. y = LN1(x)
    ln_kernel<<<MM, blk>>>(x, ln1_g, ln1_b, y);

    // 2. q,k,v = y @ {wq,wk,wv} + bias
    dim3 g_e(EE / 128, MM / 128);
    sgemm_kernel<false, false><<<g_e, blk>>>(y, wq, bq, nullptr, q, EE, EE);
    sgemm_kernel<false, false><<<g_e, blk>>>(y, wk, bk, nullptr, k, EE, EE);
    sgemm_kernel<false, false><<<g_e, blk>>>(y, wv, bv, nullptr, v, EE, EE);

    // 3. attention
    dim3 g_attn(SS, HH, BB);
    attn_kernel<<<g_attn, blk>>>(q, k, v, ctx);

    // 4. y2 = x + ctx @ wo + bo
    sgemm_kernel<false, true><<<g_e, blk>>>(ctx, wo, bo, x, y2, EE, EE);

    // 5. z = LN2(y2)
    ln_kernel<<<MM, blk>>>(y2, ln2_g, ln2_b, z);

    // 6. h = gelu(z @ w1 + b1)
    dim3 g_ff(FF / 128, MM / 128);
    sgemm_kernel<true, false><<<g_ff, blk>>>(z, w1, b1, nullptr, hbuf, FF, EE);

    // 7. out = y2 + h @ w2 + b2
    sgemm_kernel<false, true><<<g_e, blk>>>(hbuf, w2, b2, y2, out, EE, FF);
}

// round 2
// speedup vs baseline: 9.2829x; 9.2829x over previous
#include <cuda_runtime.h>
#include <math.h>

#define BB 2
#define SS 2048
#define EE 768
#define HH 12
#define DD 64
#define MM (BB*SS)      /* 4096 rows */
#define FF (4*EE)       /* 3072 */
#define BH (BB*HH)      /* 24 */

// ---------------- scratch (device globals; no allocation allowed) ----------------
__device__ float g_y  [MM*EE];
__device__ float g_q  [MM*EE];
__device__ float g_k  [MM*EE];
__device__ float g_v  [MM*EE];
__device__ float g_ctx[MM*EE];
__device__ float g_y2 [MM*EE];
__device__ float g_z  [MM*EE];
__device__ float g_h  [MM*FF];
__device__ float g_s  [(size_t)BH*SS*SS];   // 402 MB attention scores

// ---------------- LayerNorm: one block per row, 256 threads, E=768=3*256 --------
__global__ void ln_kernel(const float* __restrict__ x, const float* __restrict__ gw,
                          const float* __restrict__ bw, float* __restrict__ out) {
    int row = blockIdx.x;
    int t = threadIdx.x;
    const float* xr = x + (size_t)row * EE;
    float v0 = xr[t], v1 = xr[t + 256], v2 = xr[t + 512];
    __shared__ float red[256];
    red[t] = v0 + v1 + v2;
    __syncthreads();
    #pragma unroll
    for (int o = 128; o > 0; o >>= 1) {
        if (t < o) red[t] += red[t + o];
        __syncthreads();
    }
    float mean = red[0] * (1.0f / EE);
    __syncthreads();
    float d0 = v0 - mean, d1 = v1 - mean, d2 = v2 - mean;
    red[t] = d0*d0 + d1*d1 + d2*d2;
    __syncthreads();
    #pragma unroll
    for (int o = 128; o > 0; o >>= 1) {
        if (t < o) red[t] += red[t + o];
        __syncthreads();
    }
    float rstd = rsqrtf(red[0] * (1.0f / EE) + 1e-5f);
    float* orow = out + (size_t)row * EE;
    orow[t]       = d0 * rstd * gw[t]       + bw[t];
    orow[t + 256] = d1 * rstd * gw[t + 256] + bw[t + 256];
    orow[t + 512] = d2 * rstd * gw[t + 512] + bw[t + 512];
}

// ---------------- SGEMM: C[M,N] = A[M,K] @ W[K,N] + bias (+res) (opt gelu) ------
template<bool GELU, bool RES>
__global__ void __launch_bounds__(256)
sgemm_kernel(const float* __restrict__ A, const float* __restrict__ W,
             const float* __restrict__ bias, const float* __restrict__ res,
             float* __restrict__ C, int N, int K) {
    __shared__ float As[8][132];
    __shared__ float Bs[8][128];

    int tid = threadIdx.x;
    int row0 = blockIdx.y * 128;
    int col0 = blockIdx.x * 128;

    int arow = tid >> 1;
    int acol = (tid & 1) * 4;
    int wrow = tid >> 5;
    int wcol = (tid & 31) * 4;

    int tx = tid & 15;
    int ty = tid >> 4;

    float acc[8][8];
    #pragma unroll
    for (int i = 0; i < 8; i++)
        #pragma unroll
        for (int j = 0; j < 8; j++) acc[i][j] = 0.0f;

    const float* Aptr = A + (size_t)(row0 + arow) * K + acol;
    const float* Wptr = W + (size_t)wrow * N + col0 + wcol;

    for (int k0 = 0; k0 < K; k0 += 8) {
        float4 a4 = *(const float4*)(Aptr + k0);
        As[acol + 0][arow] = a4.x;
        As[acol + 1][arow] = a4.y;
        As[acol + 2][arow] = a4.z;
        As[acol + 3][arow] = a4.w;
        float4 w4 = *(const float4*)(Wptr + (size_t)k0 * N);
        *(float4*)&Bs[wrow][wcol] = w4;
        __syncthreads();

        #pragma unroll
        for (int kk = 0; kk < 8; kk++) {
            float4 a0 = *(const float4*)&As[kk][ty * 8];
            float4 a1 = *(const float4*)&As[kk][ty * 8 + 4];
            float4 b0 = *(const float4*)&Bs[kk][tx * 8];
            float4 b1 = *(const float4*)&Bs[kk][tx * 8 + 4];
            float aa[8] = {a0.x, a0.y, a0.z, a0.w, a1.x, a1.y, a1.z, a1.w};
            float bb[8] = {b0.x, b0.y, b0.z, b0.w, b1.x, b1.y, b1.z, b1.w};
            #pragma unroll
            for (int i = 0; i < 8; i++)
                #pragma unroll
                for (int j = 0; j < 8; j++)
                    acc[i][j] += aa[i] * bb[j];
        }
        __syncthreads();
    }

    #pragma unroll
    for (int i = 0; i < 8; i++) {
        int row = row0 + ty * 8 + i;
        #pragma unroll
        for (int j = 0; j < 8; j++) {
            int col = col0 + tx * 8 + j;
            float v = acc[i][j] + bias[col];
            if (RES) v += res[(size_t)row * N + col];
            if (GELU) v = v * 0.5f * (1.0f + erff(v * 0.70710678118654752f));
            C[(size_t)row * N + col] = v;
        }
    }
}

// ---------------- Scores: S[bh][q][k] = (Q_bh @ K_bh^T) / sqrt(E) ---------------
// Batched 128x128-tile GEMM with both operands K-major (NT gemm). BK=8, D=64.
__global__ void __launch_bounds__(256)
score_kernel(const float* __restrict__ q, const float* __restrict__ k,
             float* __restrict__ S) {
    int bh = blockIdx.z;
    int b = bh / HH, h = bh % HH;
    const float* qb = q + (size_t)b * SS * EE + h * DD;
    const float* kb = k + (size_t)b * SS * EE + h * DD;
    float* Sb = S + (size_t)bh * SS * SS;

    __shared__ float As[8][132];
    __shared__ float Bs[8][132];

    int tid = threadIdx.x;
    int row0 = blockIdx.y * 128;
    int col0 = blockIdx.x * 128;

    int lrow = tid >> 1;
    int lcol = (tid & 1) * 4;
    int tx = tid & 15;
    int ty = tid >> 4;

    float acc[8][8];
    #pragma unroll
    for (int i = 0; i < 8; i++)
        #pragma unroll
        for (int j = 0; j < 8; j++) acc[i][j] = 0.0f;

    const float* Ap = qb + (size_t)(row0 + lrow) * EE + lcol;
    const float* Bp = kb + (size_t)(col0 + lrow) * EE + lcol;

    #pragma unroll
    for (int k0 = 0; k0 < DD; k0 += 8) {
        float4 a4 = *(const float4*)(Ap + k0);
        As[lcol + 0][lrow] = a4.x;
        As[lcol + 1][lrow] = a4.y;
        As[lcol + 2][lrow] = a4.z;
        As[lcol + 3][lrow] = a4.w;
        float4 b4 = *(const float4*)(Bp + k0);
        Bs[lcol + 0][lrow] = b4.x;
        Bs[lcol + 1][lrow] = b4.y;
        Bs[lcol + 2][lrow] = b4.z;
        Bs[lcol + 3][lrow] = b4.w;
        __syncthreads();

        #pragma unroll
        for (int kk = 0; kk < 8; kk++) {
            float4 a0 = *(const float4*)&As[kk][ty * 8];
            float4 a1 = *(const float4*)&As[kk][ty * 8 + 4];
            float4 b0 = *(const float4*)&Bs[kk][tx * 8];
            float4 b1 = *(const float4*)&Bs[kk][tx * 8 + 4];
            float aa[8] = {a0.x, a0.y, a0.z, a0.w, a1.x, a1.y, a1.z, a1.w};
            float bb[8] = {b0.x, b0.y, b0.z, b0.w, b1.x, b1.y, b1.z, b1.w};
            #pragma unroll
            for (int i = 0; i < 8; i++)
                #pragma unroll
                for (int j = 0; j < 8; j++)
                    acc[i][j] += aa[i] * bb[j];
        }
        __syncthreads();
    }

    const float scale = rsqrtf((float)EE);
    #pragma unroll
    for (int i = 0; i < 8; i++) {
        float* srow = Sb + (size_t)(row0 + ty * 8 + i) * SS + col0;
        #pragma unroll
        for (int j = 0; j < 8; j += 4) {
            float4 o;
            o.x = acc[i][j + 0] * scale;
            o.y = acc[i][j + 1] * scale;
            o.z = acc[i][j + 2] * scale;
            o.w = acc[i][j + 3] * scale;
            *(float4*)(srow + tx * 8 + j) = o;
        }
    }
}

// ---------------- Row softmax over S, in place -----------------------------------
__global__ void softmax_kernel(float* __restrict__ S) {
    float* row = S + (size_t)blockIdx.y * SS * SS + (size_t)blockIdx.x * SS;
    int t = threadIdx.x;
    __shared__ float red[256];

    float vals[8];
    float lmax = -1e30f;
    #pragma unroll
    for (int r = 0; r < 8; r++) {
        vals[r] = row[t + r * 256];
        lmax = fmaxf(lmax, vals[r]);
    }
    red[t] = lmax;
    __syncthreads();
    #pragma unroll
    for (int o = 128; o > 0; o >>= 1) {
        if (t < o) red[t] = fmaxf(red[t], red[t + o]);
        __syncthreads();
    }
    float mx = red[0];
    __syncthreads();

    float lsum = 0.0f;
    #pragma unroll
    for (int r = 0; r < 8; r++) {
        vals[r] = __expf(vals[r] - mx);
        lsum += vals[r];
    }
    red[t] = lsum;
    __syncthreads();
    #pragma unroll
    for (int o = 128; o > 0; o >>= 1) {
        if (t < o) red[t] += red[t + o];
        __syncthreads();
    }
    float inv = 1.0f / red[0];
    #pragma unroll
    for (int r = 0; r < 8; r++)
        row[t + r * 256] = vals[r] * inv;
}

// ---------------- ctx = P @ V per head: [2048,2048] @ [2048,64] ------------------
// Tile 128x64, BK=32, 256 threads, 8x4 micro-tile.
__global__ void __launch_bounds__(256)
ctx_kernel(const float* __restrict__ S, const float* __restrict__ v,
           float* __restrict__ ctx) {
    int bh = blockIdx.z;
    int b = bh / HH, h = bh % HH;
    const float* Sb = S + (size_t)bh * SS * SS;
    const float* vb = v + (size_t)b * SS * EE + h * DD;
    int row0 = blockIdx.y * 128;

    __shared__ float Ps[32][132];
    __shared__ float Vs[32][64];

    int tid = threadIdx.x;
    int tx = tid & 15;
    int ty = tid >> 4;

    float acc[8][4];
    #pragma unroll
    for (int i = 0; i < 8; i++)
        #pragma unroll
        for (int j = 0; j < 4; j++) acc[i][j] = 0.0f;

    for (int k0 = 0; k0 < SS; k0 += 32) {
        // P tile: 128 rows x 32 cols, stored transposed in Ps[col][row]
        #pragma unroll
        for (int r = 0; r < 4; r++) {
            int slot = tid + r * 256;           // 0..1023 float4 slots
            int pr = slot >> 3, pc4 = slot & 7;
            float4 p4 = *(const float4*)(Sb + (size_t)(row0 + pr) * SS + k0 + pc4 * 4);
            Ps[pc4 * 4 + 0][pr] = p4.x;
            Ps[pc4 * 4 + 1][pr] = p4.y;
            Ps[pc4 * 4 + 2][pr] = p4.z;
            Ps[pc4 * 4 + 3][pr] = p4.w;
        }
        // V tile: 32 rows x 64 cols, natural layout
        #pragma unroll
        for (int r = 0; r < 2; r++) {
            int slot = tid + r * 256;           // 0..511 float4 slots
            int vr = slot >> 4, vc4 = slot & 15;
            *(float4*)&Vs[vr][vc4 * 4] =
                *(const float4*)(vb + (size_t)(k0 + vr) * EE + vc4 * 4);
        }
        __syncthreads();

        #pragma unroll
        for (int kk = 0; kk < 32; kk++) {
            float4 a0 = *(const float4*)&Ps[kk][ty * 8];
            float4 a1 = *(const float4*)&Ps[kk][ty * 8 + 4];
            float4 b0 = *(const float4*)&Vs[kk][tx * 4];
            float aa[8] = {a0.x, a0.y, a0.z, a0.w, a1.x, a1.y, a1.z, a1.w};
            float bb[4] = {b0.x, b0.y, b0.z, b0.w};
            #pragma unroll
            for (int i = 0; i < 8; i++)
                #pragma unroll
                for (int j = 0; j < 4; j++)
                    acc[i][j] += aa[i] * bb[j];
        }
        __syncthreads();
    }

    #pragma unroll
    for (int i = 0; i < 8; i++) {
        int row = row0 + ty * 8 + i;
        float4 o;
        o.x = acc[i][0]; o.y = acc[i][1]; o.z = acc[i][2]; o.w = acc[i][3];
        *(float4*)(ctx + (size_t)(b * SS + row) * EE + h * DD + tx * 4) = o;
    }
}

// ---------------- launch ---------------------------------------------------------
extern "C" void kernel_launch(void* const* d_in, const int* in_sizes, int n_in,
                              void* d_out, int out_size) {
    (void)in_sizes; (void)n_in; (void)out_size;
    const float* x     = (const float*)d_in[0];
    const float* ln1_g = (const float*)d_in[1];
    const float* ln1_b = (const float*)d_in[2];
    const float* wq    = (const float*)d_in[3];
    const float* bq    = (const float*)d_in[4];
    const float* wk    = (const float*)d_in[5];
    const float* bk    = (const float*)d_in[6];
    const float* wv    = (const float*)d_in[7];
    const float* bv    = (const float*)d_in[8];
    const float* wo    = (const float*)d_in[9];
    const float* bo    = (const float*)d_in[10];
    const float* w1    = (const float*)d_in[11];
    const float* b1    = (const float*)d_in[12];
    const float* w2    = (const float*)d_in[13];
    const float* b2    = (const float*)d_in[14];
    const float* ln2_g = (const float*)d_in[15];
    const float* ln2_b = (const float*)d_in[16];
    float* out = (float*)d_out;

    float *y, *q, *k, *v, *ctx, *y2, *z, *hbuf, *sbuf;
    cudaGetSymbolAddress((void**)&y,    g_y);
    cudaGetSymbolAddress((void**)&q,    g_q);
    cudaGetSymbolAddress((void**)&k,    g_k);
    cudaGetSymbolAddress((void**)&v,    g_v);
    cudaGetSymbolAddress((void**)&ctx,  g_ctx);
    cudaGetSymbolAddress((void**)&y2,   g_y2);
    cudaGetSymbolAddress((void**)&z,    g_z);
    cudaGetSymbolAddress((void**)&hbuf, g_h);
    cudaGetSymbolAddress((void**)&sbuf, g_s);

    dim3 blk(256);

    // 1. y = LN1(x)
    ln_kernel<<<MM, blk>>>(x, ln1_g, ln1_b, y);

    // 2. q,k,v = y @ {wq,wk,wv} + bias
    dim3 g_e(EE / 128, MM / 128);
    sgemm_kernel<false, false><<<g_e, blk>>>(y, wq, bq, nullptr, q, EE, EE);
    sgemm_kernel<false, false><<<g_e, blk>>>(y, wk, bk, nullptr, k, EE, EE);
    sgemm_kernel<false, false><<<g_e, blk>>>(y, wv, bv, nullptr, v, EE, EE);

    // 3a. S = Q K^T / sqrt(E)
    dim3 g_sc(SS / 128, SS / 128, BH);
    score_kernel<<<g_sc, blk>>>(q, k, sbuf);

    // 3b. softmax rows of S
    dim3 g_sm(SS, BH);
    softmax_kernel<<<g_sm, blk>>>(sbuf);

    // 3c. ctx = P @ V
    dim3 g_cx(1, SS / 128, BH);
    ctx_kernel<<<g_cx, blk>>>(sbuf, v, ctx);

    // 4. y2 = x + ctx @ wo + bo
    sgemm_kernel<false, true><<<g_e, blk>>>(ctx, wo, bo, x, y2, EE, EE);

    // 5. z = LN2(y2)
    ln_kernel<<<MM, blk>>>(y2, ln2_g, ln2_b, z);

    // 6. h = gelu(z @ w1 + b1)
    dim3 g_ff(FF / 128, MM / 128);
    sgemm_kernel<true, false><<<g_ff, blk>>>(z, w1, b1, nullptr, hbuf, FF, EE);

    // 7. out = y2 + h @ w2 + b2
    sgemm_kernel<false, true><<<g_e, blk>>>(hbuf, w2, b2, y2, out, EE, FF);
}

// round 3
// speedup vs baseline: 16.9260x; 1.8234x over previous
#include <cuda_runtime.h>
#include <math.h>

#define BB 2
#define SS 2048
#define EE 768
#define HH 12
#define DD 64
#define MM (BB*SS)      /* 4096 rows */
#define FF (4*EE)       /* 3072 */
#define BH (BB*HH)      /* 24 */

// ---------------- scratch (device globals; no allocation allowed) ----------------
__device__ float g_y  [MM*EE];
__device__ float g_q  [MM*EE];
__device__ float g_k  [MM*EE];
__device__ float g_v  [MM*EE];
__device__ float g_ctx[MM*EE];
__device__ float g_y2 [MM*EE];
__device__ float g_z  [MM*EE];
__device__ float g_h  [MM*FF];
__device__ float g_s  [(size_t)BH*SS*SS];   // 402 MB attention scores

// ---------------- helpers ---------------------------------------------------------
__device__ __forceinline__ unsigned f2tf(float f) {
    unsigned u;
    asm("cvt.rna.tf32.f32 %0, %1;" : "=r"(u) : "f"(f));
    return u;
}

__device__ __forceinline__ void mma_tf32(float& c0, float& c1, float& c2, float& c3,
                                         unsigned a0, unsigned a1, unsigned a2, unsigned a3,
                                         unsigned b0, unsigned b1) {
    asm volatile(
        "mma.sync.aligned.m16n8k8.row.col.f32.tf32.tf32.f32 "
        "{%0,%1,%2,%3}, {%4,%5,%6,%7}, {%8,%9}, {%0,%1,%2,%3};"
        : "+f"(c0), "+f"(c1), "+f"(c2), "+f"(c3)
        : "r"(a0), "r"(a1), "r"(a2), "r"(a3), "r"(b0), "r"(b1));
}

// ---------------- LayerNorm -------------------------------------------------------
__global__ void ln_kernel(const float* __restrict__ x, const float* __restrict__ gw,
                          const float* __restrict__ bw, float* __restrict__ out) {
    int row = blockIdx.x;
    int t = threadIdx.x;
    const float* xr = x + (size_t)row * EE;
    float v0 = xr[t], v1 = xr[t + 256], v2 = xr[t + 512];
    __shared__ float red[256];
    red[t] = v0 + v1 + v2;
    __syncthreads();
    #pragma unroll
    for (int o = 128; o > 0; o >>= 1) {
        if (t < o) red[t] += red[t + o];
        __syncthreads();
    }
    float mean = red[0] * (1.0f / EE);
    __syncthreads();
    float d0 = v0 - mean, d1 = v1 - mean, d2 = v2 - mean;
    red[t] = d0*d0 + d1*d1 + d2*d2;
    __syncthreads();
    #pragma unroll
    for (int o = 128; o > 0; o >>= 1) {
        if (t < o) red[t] += red[t + o];
        __syncthreads();
    }
    float rstd = rsqrtf(red[0] * (1.0f / EE) + 1e-5f);
    float* orow = out + (size_t)row * EE;
    orow[t]       = d0 * rstd * gw[t]       + bw[t];
    orow[t + 256] = d1 * rstd * gw[t + 256] + bw[t + 256];
    orow[t + 512] = d2 * rstd * gw[t + 512] + bw[t + 512];
}

// ---------------- TF32 GEMM: C[M,N] = A[M,K] @ W[K,N] + bias (+res) (opt gelu) ---
// 128x128 tile, BK=32, 256 threads = 8 warps in 2x4 grid; warp tile 64x32.
// m16n8k8 tf32 mma: per warp 4 m-tiles x 4 n-tiles.
#define PADA 136
template<bool GELU, bool RES>
__global__ void __launch_bounds__(256)
mm_tf32(const float* __restrict__ A, const float* __restrict__ W,
        const float* __restrict__ bias, const float* __restrict__ res,
        float* __restrict__ C, int N, int K) {
    __shared__ unsigned As[32][PADA];   // [k][m], tf32 bits
    __shared__ unsigned Bs[32][PADA];   // [k][n]

    int tid  = threadIdx.x;
    int warp = tid >> 5, lane = tid & 31;
    int gid  = lane >> 2, tig = lane & 3;
    int wm   = warp & 1;          // 0..1 -> 64 rows
    int wn   = warp >> 1;         // 0..3 -> 32 cols
    int row0 = blockIdx.y * 128;
    int col0 = blockIdx.x * 128;

    float acc[4][4][4];
    #pragma unroll
    for (int i = 0; i < 4; i++)
        #pragma unroll
        for (int j = 0; j < 4; j++)
            #pragma unroll
            for (int r = 0; r < 4; r++) acc[i][j][r] = 0.0f;

    for (int k0 = 0; k0 < K; k0 += 32) {
        // A tile 128x32 -> As[k][m] transposed
        #pragma unroll
        for (int i = 0; i < 4; i++) {
            int slot = tid + i * 256;            // 0..1023
            int ar = slot >> 3, ac4 = (slot & 7) * 4;
            float4 a4 = *(const float4*)(A + (size_t)(row0 + ar) * K + k0 + ac4);
            As[ac4 + 0][ar] = f2tf(a4.x);
            As[ac4 + 1][ar] = f2tf(a4.y);
            As[ac4 + 2][ar] = f2tf(a4.z);
            As[ac4 + 3][ar] = f2tf(a4.w);
        }
        // B tile 32x128 -> Bs[k][n] natural
        #pragma unroll
        for (int i = 0; i < 4; i++) {
            int slot = tid + i * 256;
            int br = slot >> 5, bc4 = (slot & 31) * 4;
            float4 b4 = *(const float4*)(W + (size_t)(k0 + br) * N + col0 + bc4);
            Bs[br][bc4 + 0] = f2tf(b4.x);
            Bs[br][bc4 + 1] = f2tf(b4.y);
            Bs[br][bc4 + 2] = f2tf(b4.z);
            Bs[br][bc4 + 3] = f2tf(b4.w);
        }
        __syncthreads();

        #pragma unroll
        for (int kk = 0; kk < 32; kk += 8) {
            unsigned af[4][4], bf[4][2];
            #pragma unroll
            for (int mi = 0; mi < 4; mi++) {
                int m = wm * 64 + mi * 16 + gid;
                af[mi][0] = As[kk + tig][m];
                af[mi][1] = As[kk + tig][m + 8];
                af[mi][2] = As[kk + tig + 4][m];
                af[mi][3] = As[kk + tig + 4][m + 8];
            }
            #pragma unroll
            for (int ni = 0; ni < 4; ni++) {
                int n = wn * 32 + ni * 8 + gid;
                bf[ni][0] = Bs[kk + tig][n];
                bf[ni][1] = Bs[kk + tig + 4][n];
            }
            #pragma unroll
            for (int mi = 0; mi < 4; mi++)
                #pragma unroll
                for (int ni = 0; ni < 4; ni++)
                    mma_tf32(acc[mi][ni][0], acc[mi][ni][1], acc[mi][ni][2], acc[mi][ni][3],
                             af[mi][0], af[mi][1], af[mi][2], af[mi][3],
                             bf[ni][0], bf[ni][1]);
        }
        __syncthreads();
    }

    // epilogue
    #pragma unroll
    for (int mi = 0; mi < 4; mi++) {
        int r0 = row0 + wm * 64 + mi * 16 + gid;
        int r1 = r0 + 8;
        #pragma unroll
        for (int ni = 0; ni < 4; ni++) {
            int c = col0 + wn * 32 + ni * 8 + tig * 2;
            float2 b2 = *(const float2*)(bias + c);
            float v00 = acc[mi][ni][0] + b2.x;
            float v01 = acc[mi][ni][1] + b2.y;
            float v10 = acc[mi][ni][2] + b2.x;
            float v11 = acc[mi][ni][3] + b2.y;
            if (RES) {
                float2 e0 = *(const float2*)(res + (size_t)r0 * N + c);
                float2 e1 = *(const float2*)(res + (size_t)r1 * N + c);
                v00 += e0.x; v01 += e0.y; v10 += e1.x; v11 += e1.y;
            }
            if (GELU) {
                v00 = v00 * 0.5f * (1.0f + erff(v00 * 0.70710678118654752f));
                v01 = v01 * 0.5f * (1.0f + erff(v01 * 0.70710678118654752f));
                v10 = v10 * 0.5f * (1.0f + erff(v10 * 0.70710678118654752f));
                v11 = v11 * 0.5f * (1.0f + erff(v11 * 0.70710678118654752f));
            }
            *(float2*)(C + (size_t)r0 * N + c) = make_float2(v00, v01);
            *(float2*)(C + (size_t)r1 * N + c) = make_float2(v10, v11);
        }
    }
}

// ---------------- Scores (tf32): S = Q K^T / sqrt(E) per (b,h) -------------------
__global__ void __launch_bounds__(256)
score_tf32(const float* __restrict__ q, const float* __restrict__ k,
           float* __restrict__ S) {
    int bh = blockIdx.z;
    int b = bh / HH, h = bh % HH;
    const float* qb = q + (size_t)b * SS * EE + h * DD;
    const float* kb = k + (size_t)b * SS * EE + h * DD;
    float* Sb = S + (size_t)bh * SS * SS;

    __shared__ unsigned As[32][PADA];   // [k][m] from Q
    __shared__ unsigned Bs[32][PADA];   // [k][n] from K (transposed load)

    int tid  = threadIdx.x;
    int warp = tid >> 5, lane = tid & 31;
    int gid  = lane >> 2, tig = lane & 3;
    int wm   = warp & 1;
    int wn   = warp >> 1;
    int row0 = blockIdx.y * 128;
    int col0 = blockIdx.x * 128;

    float acc[4][4][4];
    #pragma unroll
    for (int i = 0; i < 4; i++)
        #pragma unroll
        for (int j = 0; j < 4; j++)
            #pragma unroll
            for (int r = 0; r < 4; r++) acc[i][j][r] = 0.0f;

    #pragma unroll
    for (int k0 = 0; k0 < DD; k0 += 32) {
        #pragma unroll
        for (int i = 0; i < 4; i++) {
            int slot = tid + i * 256;
            int ar = slot >> 3, ac4 = (slot & 7) * 4;
            float4 a4 = *(const float4*)(qb + (size_t)(row0 + ar) * EE + k0 + ac4);
            As[ac4 + 0][ar] = f2tf(a4.x);
            As[ac4 + 1][ar] = f2tf(a4.y);
            As[ac4 + 2][ar] = f2tf(a4.z);
            As[ac4 + 3][ar] = f2tf(a4.w);
            float4 b4 = *(const float4*)(kb + (size_t)(col0 + ar) * EE + k0 + ac4);
            Bs[ac4 + 0][ar] = f2tf(b4.x);
            Bs[ac4 + 1][ar] = f2tf(b4.y);
            Bs[ac4 + 2][ar] = f2tf(b4.z);
            Bs[ac4 + 3][ar] = f2tf(b4.w);
        }
        __syncthreads();

        #pragma unroll
        for (int kk = 0; kk < 32; kk += 8) {
            unsigned af[4][4], bf[4][2];
            #pragma unroll
            for (int mi = 0; mi < 4; mi++) {
                int m = wm * 64 + mi * 16 + gid;
                af[mi][0] = As[kk + tig][m];
                af[mi][1] = As[kk + tig][m + 8];
                af[mi][2] = As[kk + tig + 4][m];
                af[mi][3] = As[kk + tig + 4][m + 8];
            }
            #pragma unroll
            for (int ni = 0; ni < 4; ni++) {
                int n = wn * 32 + ni * 8 + gid;
                bf[ni][0] = Bs[kk + tig][n];
                bf[ni][1] = Bs[kk + tig + 4][n];
            }
            #pragma unroll
            for (int mi = 0; mi < 4; mi++)
                #pragma unroll
                for (int ni = 0; ni < 4; ni++)
                    mma_tf32(acc[mi][ni][0], acc[mi][ni][1], acc[mi][ni][2], acc[mi][ni][3],
                             af[mi][0], af[mi][1], af[mi][2], af[mi][3],
                             bf[ni][0], bf[ni][1]);
        }
        __syncthreads();
    }

    const float scale = rsqrtf((float)EE);
    #pragma unroll
    for (int mi = 0; mi < 4; mi++) {
        int r0 = row0 + wm * 64 + mi * 16 + gid;
        int r1 = r0 + 8;
        #pragma unroll
        for (int ni = 0; ni < 4; ni++) {
            int c = col0 + wn * 32 + ni * 8 + tig * 2;
            *(float2*)(Sb + (size_t)r0 * SS + c) =
                make_float2(acc[mi][ni][0] * scale, acc[mi][ni][1] * scale);
            *(float2*)(Sb + (size_t)r1 * SS + c) =
                make_float2(acc[mi][ni][2] * scale, acc[mi][ni][3] * scale);
        }
    }
}

// ---------------- Row softmax over S, in place -----------------------------------
__global__ void softmax_kernel(float* __restrict__ S) {
    float* row = S + (size_t)blockIdx.y * SS * SS + (size_t)blockIdx.x * SS;
    int t = threadIdx.x;
    __shared__ float red[256];

    float vals[8];
    float lmax = -1e30f;
    #pragma unroll
    for (int r = 0; r < 8; r++) {
        vals[r] = row[t + r * 256];
        lmax = fmaxf(lmax, vals[r]);
    }
    red[t] = lmax;
    __syncthreads();
    #pragma unroll
    for (int o = 128; o > 0; o >>= 1) {
        if (t < o) red[t] = fmaxf(red[t], red[t + o]);
        __syncthreads();
    }
    float mx = red[0];
    __syncthreads();

    float lsum = 0.0f;
    #pragma unroll
    for (int r = 0; r < 8; r++) {
        vals[r] = __expf(vals[r] - mx);
        lsum += vals[r];
    }
    red[t] = lsum;
    __syncthreads();
    #pragma unroll
    for (int o = 128; o > 0; o >>= 1) {
        if (t < o) red[t] += red[t + o];
        __syncthreads();
    }
    float inv = 1.0f / red[0];
    #pragma unroll
    for (int r = 0; r < 8; r++)
        row[t + r * 256] = vals[r] * inv;
}

// ---------------- ctx = P @ V per head (tf32): [2048,2048]@[2048,64] -------------
// 128x64 tile, BK=32, 8 warps 2x4; warp tile 64x16 = 4 m-tiles x 2 n-tiles.
#define PADV 72
__global__ void __launch_bounds__(256)
ctx_tf32(const float* __restrict__ S, const float* __restrict__ v,
         float* __restrict__ ctx) {
    int bh = blockIdx.z;
    int b = bh / HH, h = bh % HH;
    const float* Sb = S + (size_t)bh * SS * SS;
    const float* vb = v + (size_t)b * SS * EE + h * DD;
    int row0 = blockIdx.y * 128;

    __shared__ unsigned Ps[32][PADA];   // [k][m]
    __shared__ unsigned Vs[32][PADV];   // [k][n]

    int tid  = threadIdx.x;
    int warp = tid >> 5, lane = tid & 31;
    int gid  = lane >> 2, tig = lane & 3;
    int wm   = warp & 1;          // 64 rows
    int wn   = warp >> 1;         // 16 cols

    float acc[4][2][4];
    #pragma unroll
    for (int i = 0; i < 4; i++)
        #pragma unroll
        for (int j = 0; j < 2; j++)
            #pragma unroll
            for (int r = 0; r < 4; r++) acc[i][j][r] = 0.0f;

    for (int k0 = 0; k0 < SS; k0 += 32) {
        #pragma unroll
        for (int i = 0; i < 4; i++) {
            int slot = tid + i * 256;
            int pr = slot >> 3, pc4 = (slot & 7) * 4;
            float4 p4 = *(const float4*)(Sb + (size_t)(row0 + pr) * SS + k0 + pc4);
            Ps[pc4 + 0][pr] = f2tf(p4.x);
            Ps[pc4 + 1][pr] = f2tf(p4.y);
            Ps[pc4 + 2][pr] = f2tf(p4.z);
            Ps[pc4 + 3][pr] = f2tf(p4.w);
        }
        #pragma unroll
        for (int i = 0; i < 2; i++) {
            int slot = tid + i * 256;            // 0..511
            int vr = slot >> 4, vc4 = (slot & 15) * 4;
            float4 v4 = *(const float4*)(vb + (size_t)(k0 + vr) * EE + vc4);
            Vs[vr][vc4 + 0] = f2tf(v4.x);
            Vs[vr][vc4 + 1] = f2tf(v4.y);
            Vs[vr][vc4 + 2] = f2tf(v4.z);
            Vs[vr][vc4 + 3] = f2tf(v4.w);
        }
        __syncthreads();

        #pragma unroll
        for (int kk = 0; kk < 32; kk += 8) {
            unsigned af[4][4], bf[2][2];
            #pragma unroll
            for (int mi = 0; mi < 4; mi++) {
                int m = wm * 64 + mi * 16 + gid;
                af[mi][0] = Ps[kk + tig][m];
                af[mi][1] = Ps[kk + tig][m + 8];
                af[mi][2] = Ps[kk + tig + 4][m];
                af[mi][3] = Ps[kk + tig + 4][m + 8];
            }
            #pragma unroll
            for (int ni = 0; ni < 2; ni++) {
                int n = wn * 16 + ni * 8 + gid;
                bf[ni][0] = Vs[kk + tig][n];
                bf[ni][1] = Vs[kk + tig + 4][n];
            }
            #pragma unroll
            for (int mi = 0; mi < 4; mi++)
                #pragma unroll
                for (int ni = 0; ni < 2; ni++)
                    mma_tf32(acc[mi][ni][0], acc[mi][ni][1], acc[mi][ni][2], acc[mi][ni][3],
                             af[mi][0], af[mi][1], af[mi][2], af[mi][3],
                             bf[ni][0], bf[ni][1]);
        }
        __syncthreads();
    }

    #pragma unroll
    for (int mi = 0; mi < 4; mi++) {
        int r0 = row0 + wm * 64 + mi * 16 + gid;
        int r1 = r0 + 8;
        #pragma unroll
        for (int ni = 0; ni < 2; ni++) {
            int c = h * DD + wn * 16 + ni * 8 + tig * 2;
            *(float2*)(ctx + (size_t)(b * SS + r0) * EE + c) =
                make_float2(acc[mi][ni][0], acc[mi][ni][1]);
            *(float2*)(ctx + (size_t)(b * SS + r1) * EE + c) =
                make_float2(acc[mi][ni][2], acc[mi][ni][3]);
        }
    }
}

// ---------------- launch ---------------------------------------------------------
extern "C" void kernel_launch(void* const* d_in, const int* in_sizes, int n_in,
                              void* d_out, int out_size) {
    (void)in_sizes; (void)n_in; (void)out_size;
    const float* x     = (const float*)d_in[0];
    const float* ln1_g = (const float*)d_in[1];
    const float* ln1_b = (const float*)d_in[2];
    const float* wq    = (const float*)d_in[3];
    const float* bq    = (const float*)d_in[4];
    const float* wk    = (const float*)d_in[5];
    const float* bk    = (const float*)d_in[6];
    const float* wv    = (const float*)d_in[7];
    const float* bv    = (const float*)d_in[8];
    const float* wo    = (const float*)d_in[9];
    const float* bo    = (const float*)d_in[10];
    const float* w1    = (const float*)d_in[11];
    const float* b1    = (const float*)d_in[12];
    const float* w2    = (const float*)d_in[13];
    const float* b2    = (const float*)d_in[14];
    const float* ln2_g = (const float*)d_in[15];
    const float* ln2_b = (const float*)d_in[16];
    float* out = (float*)d_out;

    float *y, *q, *k, *v, *ctx, *y2, *z, *hbuf, *sbuf;
    cudaGetSymbolAddress((void**)&y,    g_y);
    cudaGetSymbolAddress((void**)&q,    g_q);
    cudaGetSymbolAddress((void**)&k,    g_k);
    cudaGetSymbolAddress((void**)&v,    g_v);
    cudaGetSymbolAddress((void**)&ctx,  g_ctx);
    cudaGetSymbolAddress((void**)&y2,   g_y2);
    cudaGetSymbolAddress((void**)&z,    g_z);
    cudaGetSymbolAddress((void**)&hbuf, g_h);
    cudaGetSymbolAddress((void**)&sbuf, g_s);

    dim3 blk(256);

    // 1. y = LN1(x)
    ln_kernel<<<MM, blk>>>(x, ln1_g, ln1_b, y);

    // 2. q,k,v = y @ {wq,wk,wv} + bias
    dim3 g_e(EE / 128, MM / 128);
    mm_tf32<false, false><<<g_e, blk>>>(y, wq, bq, nullptr, q, EE, EE);
    mm_tf32<false, false><<<g_e, blk>>>(y, wk, bk, nullptr, k, EE, EE);
    mm_tf32<false, false><<<g_e, blk>>>(y, wv, bv, nullptr, v, EE, EE);

    // 3a. S = Q K^T / sqrt(E)
    dim3 g_sc(SS / 128, SS / 128, BH);
    score_tf32<<<g_sc, blk>>>(q, k, sbuf);

    // 3b. softmax rows of S
    dim3 g_sm(SS, BH);
    softmax_kernel<<<g_sm, blk>>>(sbuf);

    // 3c. ctx = P @ V
    dim3 g_cx(1, SS / 128, BH);
    ctx_tf32<<<g_cx, blk>>>(sbuf, v, ctx);

    // 4. y2 = x + ctx @ wo + bo
    mm_tf32<false, true><<<g_e, blk>>>(ctx, wo, bo, x, y2, EE, EE);

    // 5. z = LN2(y2)
    ln_kernel<<<MM, blk>>>(y2, ln2_g, ln2_b, z);

    // 6. h = gelu(z @ w1 + b1)
    dim3 g_ff(FF / 128, MM / 128);
    mm_tf32<true, false><<<g_ff, blk>>>(z, w1, b1, nullptr, hbuf, FF, EE);

    // 7. out = y2 + h @ w2 + b2
    mm_tf32<false, true><<<g_e, blk>>>(hbuf, w2, b2, y2, out, EE, FF);
}

// round 4
// speedup vs baseline: 24.4033x; 1.4418x over previous
#include <cuda_runtime.h>
#include <math.h>

#define BB 2
#define SS 2048
#define EE 768
#define HH 12
#define DD 64
#define MM (BB*SS)      /* 4096 rows */
#define FF (4*EE)       /* 3072 */
#define BH (BB*HH)      /* 24 */

#define BK 16
#define PA 20           /* [row][k] pad: 20*gid mod 32 all distinct */
#define PB 136          /* [k][n] pad: 136 mod 32 = 8 -> 8*tig+gid distinct */
#define PV 72           /* 72 mod 32 = 8 */

// ---------------- scratch (device globals; no allocation allowed) ----------------
__device__ float g_y  [MM*EE];
__device__ float g_q  [MM*EE];
__device__ float g_k  [MM*EE];
__device__ float g_v  [MM*EE];
__device__ float g_ctx[MM*EE];
__device__ float g_y2 [MM*EE];
__device__ float g_z  [MM*EE];
__device__ float g_h  [MM*FF];
__device__ float g_s  [(size_t)BH*SS*SS];   // 402 MB attention scores

// ---------------- helpers ---------------------------------------------------------
__device__ __forceinline__ void mma_tf32(float& c0, float& c1, float& c2, float& c3,
                                         unsigned a0, unsigned a1, unsigned a2, unsigned a3,
                                         unsigned b0, unsigned b1) {
    asm volatile(
        "mma.sync.aligned.m16n8k8.row.col.f32.tf32.tf32.f32 "
        "{%0,%1,%2,%3}, {%4,%5,%6,%7}, {%8,%9}, {%0,%1,%2,%3};"
        : "+f"(c0), "+f"(c1), "+f"(c2), "+f"(c3)
        : "r"(a0), "r"(a1), "r"(a2), "r"(a3), "r"(b0), "r"(b1));
}

__device__ __forceinline__ void cp16(unsigned saddr, const void* g) {
    asm volatile("cp.async.cg.shared.global [%0], [%1], 16;" :: "r"(saddr), "l"(g));
}
__device__ __forceinline__ void cp_commit() {
    asm volatile("cp.async.commit_group;");
}
__device__ __forceinline__ void cp_wait0() {
    asm volatile("cp.async.wait_group 0;");
}

// ---------------- LayerNorm -------------------------------------------------------
__global__ void ln_kernel(const float* __restrict__ x, const float* __restrict__ gw,
                          const float* __restrict__ bw, float* __restrict__ out) {
    int row = blockIdx.x;
    int t = threadIdx.x;
    const float* xr = x + (size_t)row * EE;
    float v0 = xr[t], v1 = xr[t + 256], v2 = xr[t + 512];
    __shared__ float red[256];
    red[t] = v0 + v1 + v2;
    __syncthreads();
    #pragma unroll
    for (int o = 128; o > 0; o >>= 1) {
        if (t < o) red[t] += red[t + o];
        __syncthreads();
    }
    float mean = red[0] * (1.0f / EE);
    __syncthreads();
    float d0 = v0 - mean, d1 = v1 - mean, d2 = v2 - mean;
    red[t] = d0*d0 + d1*d1 + d2*d2;
    __syncthreads();
    #pragma unroll
    for (int o = 128; o > 0; o >>= 1) {
        if (t < o) red[t] += red[t + o];
        __syncthreads();
    }
    float rstd = rsqrtf(red[0] * (1.0f / EE) + 1e-5f);
    float* orow = out + (size_t)row * EE;
    orow[t]       = d0 * rstd * gw[t]       + bw[t];
    orow[t + 256] = d1 * rstd * gw[t + 256] + bw[t + 256];
    orow[t + 512] = d2 * rstd * gw[t + 512] + bw[t + 512];
}

// ---------------- TF32 GEMM, cp.async double-buffered ----------------------------
// C[M,N] = A[M,K] @ W[K,N] + bias (+res) (opt gelu). 128x128 tile, BK=16,
// 8 warps (2x4), warp tile 64x32, m16n8k8 tf32 mma with raw fp32 bits.
template<bool GELU, bool RES>
__global__ void __launch_bounds__(256)
mm_tc(const float* __restrict__ A, const float* __restrict__ W,
      const float* __restrict__ bias, const float* __restrict__ res,
      float* __restrict__ C, int N, int K) {
    __shared__ unsigned As[2][128][PA];   // [m][k], fp32 bits
    __shared__ unsigned Bs[2][BK][PB];    // [k][n]

    int tid  = threadIdx.x;
    int warp = tid >> 5, lane = tid & 31;
    int gid  = lane >> 2, tig = lane & 3;
    int wm   = warp & 1;
    int wn   = warp >> 1;
    int row0 = blockIdx.y * 128;
    int col0 = blockIdx.x * 128;

    unsigned sA = (unsigned)__cvta_generic_to_shared(&As[0][0][0]);
    unsigned sB = (unsigned)__cvta_generic_to_shared(&Bs[0][0][0]);

    // loader indices
    int a_r = tid >> 2, a_c = (tid & 3) * 4;       // +i*64 rows
    int b_r = tid >> 5, b_c = (tid & 31) * 4;      // +i*8 rows

    float acc[4][4][4];
    #pragma unroll
    for (int i = 0; i < 4; i++)
        #pragma unroll
        for (int j = 0; j < 4; j++)
            #pragma unroll
            for (int r = 0; r < 4; r++) acc[i][j][r] = 0.0f;

    int NIT = K / BK;

    // preload stage 0
    {
        #pragma unroll
        for (int i = 0; i < 2; i++) {
            int r = a_r + i * 64;
            cp16(sA + ((0*128 + r)*PA + a_c)*4, A + (size_t)(row0 + r) * K + a_c);
        }
        #pragma unroll
        for (int i = 0; i < 2; i++) {
            int r = b_r + i * 8;
            cp16(sB + ((0*BK + r)*PB + b_c)*4, W + (size_t)r * N + col0 + b_c);
        }
        cp_commit();
    }

    for (int it = 0; it < NIT; it++) {
        cp_wait0();
        __syncthreads();

        int buf = it & 1;
        if (it + 1 < NIT) {
            int nb = buf ^ 1;
            int k0 = (it + 1) * BK;
            #pragma unroll
            for (int i = 0; i < 2; i++) {
                int r = a_r + i * 64;
                cp16(sA + ((nb*128 + r)*PA + a_c)*4, A + (size_t)(row0 + r) * K + k0 + a_c);
            }
            #pragma unroll
            for (int i = 0; i < 2; i++) {
                int r = b_r + i * 8;
                cp16(sB + ((nb*BK + r)*PB + b_c)*4, W + (size_t)(k0 + r) * N + col0 + b_c);
            }
            cp_commit();
        }

        #pragma unroll
        for (int kk = 0; kk < BK; kk += 8) {
            unsigned af[4][4], bf[4][2];
            #pragma unroll
            for (int mi = 0; mi < 4; mi++) {
                int m = wm * 64 + mi * 16 + gid;
                af[mi][0] = As[buf][m][kk + tig];
                af[mi][1] = As[buf][m + 8][kk + tig];
                af[mi][2] = As[buf][m][kk + tig + 4];
                af[mi][3] = As[buf][m + 8][kk + tig + 4];
            }
            #pragma unroll
            for (int ni = 0; ni < 4; ni++) {
                int n = wn * 32 + ni * 8 + gid;
                bf[ni][0] = Bs[buf][kk + tig][n];
                bf[ni][1] = Bs[buf][kk + tig + 4][n];
            }
            #pragma unroll
            for (int mi = 0; mi < 4; mi++)
                #pragma unroll
                for (int ni = 0; ni < 4; ni++)
                    mma_tf32(acc[mi][ni][0], acc[mi][ni][1], acc[mi][ni][2], acc[mi][ni][3],
                             af[mi][0], af[mi][1], af[mi][2], af[mi][3],
                             bf[ni][0], bf[ni][1]);
        }
    }

    #pragma unroll
    for (int mi = 0; mi < 4; mi++) {
        int r0 = row0 + wm * 64 + mi * 16 + gid;
        int r1 = r0 + 8;
        #pragma unroll
        for (int ni = 0; ni < 4; ni++) {
            int c = col0 + wn * 32 + ni * 8 + tig * 2;
            float2 b2 = *(const float2*)(bias + c);
            float v00 = acc[mi][ni][0] + b2.x;
            float v01 = acc[mi][ni][1] + b2.y;
            float v10 = acc[mi][ni][2] + b2.x;
            float v11 = acc[mi][ni][3] + b2.y;
            if (RES) {
                float2 e0 = *(const float2*)(res + (size_t)r0 * N + c);
                float2 e1 = *(const float2*)(res + (size_t)r1 * N + c);
                v00 += e0.x; v01 += e0.y; v10 += e1.x; v11 += e1.y;
            }
            if (GELU) {
                v00 = v00 * 0.5f * (1.0f + erff(v00 * 0.70710678118654752f));
                v01 = v01 * 0.5f * (1.0f + erff(v01 * 0.70710678118654752f));
                v10 = v10 * 0.5f * (1.0f + erff(v10 * 0.70710678118654752f));
                v11 = v11 * 0.5f * (1.0f + erff(v11 * 0.70710678118654752f));
            }
            *(float2*)(C + (size_t)r0 * N + c) = make_float2(v00, v01);
            *(float2*)(C + (size_t)r1 * N + c) = make_float2(v10, v11);
        }
    }
}

// ---------------- Scores: S = Q K^T / sqrt(E), pipelined -------------------------
__global__ void __launch_bounds__(256)
score_tc(const float* __restrict__ q, const float* __restrict__ k,
         float* __restrict__ S) {
    int bh = blockIdx.z;
    int b = bh / HH, h = bh % HH;
    const float* qb = q + (size_t)b * SS * EE + h * DD;
    const float* kb = k + (size_t)b * SS * EE + h * DD;
    float* Sb = S + (size_t)bh * SS * SS;

    __shared__ unsigned As[2][128][PA];   // Q [m][k]
    __shared__ unsigned Bs[2][128][PA];   // K [n][k]

    int tid  = threadIdx.x;
    int warp = tid >> 5, lane = tid & 31;
    int gid  = lane >> 2, tig = lane & 3;
    int wm   = warp & 1;
    int wn   = warp >> 1;
    int row0 = blockIdx.y * 128;
    int col0 = blockIdx.x * 128;

    unsigned sA = (unsigned)__cvta_generic_to_shared(&As[0][0][0]);
    unsigned sB = (unsigned)__cvta_generic_to_shared(&Bs[0][0][0]);

    int a_r = tid >> 2, a_c = (tid & 3) * 4;

    float acc[4][4][4];
    #pragma unroll
    for (int i = 0; i < 4; i++)
        #pragma unroll
        for (int j = 0; j < 4; j++)
            #pragma unroll
            for (int r = 0; r < 4; r++) acc[i][j][r] = 0.0f;

    const int NIT = DD / BK;   // 4

    {
        #pragma unroll
        for (int i = 0; i < 2; i++) {
            int r = a_r + i * 64;
            cp16(sA + ((0*128 + r)*PA + a_c)*4, qb + (size_t)(row0 + r) * EE + a_c);
            cp16(sB + ((0*128 + r)*PA + a_c)*4, kb + (size_t)(col0 + r) * EE + a_c);
        }
        cp_commit();
    }

    for (int it = 0; it < NIT; it++) {
        cp_wait0();
        __syncthreads();

        int buf = it & 1;
        if (it + 1 < NIT) {
            int nb = buf ^ 1;
            int k0 = (it + 1) * BK;
            #pragma unroll
            for (int i = 0; i < 2; i++) {
                int r = a_r + i * 64;
                cp16(sA + ((nb*128 + r)*PA + a_c)*4, qb + (size_t)(row0 + r) * EE + k0 + a_c);
                cp16(sB + ((nb*128 + r)*PA + a_c)*4, kb + (size_t)(col0 + r) * EE + k0 + a_c);
            }
            cp_commit();
        }

        #pragma unroll
        for (int kk = 0; kk < BK; kk += 8) {
            unsigned af[4][4], bf[4][2];
            #pragma unroll
            for (int mi = 0; mi < 4; mi++) {
                int m = wm * 64 + mi * 16 + gid;
                af[mi][0] = As[buf][m][kk + tig];
                af[mi][1] = As[buf][m + 8][kk + tig];
                af[mi][2] = As[buf][m][kk + tig + 4];
                af[mi][3] = As[buf][m + 8][kk + tig + 4];
            }
            #pragma unroll
            for (int ni = 0; ni < 4; ni++) {
                int n = wn * 32 + ni * 8 + gid;
                bf[ni][0] = Bs[buf][n][kk + tig];
                bf[ni][1] = Bs[buf][n][kk + tig + 4];
            }
            #pragma unroll
            for (int mi = 0; mi < 4; mi++)
                #pragma unroll
                for (int ni = 0; ni < 4; ni++)
                    mma_tf32(acc[mi][ni][0], acc[mi][ni][1], acc[mi][ni][2], acc[mi][ni][3],
                             af[mi][0], af[mi][1], af[mi][2], af[mi][3],
                             bf[ni][0], bf[ni][1]);
        }
    }

    const float scale = rsqrtf((float)EE);
    #pragma unroll
    for (int mi = 0; mi < 4; mi++) {
        int r0 = row0 + wm * 64 + mi * 16 + gid;
        int r1 = r0 + 8;
        #pragma unroll
        for (int ni = 0; ni < 4; ni++) {
            int c = col0 + wn * 32 + ni * 8 + tig * 2;
            *(float2*)(Sb + (size_t)r0 * SS + c) =
                make_float2(acc[mi][ni][0] * scale, acc[mi][ni][1] * scale);
            *(float2*)(Sb + (size_t)r1 * SS + c) =
                make_float2(acc[mi][ni][2] * scale, acc[mi][ni][3] * scale);
        }
    }
}

// ---------------- Row softmax over S, in place -----------------------------------
__global__ void softmax_kernel(float* __restrict__ S) {
    float* row = S + (size_t)blockIdx.y * SS * SS + (size_t)blockIdx.x * SS;
    int t = threadIdx.x;
    __shared__ float red[256];

    float vals[8];
    float lmax = -1e30f;
    #pragma unroll
    for (int r = 0; r < 8; r++) {
        vals[r] = row[t + r * 256];
        lmax = fmaxf(lmax, vals[r]);
    }
    red[t] = lmax;
    __syncthreads();
    #pragma unroll
    for (int o = 128; o > 0; o >>= 1) {
        if (t < o) red[t] = fmaxf(red[t], red[t + o]);
        __syncthreads();
    }
    float mx = red[0];
    __syncthreads();

    float lsum = 0.0f;
    #pragma unroll
    for (int r = 0; r < 8; r++) {
        vals[r] = __expf(vals[r] - mx);
        lsum += vals[r];
    }
    red[t] = lsum;
    __syncthreads();
    #pragma unroll
    for (int o = 128; o > 0; o >>= 1) {
        if (t < o) red[t] += red[t + o];
        __syncthreads();
    }
    float inv = 1.0f / red[0];
    #pragma unroll
    for (int r = 0; r < 8; r++)
        row[t + r * 256] = vals[r] * inv;
}

// ---------------- ctx = P @ V per head, pipelined ---------------------------------
// 128x64 tile, BK=16, warp tile 64x16.
__global__ void __launch_bounds__(256)
ctx_tc(const float* __restrict__ S, const float* __restrict__ v,
       float* __restrict__ ctx) {
    int bh = blockIdx.z;
    int b = bh / HH, h = bh % HH;
    const float* Sb = S + (size_t)bh * SS * SS;
    const float* vb = v + (size_t)b * SS * EE + h * DD;
    int row0 = blockIdx.y * 128;

    __shared__ unsigned Ps[2][128][PA];   // [m][k]
    __shared__ unsigned Vs[2][BK][PV];    // [k][n]

    int tid  = threadIdx.x;
    int warp = tid >> 5, lane = tid & 31;
    int gid  = lane >> 2, tig = lane & 3;
    int wm   = warp & 1;
    int wn   = warp >> 1;

    unsigned sP = (unsigned)__cvta_generic_to_shared(&Ps[0][0][0]);
    unsigned sV = (unsigned)__cvta_generic_to_shared(&Vs[0][0][0]);

    int a_r = tid >> 2, a_c = (tid & 3) * 4;
    int v_r = tid >> 4, v_c = (tid & 15) * 4;   // tid<256: 16 rows x 16 chunks

    float acc[4][2][4];
    #pragma unroll
    for (int i = 0; i < 4; i++)
        #pragma unroll
        for (int j = 0; j < 2; j++)
            #pragma unroll
            for (int r = 0; r < 4; r++) acc[i][j][r] = 0.0f;

    const int NIT = SS / BK;   // 128

    {
        #pragma unroll
        for (int i = 0; i < 2; i++) {
            int r = a_r + i * 64;
            cp16(sP + ((0*128 + r)*PA + a_c)*4, Sb + (size_t)(row0 + r) * SS + a_c);
        }
        cp16(sV + ((0*BK + v_r)*PV + v_c)*4, vb + (size_t)v_r * EE + v_c);
        cp_commit();
    }

    for (int it = 0; it < NIT; it++) {
        cp_wait0();
        __syncthreads();

        int buf = it & 1;
        if (it + 1 < NIT) {
            int nb = buf ^ 1;
            int k0 = (it + 1) * BK;
            #pragma unroll
            for (int i = 0; i < 2; i++) {
                int r = a_r + i * 64;
                cp16(sP + ((nb*128 + r)*PA + a_c)*4, Sb + (size_t)(row0 + r) * SS + k0 + a_c);
            }
            cp16(sV + ((nb*BK + v_r)*PV + v_c)*4, vb + (size_t)(k0 + v_r) * EE + v_c);
            cp_commit();
        }

        #pragma unroll
        for (int kk = 0; kk < BK; kk += 8) {
            unsigned af[4][4], bf[2][2];
            #pragma unroll
            for (int mi = 0; mi < 4; mi++) {
                int m = wm * 64 + mi * 16 + gid;
                af[mi][0] = Ps[buf][m][kk + tig];
                af[mi][1] = Ps[buf][m + 8][kk + tig];
                af[mi][2] = Ps[buf][m][kk + tig + 4];
                af[mi][3] = Ps[buf][m + 8][kk + tig + 4];
            }
            #pragma unroll
            for (int ni = 0; ni < 2; ni++) {
                int n = wn * 16 + ni * 8 + gid;
                bf[ni][0] = Vs[buf][kk + tig][n];
                bf[ni][1] = Vs[buf][kk + tig + 4][n];
            }
            #pragma unroll
            for (int mi = 0; mi < 4; mi++)
                #pragma unroll
                for (int ni = 0; ni < 2; ni++)
                    mma_tf32(acc[mi][ni][0], acc[mi][ni][1], acc[mi][ni][2], acc[mi][ni][3],
                             af[mi][0], af[mi][1], af[mi][2], af[mi][3],
                             bf[ni][0], bf[ni][1]);
        }
    }

    #pragma unroll
    for (int mi = 0; mi < 4; mi++) {
        int r0 = row0 + wm * 64 + mi * 16 + gid;
        int r1 = r0 + 8;
        #pragma unroll
        for (int ni = 0; ni < 2; ni++) {
            int c = h * DD + wn * 16 + ni * 8 + tig * 2;
            *(float2*)(ctx + (size_t)(b * SS + r0) * EE + c) =
                make_float2(acc[mi][ni][0], acc[mi][ni][1]);
            *(float2*)(ctx + (size_t)(b * SS + r1) * EE + c) =
                make_float2(acc[mi][ni][2], acc[mi][ni][3]);
        }
    }
}

// ---------------- launch ---------------------------------------------------------
extern "C" void kernel_launch(void* const* d_in, const int* in_sizes, int n_in,
                              void* d_out, int out_size) {
    (void)in_sizes; (void)n_in; (void)out_size;
    const float* x     = (const float*)d_in[0];
    const float* ln1_g = (const float*)d_in[1];
    const float* ln1_b = (const float*)d_in[2];
    const float* wq    = (const float*)d_in[3];
    const float* bq    = (const float*)d_in[4];
    const float* wk    = (const float*)d_in[5];
    const float* bk    = (const float*)d_in[6];
    const float* wv    = (const float*)d_in[7];
    const float* bv    = (const float*)d_in[8];
    const float* wo    = (const float*)d_in[9];
    const float* bo    = (const float*)d_in[10];
    const float* w1    = (const float*)d_in[11];
    const float* b1    = (const float*)d_in[12];
    const float* w2    = (const float*)d_in[13];
    const float* b2    = (const float*)d_in[14];
    const float* ln2_g = (const float*)d_in[15];
    const float* ln2_b = (const float*)d_in[16];
    float* out = (float*)d_out;

    float *y, *q, *k, *v, *ctx, *y2, *z, *hbuf, *sbuf;
    cudaGetSymbolAddress((void**)&y,    g_y);
    cudaGetSymbolAddress((void**)&q,    g_q);
    cudaGetSymbolAddress((void**)&k,    g_k);
    cudaGetSymbolAddress((void**)&v,    g_v);
    cudaGetSymbolAddress((void**)&ctx,  g_ctx);
    cudaGetSymbolAddress((void**)&y2,   g_y2);
    cudaGetSymbolAddress((void**)&z,    g_z);
    cudaGetSymbolAddress((void**)&hbuf, g_h);
    cudaGetSymbolAddress((void**)&sbuf, g_s);

    dim3 blk(256);

    // 1. y = LN1(x)
    ln_kernel<<<MM, blk>>>(x, ln1_g, ln1_b, y);

    // 2. q,k,v = y @ {wq,wk,wv} + bias
    dim3 g_e(EE / 128, MM / 128);
    mm_tc<false, false><<<g_e, blk>>>(y, wq, bq, nullptr, q, EE, EE);
    mm_tc<false, false><<<g_e, blk>>>(y, wk, bk, nullptr, k, EE, EE);
    mm_tc<false, false><<<g_e, blk>>>(y, wv, bv, nullptr, v, EE, EE);

    // 3a. S = Q K^T / sqrt(E)
    dim3 g_sc(SS / 128, SS / 128, BH);
    score_tc<<<g_sc, blk>>>(q, k, sbuf);

    // 3b. softmax rows of S
    dim3 g_sm(SS, BH);
    softmax_kernel<<<g_sm, blk>>>(sbuf);

    // 3c. ctx = P @ V
    dim3 g_cx(1, SS / 128, BH);
    ctx_tc<<<g_cx, blk>>>(sbuf, v, ctx);

    // 4. y2 = x + ctx @ wo + bo
    mm_tc<false, true><<<g_e, blk>>>(ctx, wo, bo, x, y2, EE, EE);

    // 5. z = LN2(y2)
    ln_kernel<<<MM, blk>>>(y2, ln2_g, ln2_b, z);

    // 6. h = gelu(z @ w1 + b1)
    dim3 g_ff(FF / 128, MM / 128);
    mm_tc<true, false><<<g_ff, blk>>>(z, w1, b1, nullptr, hbuf, FF, EE);

    // 7. out = y2 + h @ w2 + b2
    mm_tc<false, true><<<g_e, blk>>>(hbuf, w2, b2, y2, out, EE, FF);
}

// round 5
// speedup vs baseline: 26.1879x; 1.0731x over previous
#include <cuda_runtime.h>
#include <math.h>

#define BB 2
#define SS 2048
#define EE 768
#define HH 12
#define DD 64
#define MM (BB*SS)      /* 4096 rows */
#define FF (4*EE)       /* 3072 */
#define BH (BB*HH)      /* 24 */

#define BK 16
#define STG 3
#define PA 20           /* [row][k] pad: 20*gid mod 32 all distinct */
#define PB 136          /* [k][n] pad: 136 mod 32 = 8 */
#define PV 72           /* 72 mod 32 = 8 */

// dynamic smem sizes (bytes)
#define SM_MM    (STG*(128*PA + BK*PB)*4)       /* 56832 */
#define SM_SCORE (STG*(2*128*PA)*4)             /* 61440 */
#define SM_CTX   (STG*(128*PA + BK*PV)*4)       /* 44544 */

// ---------------- scratch (device globals; no allocation allowed) ----------------
__device__ float g_y  [MM*EE];
__device__ float g_q  [MM*EE];
__device__ float g_k  [MM*EE];
__device__ float g_v  [MM*EE];
__device__ float g_ctx[MM*EE];
__device__ float g_y2 [MM*EE];
__device__ float g_z  [MM*EE];
__device__ float g_h  [MM*FF];
__device__ float g_s  [(size_t)BH*SS*SS];   // 402 MB attention scores

// ---------------- helpers ---------------------------------------------------------
__device__ __forceinline__ void mma_tf32(float& c0, float& c1, float& c2, float& c3,
                                         unsigned a0, unsigned a1, unsigned a2, unsigned a3,
                                         unsigned b0, unsigned b1) {
    asm volatile(
        "mma.sync.aligned.m16n8k8.row.col.f32.tf32.tf32.f32 "
        "{%0,%1,%2,%3}, {%4,%5,%6,%7}, {%8,%9}, {%0,%1,%2,%3};"
        : "+f"(c0), "+f"(c1), "+f"(c2), "+f"(c3)
        : "r"(a0), "r"(a1), "r"(a2), "r"(a3), "r"(b0), "r"(b1));
}

__device__ __forceinline__ void cp16(unsigned saddr, const void* g) {
    asm volatile("cp.async.cg.shared.global [%0], [%1], 16;" :: "r"(saddr), "l"(g));
}
__device__ __forceinline__ void cp_commit() {
    asm volatile("cp.async.commit_group;");
}
__device__ __forceinline__ void cp_wait0() {
    asm volatile("cp.async.wait_group 0;");
}
__device__ __forceinline__ void cp_wait1() {
    asm volatile("cp.async.wait_group 1;");
}

// ---------------- LayerNorm -------------------------------------------------------
__global__ void ln_kernel(const float* __restrict__ x, const float* __restrict__ gw,
                          const float* __restrict__ bw, float* __restrict__ out) {
    int row = blockIdx.x;
    int t = threadIdx.x;
    const float* xr = x + (size_t)row * EE;
    float v0 = xr[t], v1 = xr[t + 256], v2 = xr[t + 512];
    __shared__ float red[256];
    red[t] = v0 + v1 + v2;
    __syncthreads();
    #pragma unroll
    for (int o = 128; o > 0; o >>= 1) {
        if (t < o) red[t] += red[t + o];
        __syncthreads();
    }
    float mean = red[0] * (1.0f / EE);
    __syncthreads();
    float d0 = v0 - mean, d1 = v1 - mean, d2 = v2 - mean;
    red[t] = d0*d0 + d1*d1 + d2*d2;
    __syncthreads();
    #pragma unroll
    for (int o = 128; o > 0; o >>= 1) {
        if (t < o) red[t] += red[t + o];
        __syncthreads();
    }
    float rstd = rsqrtf(red[0] * (1.0f / EE) + 1e-5f);
    float* orow = out + (size_t)row * EE;
    orow[t]       = d0 * rstd * gw[t]       + bw[t];
    orow[t + 256] = d1 * rstd * gw[t + 256] + bw[t + 256];
    orow[t + 512] = d2 * rstd * gw[t + 512] + bw[t + 512];
}

// ---------------- GEMM core (device inline): 128x128 tile, BK=16, 3-stage --------
template<bool GELU, bool RES>
__device__ __forceinline__ void
mm_body(const float* __restrict__ A, const float* __restrict__ W,
        const float* __restrict__ bias, const float* __restrict__ res,
        float* __restrict__ C, int N, int K, int row0, int col0, char* smem) {
    unsigned* As_ = (unsigned*)smem;                       // [STG][128][PA]
    unsigned* Bs_ = As_ + STG * 128 * PA;                  // [STG][BK][PB]
    unsigned sA = (unsigned)__cvta_generic_to_shared(As_);
    unsigned sB = (unsigned)__cvta_generic_to_shared(Bs_);

    int tid  = threadIdx.x;
    int warp = tid >> 5, lane = tid & 31;
    int gid  = lane >> 2, tig = lane & 3;
    int wm   = warp & 1;
    int wn   = warp >> 1;

    int a_r = tid >> 2, a_c = (tid & 3) * 4;
    int b_r = tid >> 5, b_c = (tid & 31) * 4;

    float acc[4][4][4];
    #pragma unroll
    for (int i = 0; i < 4; i++)
        #pragma unroll
        for (int j = 0; j < 4; j++)
            #pragma unroll
            for (int r = 0; r < 4; r++) acc[i][j][r] = 0.0f;

    int NIT = K / BK;

    // stage loader
    auto load_st = [&](int st, int k0) {
        #pragma unroll
        for (int i = 0; i < 2; i++) {
            int r = a_r + i * 64;
            cp16(sA + (unsigned)((st*128 + r)*PA + a_c)*4,
                 A + (size_t)(row0 + r) * K + k0 + a_c);
        }
        #pragma unroll
        for (int i = 0; i < 2; i++) {
            int r = b_r + i * 8;
            cp16(sB + (unsigned)((st*BK + r)*PB + b_c)*4,
                 W + (size_t)(k0 + r) * N + col0 + b_c);
        }
        cp_commit();
    };

    load_st(0, 0);
    if (NIT > 1) load_st(1, BK);

    for (int it = 0; it < NIT; it++) {
        if (it == NIT - 1) cp_wait0(); else cp_wait1();
        __syncthreads();

        if (it + 2 < NIT) load_st((it + 2) % STG, (it + 2) * BK);

        int buf = it % STG;
        const unsigned* Ab = As_ + buf * 128 * PA;
        const unsigned* Bb = Bs_ + buf * BK * PB;

        #pragma unroll
        for (int kk = 0; kk < BK; kk += 8) {
            unsigned af[4][4], bf[4][2];
            #pragma unroll
            for (int mi = 0; mi < 4; mi++) {
                int m = wm * 64 + mi * 16 + gid;
                af[mi][0] = Ab[m * PA + kk + tig];
                af[mi][1] = Ab[(m + 8) * PA + kk + tig];
                af[mi][2] = Ab[m * PA + kk + tig + 4];
                af[mi][3] = Ab[(m + 8) * PA + kk + tig + 4];
            }
            #pragma unroll
            for (int ni = 0; ni < 4; ni++) {
                int n = wn * 32 + ni * 8 + gid;
                bf[ni][0] = Bb[(kk + tig) * PB + n];
                bf[ni][1] = Bb[(kk + tig + 4) * PB + n];
            }
            #pragma unroll
            for (int mi = 0; mi < 4; mi++)
                #pragma unroll
                for (int ni = 0; ni < 4; ni++)
                    mma_tf32(acc[mi][ni][0], acc[mi][ni][1], acc[mi][ni][2], acc[mi][ni][3],
                             af[mi][0], af[mi][1], af[mi][2], af[mi][3],
                             bf[ni][0], bf[ni][1]);
        }
        __syncthreads();
    }

    #pragma unroll
    for (int mi = 0; mi < 4; mi++) {
        int r0 = row0 + wm * 64 + mi * 16 + gid;
        int r1 = r0 + 8;
        #pragma unroll
        for (int ni = 0; ni < 4; ni++) {
            int c = col0 + wn * 32 + ni * 8 + tig * 2;
            float2 b2 = *(const float2*)(bias + c);
            float v00 = acc[mi][ni][0] + b2.x;
            float v01 = acc[mi][ni][1] + b2.y;
            float v10 = acc[mi][ni][2] + b2.x;
            float v11 = acc[mi][ni][3] + b2.y;
            if (RES) {
                float2 e0 = *(const float2*)(res + (size_t)r0 * N + c);
                float2 e1 = *(const float2*)(res + (size_t)r1 * N + c);
                v00 += e0.x; v01 += e0.y; v10 += e1.x; v11 += e1.y;
            }
            if (GELU) {
                v00 = v00 * 0.5f * (1.0f + erff(v00 * 0.70710678118654752f));
                v01 = v01 * 0.5f * (1.0f + erff(v01 * 0.70710678118654752f));
                v10 = v10 * 0.5f * (1.0f + erff(v10 * 0.70710678118654752f));
                v11 = v11 * 0.5f * (1.0f + erff(v11 * 0.70710678118654752f));
            }
            *(float2*)(C + (size_t)r0 * N + c) = make_float2(v00, v01);
            *(float2*)(C + (size_t)r1 * N + c) = make_float2(v10, v11);
        }
    }
}

template<bool GELU, bool RES>
__global__ void __launch_bounds__(256)
mm_tc(const float* __restrict__ A, const float* __restrict__ W,
      const float* __restrict__ bias, const float* __restrict__ res,
      float* __restrict__ C, int N, int K) {
    extern __shared__ char smem[];
    mm_body<GELU, RES>(A, W, bias, res, C, N, K,
                       blockIdx.y * 128, blockIdx.x * 128, smem);
}

// Fused QKV: z selects which projection; 3x blocks in one launch.
__global__ void __launch_bounds__(256)
qkv_tc(const float* __restrict__ y,
       const float* __restrict__ wq, const float* __restrict__ bq, float* __restrict__ q,
       const float* __restrict__ wk, const float* __restrict__ bk, float* __restrict__ k,
       const float* __restrict__ wv, const float* __restrict__ bv, float* __restrict__ v) {
    extern __shared__ char smem[];
    const float* W; const float* bias; float* C;
    if (blockIdx.z == 0)      { W = wq; bias = bq; C = q; }
    else if (blockIdx.z == 1) { W = wk; bias = bk; C = k; }
    else                      { W = wv; bias = bv; C = v; }
    mm_body<false, false>(y, W, bias, nullptr, C, EE, EE,
                          blockIdx.y * 128, blockIdx.x * 128, smem);
}

// ---------------- Scores: S = Q K^T / sqrt(E), 3-stage pipelined ------------------
__global__ void __launch_bounds__(256)
score_tc(const float* __restrict__ q, const float* __restrict__ k,
         float* __restrict__ S) {
    extern __shared__ char smem[];
    int bh = blockIdx.z;
    int b = bh / HH, h = bh % HH;
    const float* qb = q + (size_t)b * SS * EE + h * DD;
    const float* kb = k + (size_t)b * SS * EE + h * DD;
    float* Sb = S + (size_t)bh * SS * SS;

    unsigned* As_ = (unsigned*)smem;                   // [STG][128][PA]
    unsigned* Bs_ = As_ + STG * 128 * PA;              // [STG][128][PA]
    unsigned sA = (unsigned)__cvta_generic_to_shared(As_);
    unsigned sB = (unsigned)__cvta_generic_to_shared(Bs_);

    int tid  = threadIdx.x;
    int warp = tid >> 5, lane = tid & 31;
    int gid  = lane >> 2, tig = lane & 3;
    int wm   = warp & 1;
    int wn   = warp >> 1;
    int row0 = blockIdx.y * 128;
    int col0 = blockIdx.x * 128;

    int a_r = tid >> 2, a_c = (tid & 3) * 4;

    float acc[4][4][4];
    #pragma unroll
    for (int i = 0; i < 4; i++)
        #pragma unroll
        for (int j = 0; j < 4; j++)
            #pragma unroll
            for (int r = 0; r < 4; r++) acc[i][j][r] = 0.0f;

    const int NIT = DD / BK;   // 4

    auto load_st = [&](int st, int k0) {
        #pragma unroll
        for (int i = 0; i < 2; i++) {
            int r = a_r + i * 64;
            cp16(sA + (unsigned)((st*128 + r)*PA + a_c)*4,
                 qb + (size_t)(row0 + r) * EE + k0 + a_c);
            cp16(sB + (unsigned)((st*128 + r)*PA + a_c)*4,
                 kb + (size_t)(col0 + r) * EE + k0 + a_c);
        }
        cp_commit();
    };

    load_st(0, 0);
    load_st(1, BK);

    for (int it = 0; it < NIT; it++) {
        if (it == NIT - 1) cp_wait0(); else cp_wait1();
        __syncthreads();

        if (it + 2 < NIT) load_st((it + 2) % STG, (it + 2) * BK);

        int buf = it % STG;
        const unsigned* Ab = As_ + buf * 128 * PA;
        const unsigned* Bb = Bs_ + buf * 128 * PA;

        #pragma unroll
        for (int kk = 0; kk < BK; kk += 8) {
            unsigned af[4][4], bf[4][2];
            #pragma unroll
            for (int mi = 0; mi < 4; mi++) {
                int m = wm * 64 + mi * 16 + gid;
                af[mi][0] = Ab[m * PA + kk + tig];
                af[mi][1] = Ab[(m + 8) * PA + kk + tig];
                af[mi][2] = Ab[m * PA + kk + tig + 4];
                af[mi][3] = Ab[(m + 8) * PA + kk + tig + 4];
            }
            #pragma unroll
            for (int ni = 0; ni < 4; ni++) {
                int n = wn * 32 + ni * 8 + gid;
                bf[ni][0] = Bb[n * PA + kk + tig];
                bf[ni][1] = Bb[n * PA + kk + tig + 4];
            }
            #pragma unroll
            for (int mi = 0; mi < 4; mi++)
                #pragma unroll
                for (int ni = 0; ni < 4; ni++)
                    mma_tf32(acc[mi][ni][0], acc[mi][ni][1], acc[mi][ni][2], acc[mi][ni][3],
                             af[mi][0], af[mi][1], af[mi][2], af[mi][3],
                             bf[ni][0], bf[ni][1]);
        }
        __syncthreads();
    }

    const float scale = rsqrtf((float)EE);
    #pragma unroll
    for (int mi = 0; mi < 4; mi++) {
        int r0 = row0 + wm * 64 + mi * 16 + gid;
        int r1 = r0 + 8;
        #pragma unroll
        for (int ni = 0; ni < 4; ni++) {
            int c = col0 + wn * 32 + ni * 8 + tig * 2;
            *(float2*)(Sb + (size_t)r0 * SS + c) =
                make_float2(acc[mi][ni][0] * scale, acc[mi][ni][1] * scale);
            *(float2*)(Sb + (size_t)r1 * SS + c) =
                make_float2(acc[mi][ni][2] * scale, acc[mi][ni][3] * scale);
        }
    }
}

// ---------------- Row softmax over S, in place -----------------------------------
__global__ void softmax_kernel(float* __restrict__ S) {
    float* row = S + (size_t)blockIdx.y * SS * SS + (size_t)blockIdx.x * SS;
    int t = threadIdx.x;
    __shared__ float red[256];

    float vals[8];
    float lmax = -1e30f;
    #pragma unroll
    for (int r = 0; r < 8; r++) {
        vals[r] = row[t + r * 256];
        lmax = fmaxf(lmax, vals[r]);
    }
    red[t] = lmax;
    __syncthreads();
    #pragma unroll
    for (int o = 128; o > 0; o >>= 1) {
        if (t < o) red[t] = fmaxf(red[t], red[t + o]);
        __syncthreads();
    }
    float mx = red[0];
    __syncthreads();

    float lsum = 0.0f;
    #pragma unroll
    for (int r = 0; r < 8; r++) {
        vals[r] = __expf(vals[r] - mx);
        lsum += vals[r];
    }
    red[t] = lsum;
    __syncthreads();
    #pragma unroll
    for (int o = 128; o > 0; o >>= 1) {
        if (t < o) red[t] += red[t + o];
        __syncthreads();
    }
    float inv = 1.0f / red[0];
    #pragma unroll
    for (int r = 0; r < 8; r++)
        row[t + r * 256] = vals[r] * inv;
}

// ---------------- ctx = P @ V per head, 3-stage pipelined -------------------------
__global__ void __launch_bounds__(256)
ctx_tc(const float* __restrict__ S, const float* __restrict__ v,
       float* __restrict__ ctx) {
    extern __shared__ char smem[];
    int bh = blockIdx.z;
    int b = bh / HH, h = bh % HH;
    const float* Sb = S + (size_t)bh * SS * SS;
    const float* vb = v + (size_t)b * SS * EE + h * DD;
    int row0 = blockIdx.y * 128;

    unsigned* Ps_ = (unsigned*)smem;                   // [STG][128][PA]
    unsigned* Vs_ = Ps_ + STG * 128 * PA;              // [STG][BK][PV]
    unsigned sP = (unsigned)__cvta_generic_to_shared(Ps_);
    unsigned sV = (unsigned)__cvta_generic_to_shared(Vs_);

    int tid  = threadIdx.x;
    int warp = tid >> 5, lane = tid & 31;
    int gid  = lane >> 2, tig = lane & 3;
    int wm   = warp & 1;
    int wn   = warp >> 1;

    int a_r = tid >> 2, a_c = (tid & 3) * 4;
    int v_r = tid >> 4, v_c = (tid & 15) * 4;

    float acc[4][2][4];
    #pragma unroll
    for (int i = 0; i < 4; i++)
        #pragma unroll
        for (int j = 0; j < 2; j++)
            #pragma unroll
            for (int r = 0; r < 4; r++) acc[i][j][r] = 0.0f;

    const int NIT = SS / BK;   // 128

    auto load_st = [&](int st, int k0) {
        #pragma unroll
        for (int i = 0; i < 2; i++) {
            int r = a_r + i * 64;
            cp16(sP + (unsigned)((st*128 + r)*PA + a_c)*4,
                 Sb + (size_t)(row0 + r) * SS + k0 + a_c);
        }
        cp16(sV + (unsigned)((st*BK + v_r)*PV + v_c)*4,
             vb + (size_t)(k0 + v_r) * EE + v_c);
        cp_commit();
    };

    load_st(0, 0);
    load_st(1, BK);

    for (int it = 0; it < NIT; it++) {
        if (it == NIT - 1) cp_wait0(); else cp_wait1();
        __syncthreads();

        if (it + 2 < NIT) load_st((it + 2) % STG, (it + 2) * BK);

        int buf = it % STG;
        const unsigned* Pb = Ps_ + buf * 128 * PA;
        const unsigned* Vb = Vs_ + buf * BK * PV;

        #pragma unroll
        for (int kk = 0; kk < BK; kk += 8) {
            unsigned af[4][4], bf[2][2];
            #pragma unroll
            for (int mi = 0; mi < 4; mi++) {
                int m = wm * 64 + mi * 16 + gid;
                af[mi][0] = Pb[m * PA + kk + tig];
                af[mi][1] = Pb[(m + 8) * PA + kk + tig];
                af[mi][2] = Pb[m * PA + kk + tig + 4];
                af[mi][3] = Pb[(m + 8) * PA + kk + tig + 4];
            }
            #pragma unroll
            for (int ni = 0; ni < 2; ni++) {
                int n = wn * 16 + ni * 8 + gid;
                bf[ni][0] = Vb[(kk + tig) * PV + n];
                bf[ni][1] = Vb[(kk + tig + 4) * PV + n];
            }
            #pragma unroll
            for (int mi = 0; mi < 4; mi++)
                #pragma unroll
                for (int ni = 0; ni < 2; ni++)
                    mma_tf32(acc[mi][ni][0], acc[mi][ni][1], acc[mi][ni][2], acc[mi][ni][3],
                             af[mi][0], af[mi][1], af[mi][2], af[mi][3],
                             bf[ni][0], bf[ni][1]);
        }
        __syncthreads();
    }

    #pragma unroll
    for (int mi = 0; mi < 4; mi++) {
        int r0 = row0 + wm * 64 + mi * 16 + gid;
        int r1 = r0 + 8;
        #pragma unroll
        for (int ni = 0; ni < 2; ni++) {
            int c = h * DD + wn * 16 + ni * 8 + tig * 2;
            *(float2*)(ctx + (size_t)(b * SS + r0) * EE + c) =
                make_float2(acc[mi][ni][0], acc[mi][ni][1]);
            *(float2*)(ctx + (size_t)(b * SS + r1) * EE + c) =
                make_float2(acc[mi][ni][2], acc[mi][ni][3]);
        }
    }
}

// ---------------- launch ---------------------------------------------------------
extern "C" void kernel_launch(void* const* d_in, const int* in_sizes, int n_in,
                              void* d_out, int out_size) {
    (void)in_sizes; (void)n_in; (void)out_size;
    const float* x     = (const float*)d_in[0];
    const float* ln1_g = (const float*)d_in[1];
    const float* ln1_b = (const float*)d_in[2];
    const float* wq    = (const float*)d_in[3];
    const float* bq    = (const float*)d_in[4];
    const float* wk    = (const float*)d_in[5];
    const float* bk    = (const float*)d_in[6];
    const float* wv    = (const float*)d_in[7];
    const float* bv    = (const float*)d_in[8];
    const float* wo    = (const float*)d_in[9];
    const float* bo    = (const float*)d_in[10];
    const float* w1    = (const float*)d_in[11];
    const float* b1    = (const float*)d_in[12];
    const float* w2    = (const float*)d_in[13];
    const float* b2    = (const float*)d_in[14];
    const float* ln2_g = (const float*)d_in[15];
    const float* ln2_b = (const float*)d_in[16];
    float* out = (float*)d_out;

    float *y, *q, *k, *v, *ctx, *y2, *z, *hbuf, *sbuf;
    cudaGetSymbolAddress((void**)&y,    g_y);
    cudaGetSymbolAddress((void**)&q,    g_q);
    cudaGetSymbolAddress((void**)&k,    g_k);
    cudaGetSymbolAddress((void**)&v,    g_v);
    cudaGetSymbolAddress((void**)&ctx,  g_ctx);
    cudaGetSymbolAddress((void**)&y2,   g_y2);
    cudaGetSymbolAddress((void**)&z,    g_z);
    cudaGetSymbolAddress((void**)&hbuf, g_h);
    cudaGetSymbolAddress((void**)&sbuf, g_s);

    // opt-in to >48KB dynamic smem (host-side attribute; capture-safe)
    static bool attr_done = false;
    if (!attr_done) {
        cudaFuncSetAttribute(mm_tc<false,false>, cudaFuncAttributeMaxDynamicSharedMemorySize, SM_MM);
        cudaFuncSetAttribute(mm_tc<false,true>,  cudaFuncAttributeMaxDynamicSharedMemorySize, SM_MM);
        cudaFuncSetAttribute(mm_tc<true,false>,  cudaFuncAttributeMaxDynamicSharedMemorySize, SM_MM);
        cudaFuncSetAttribute(qkv_tc,   cudaFuncAttributeMaxDynamicSharedMemorySize, SM_MM);
        cudaFuncSetAttribute(score_tc, cudaFuncAttributeMaxDynamicSharedMemorySize, SM_SCORE);
        cudaFuncSetAttribute(ctx_tc,   cudaFuncAttributeMaxDynamicSharedMemorySize, SM_CTX);
        attr_done = true;
    }

    dim3 blk(256);

    // 1. y = LN1(x)
    ln_kernel<<<MM, blk>>>(x, ln1_g, ln1_b, y);

    // 2. fused q,k,v projections
    dim3 g_qkv(EE / 128, MM / 128, 3);
    qkv_tc<<<g_qkv, blk, SM_MM>>>(y, wq, bq, q, wk, bk, k, wv, bv, v);

    // 3a. S = Q K^T / sqrt(E)
    dim3 g_sc(SS / 128, SS / 128, BH);
    score_tc<<<g_sc, blk, SM_SCORE>>>(q, k, sbuf);

    // 3b. softmax rows of S
    dim3 g_sm(SS, BH);
    softmax_kernel<<<g_sm, blk>>>(sbuf);

    // 3c. ctx = P @ V
    dim3 g_cx(1, SS / 128, BH);
    ctx_tc<<<g_cx, blk, SM_CTX>>>(sbuf, v, ctx);

    // 4. y2 = x + ctx @ wo + bo
    dim3 g_e(EE / 128, MM / 128);
    mm_tc<false, true><<<g_e, blk, SM_MM>>>(ctx, wo, bo, x, y2, EE, EE);

    // 5. z = LN2(y2)
    ln_kernel<<<MM, blk>>>(y2, ln2_g, ln2_b, z);

    // 6. h = gelu(z @ w1 + b1)
    dim3 g_ff(FF / 128, MM / 128);
    mm_tc<true, false><<<g_ff, blk, SM_MM>>>(z, w1, b1, nullptr, hbuf, FF, EE);

    // 7. out = y2 + h @ w2 + b2
    mm_tc<false, true><<<g_e, blk, SM_MM>>>(hbuf, w2, b2, y2, out, EE, FF);
}

// round 6
// speedup vs baseline: 31.4338x; 1.2003x over previous
#include <cuda_runtime.h>
#include <math.h>

#define BB 2
#define SS 2048
#define EE 768
#define HH 12
#define DD 64
#define MM (BB*SS)      /* 4096 rows */
#define FF (4*EE)       /* 3072 */
#define BH (BB*HH)      /* 24 */

#define BK 16
#define STG 3
#define PA 20           /* [row][k] pad: 4*gid+tig distinct */
#define PB 136          /* [k][n] pad: 136 mod 32 = 8 */

/* flash attention tiles */
#define FM 128          /* q rows per CTA */
#define FK 64           /* keys per iteration */
#define PQ 68           /* Q/P/K pitch ([row][k]): 68 mod 32 = 4 */
#define PVV 72          /* V pitch ([k][n]): 72 mod 32 = 8 */
#define FSTG 3

// dynamic smem sizes (bytes)
#define SM_MM    (STG*(128*PA + BK*PB)*4)
#define SM_FLASH ((128*PQ + FSTG*FK*PQ + FSTG*FK*PVV)*4)   /* 142336 */

// ---------------- scratch (device globals; no allocation allowed) ----------------
__device__ float g_y  [MM*EE];
__device__ float g_q  [MM*EE];
__device__ float g_k  [MM*EE];
__device__ float g_v  [MM*EE];
__device__ float g_ctx[MM*EE];
__device__ float g_y2 [MM*EE];
__device__ float g_z  [MM*EE];
__device__ float g_h  [MM*FF];

// ---------------- helpers ---------------------------------------------------------
__device__ __forceinline__ void mma_tf32(float& c0, float& c1, float& c2, float& c3,
                                         unsigned a0, unsigned a1, unsigned a2, unsigned a3,
                                         unsigned b0, unsigned b1) {
    asm volatile(
        "mma.sync.aligned.m16n8k8.row.col.f32.tf32.tf32.f32 "
        "{%0,%1,%2,%3}, {%4,%5,%6,%7}, {%8,%9}, {%0,%1,%2,%3};"
        : "+f"(c0), "+f"(c1), "+f"(c2), "+f"(c3)
        : "r"(a0), "r"(a1), "r"(a2), "r"(a3), "r"(b0), "r"(b1));
}

__device__ __forceinline__ void cp16(unsigned saddr, const void* g) {
    asm volatile("cp.async.cg.shared.global [%0], [%1], 16;" :: "r"(saddr), "l"(g));
}
__device__ __forceinline__ void cp_commit() { asm volatile("cp.async.commit_group;"); }
__device__ __forceinline__ void cp_wait0()  { asm volatile("cp.async.wait_group 0;"); }
__device__ __forceinline__ void cp_wait1()  { asm volatile("cp.async.wait_group 1;"); }
__device__ __forceinline__ void cp_wait2()  { asm volatile("cp.async.wait_group 2;"); }

// ---------------- LayerNorm -------------------------------------------------------
__global__ void ln_kernel(const float* __restrict__ x, const float* __restrict__ gw,
                          const float* __restrict__ bw, float* __restrict__ out) {
    int row = blockIdx.x;
    int t = threadIdx.x;
    const float* xr = x + (size_t)row * EE;
    float v0 = xr[t], v1 = xr[t + 256], v2 = xr[t + 512];
    __shared__ float red[256];
    red[t] = v0 + v1 + v2;
    __syncthreads();
    #pragma unroll
    for (int o = 128; o > 0; o >>= 1) {
        if (t < o) red[t] += red[t + o];
        __syncthreads();
    }
    float mean = red[0] * (1.0f / EE);
    __syncthreads();
    float d0 = v0 - mean, d1 = v1 - mean, d2 = v2 - mean;
    red[t] = d0*d0 + d1*d1 + d2*d2;
    __syncthreads();
    #pragma unroll
    for (int o = 128; o > 0; o >>= 1) {
        if (t < o) red[t] += red[t + o];
        __syncthreads();
    }
    float rstd = rsqrtf(red[0] * (1.0f / EE) + 1e-5f);
    float* orow = out + (size_t)row * EE;
    orow[t]       = d0 * rstd * gw[t]       + bw[t];
    orow[t + 256] = d1 * rstd * gw[t + 256] + bw[t + 256];
    orow[t + 512] = d2 * rstd * gw[t + 512] + bw[t + 512];
}

// ---------------- GEMM core: 128x128 tile, BK=16, 3-stage cp.async ----------------
template<bool GELU, bool RES>
__device__ __forceinline__ void
mm_body(const float* __restrict__ A, const float* __restrict__ W,
        const float* __restrict__ bias, const float* __restrict__ res,
        float* __restrict__ C, int N, int K, int row0, int col0, char* smem) {
    unsigned* As_ = (unsigned*)smem;
    unsigned* Bs_ = As_ + STG * 128 * PA;
    unsigned sA = (unsigned)__cvta_generic_to_shared(As_);
    unsigned sB = (unsigned)__cvta_generic_to_shared(Bs_);

    int tid  = threadIdx.x;
    int warp = tid >> 5, lane = tid & 31;
    int gid  = lane >> 2, tig = lane & 3;
    int wm   = warp & 1;
    int wn   = warp >> 1;

    int a_r = tid >> 2, a_c = (tid & 3) * 4;
    int b_r = tid >> 5, b_c = (tid & 31) * 4;

    float acc[4][4][4];
    #pragma unroll
    for (int i = 0; i < 4; i++)
        #pragma unroll
        for (int j = 0; j < 4; j++)
            #pragma unroll
            for (int r = 0; r < 4; r++) acc[i][j][r] = 0.0f;

    int NIT = K / BK;

    auto load_st = [&](int st, int k0) {
        #pragma unroll
        for (int i = 0; i < 2; i++) {
            int r = a_r + i * 64;
            cp16(sA + (unsigned)((st*128 + r)*PA + a_c)*4,
                 A + (size_t)(row0 + r) * K + k0 + a_c);
        }
        #pragma unroll
        for (int i = 0; i < 2; i++) {
            int r = b_r + i * 8;
            cp16(sB + (unsigned)((st*BK + r)*PB + b_c)*4,
                 W + (size_t)(k0 + r) * N + col0 + b_c);
        }
        cp_commit();
    };

    load_st(0, 0);
    if (NIT > 1) load_st(1, BK);

    for (int it = 0; it < NIT; it++) {
        if (it == NIT - 1) cp_wait0(); else cp_wait1();
        __syncthreads();

        if (it + 2 < NIT) load_st((it + 2) % STG, (it + 2) * BK);

        int buf = it % STG;
        const unsigned* Ab = As_ + buf * 128 * PA;
        const unsigned* Bb = Bs_ + buf * BK * PB;

        #pragma unroll
        for (int kk = 0; kk < BK; kk += 8) {
            unsigned af[4][4], bf[4][2];
            #pragma unroll
            for (int mi = 0; mi < 4; mi++) {
                int m = wm * 64 + mi * 16 + gid;
                af[mi][0] = Ab[m * PA + kk + tig];
                af[mi][1] = Ab[(m + 8) * PA + kk + tig];
                af[mi][2] = Ab[m * PA + kk + tig + 4];
                af[mi][3] = Ab[(m + 8) * PA + kk + tig + 4];
            }
            #pragma unroll
            for (int ni = 0; ni < 4; ni++) {
                int n = wn * 32 + ni * 8 + gid;
                bf[ni][0] = Bb[(kk + tig) * PB + n];
                bf[ni][1] = Bb[(kk + tig + 4) * PB + n];
            }
            #pragma unroll
            for (int mi = 0; mi < 4; mi++)
                #pragma unroll
                for (int ni = 0; ni < 4; ni++)
                    mma_tf32(acc[mi][ni][0], acc[mi][ni][1], acc[mi][ni][2], acc[mi][ni][3],
                             af[mi][0], af[mi][1], af[mi][2], af[mi][3],
                             bf[ni][0], bf[ni][1]);
        }
        __syncthreads();
    }

    #pragma unroll
    for (int mi = 0; mi < 4; mi++) {
        int r0 = row0 + wm * 64 + mi * 16 + gid;
        int r1 = r0 + 8;
        #pragma unroll
        for (int ni = 0; ni < 4; ni++) {
            int c = col0 + wn * 32 + ni * 8 + tig * 2;
            float2 b2 = *(const float2*)(bias + c);
            float v00 = acc[mi][ni][0] + b2.x;
            float v01 = acc[mi][ni][1] + b2.y;
            float v10 = acc[mi][ni][2] + b2.x;
            float v11 = acc[mi][ni][3] + b2.y;
            if (RES) {
                float2 e0 = *(const float2*)(res + (size_t)r0 * N + c);
                float2 e1 = *(const float2*)(res + (size_t)r1 * N + c);
                v00 += e0.x; v01 += e0.y; v10 += e1.x; v11 += e1.y;
            }
            if (GELU) {
                v00 = v00 * 0.5f * (1.0f + erff(v00 * 0.70710678118654752f));
                v01 = v01 * 0.5f * (1.0f + erff(v01 * 0.70710678118654752f));
                v10 = v10 * 0.5f * (1.0f + erff(v10 * 0.70710678118654752f));
                v11 = v11 * 0.5f * (1.0f + erff(v11 * 0.70710678118654752f));
            }
            *(float2*)(C + (size_t)r0 * N + c) = make_float2(v00, v01);
            *(float2*)(C + (size_t)r1 * N + c) = make_float2(v10, v11);
        }
    }
}

template<bool GELU, bool RES>
__global__ void __launch_bounds__(256)
mm_tc(const float* __restrict__ A, const float* __restrict__ W,
      const float* __restrict__ bias, const float* __restrict__ res,
      float* __restrict__ C, int N, int K) {
    extern __shared__ char smem[];
    mm_body<GELU, RES>(A, W, bias, res, C, N, K,
                       blockIdx.y * 128, blockIdx.x * 128, smem);
}

__global__ void __launch_bounds__(256)
qkv_tc(const float* __restrict__ y,
       const float* __restrict__ wq, const float* __restrict__ bq, float* __restrict__ q,
       const float* __restrict__ wk, const float* __restrict__ bk, float* __restrict__ k,
       const float* __restrict__ wv, const float* __restrict__ bv, float* __restrict__ v) {
    extern __shared__ char smem[];
    const float* W; const float* bias; float* C;
    if (blockIdx.z == 0)      { W = wq; bias = bq; C = q; }
    else if (blockIdx.z == 1) { W = wk; bias = bk; C = k; }
    else                      { W = wv; bias = bv; C = v; }
    mm_body<false, false>(y, W, bias, nullptr, C, EE, EE,
                          blockIdx.y * 128, blockIdx.x * 128, smem);
}

// ---------------- Flash attention: fused scores+softmax+PV ------------------------
// One CTA per (b, h, 128 q-rows). 8 warps, warp w owns rows [w*16, w*16+16).
// K/V streamed in 64-key tiles, 3-stage cp.async. Online softmax; P scratch is
// warp-private smem (reuses the Q region).
__global__ void __launch_bounds__(256)
flash_tc(const float* __restrict__ q, const float* __restrict__ k,
         const float* __restrict__ v, float* __restrict__ ctx) {
    extern __shared__ char smem[];
    float* QP = (float*)smem;                    // [128][PQ]  Q, then per-warp P
    float* Ks = QP + 128 * PQ;                   // [FSTG][FK][PQ]   K: [key][d]
    float* Vs = Ks + FSTG * FK * PQ;             // [FSTG][FK][PVV]  V: [key][d] -> [k][n]
    unsigned sQ = (unsigned)__cvta_generic_to_shared(QP);
    unsigned sK = (unsigned)__cvta_generic_to_shared(Ks);
    unsigned sV = (unsigned)__cvta_generic_to_shared(Vs);

    int bh = blockIdx.y;
    int b = bh / HH, h = bh % HH;
    int row0 = blockIdx.x * FM;
    const float* qb = q + (size_t)b * SS * EE + h * DD;
    const float* kb = k + (size_t)b * SS * EE + h * DD;
    const float* vb = v + (size_t)b * SS * EE + h * DD;

    int tid  = threadIdx.x;
    int warp = tid >> 5, lane = tid & 31;
    int gid  = lane >> 2, tig = lane & 3;

    int l_r = tid >> 4, l_c = (tid & 15) * 4;    // 16 rows x 16 float4-chunks per pass

    // group 0: Q tile (128 x 64)
    #pragma unroll
    for (int i = 0; i < 8; i++) {
        int r = l_r + i * 16;
        cp16(sQ + (unsigned)(r * PQ + l_c) * 4, qb + (size_t)(row0 + r) * EE + l_c);
    }
    cp_commit();

    auto load_kv = [&](int st, int k0) {
        #pragma unroll
        for (int i = 0; i < 4; i++) {
            int r = l_r + i * 16;
            cp16(sK + (unsigned)((st*FK + r) * PQ + l_c) * 4,
                 kb + (size_t)(k0 + r) * EE + l_c);
        }
        #pragma unroll
        for (int i = 0; i < 4; i++) {
            int r = l_r + i * 16;
            cp16(sV + (unsigned)((st*FK + r) * PVV + l_c) * 4,
                 vb + (size_t)(k0 + r) * EE + l_c);
        }
        cp_commit();
    };
    load_kv(0, 0);
    load_kv(1, FK);

    cp_wait2();           // Q ready
    __syncthreads();

    // preload Q fragments (warp-private rows)
    int m0r = warp * 16 + gid;
    const unsigned* QPu = (const unsigned*)QP;
    unsigned qf[8][4];
    #pragma unroll
    for (int kc = 0; kc < 8; kc++) {
        qf[kc][0] = QPu[m0r * PQ + kc*8 + tig];
        qf[kc][1] = QPu[(m0r + 8) * PQ + kc*8 + tig];
        qf[kc][2] = QPu[m0r * PQ + kc*8 + tig + 4];
        qf[kc][3] = QPu[(m0r + 8) * PQ + kc*8 + tig + 4];
    }
    __syncwarp();

    float* Pw = QP + (warp * 16) * PQ;           // warp-private P strip [16][PQ]
    const unsigned* Pwu = (const unsigned*)Pw;

    float o[8][4];
    #pragma unroll
    for (int ni = 0; ni < 8; ni++)
        #pragma unroll
        for (int r = 0; r < 4; r++) o[ni][r] = 0.0f;
    float mx0 = -1e30f, mx1 = -1e30f, l0 = 0.0f, l1 = 0.0f;
    const float scale = rsqrtf((float)EE);

    const int NIT = SS / FK;   // 32
    for (int it = 0; it < NIT; it++) {
        if (it == NIT - 1) cp_wait0(); else cp_wait1();
        __syncthreads();
        if (it + 2 < NIT) load_kv((it + 2) % FSTG, (it + 2) * FK);

        int buf = it % FSTG;
        const unsigned* Kb = (const unsigned*)(Ks + buf * FK * PQ);
        const unsigned* Vb = (const unsigned*)(Vs + buf * FK * PVV);

        // ---- S = Q K^T (16 x 64 per warp) ----
        float s[8][4];
        #pragma unroll
        for (int ni = 0; ni < 8; ni++)
            #pragma unroll
            for (int r = 0; r < 4; r++) s[ni][r] = 0.0f;

        #pragma unroll
        for (int kc = 0; kc < 8; kc++) {
            #pragma unroll
            for (int ni = 0; ni < 8; ni++) {
                int n = ni * 8 + gid;
                unsigned b0 = Kb[n * PQ + kc*8 + tig];
                unsigned b1 = Kb[n * PQ + kc*8 + tig + 4];
                mma_tf32(s[ni][0], s[ni][1], s[ni][2], s[ni][3],
                         qf[kc][0], qf[kc][1], qf[kc][2], qf[kc][3], b0, b1);
            }
        }

        // ---- online softmax ----
        float rm0 = -1e30f, rm1 = -1e30f;
        #pragma unroll
        for (int ni = 0; ni < 8; ni++) {
            s[ni][0] *= scale; s[ni][1] *= scale;
            s[ni][2] *= scale; s[ni][3] *= scale;
            rm0 = fmaxf(rm0, fmaxf(s[ni][0], s[ni][1]));
            rm1 = fmaxf(rm1, fmaxf(s[ni][2], s[ni][3]));
        }
        rm0 = fmaxf(rm0, __shfl_xor_sync(0xffffffffu, rm0, 1));
        rm0 = fmaxf(rm0, __shfl_xor_sync(0xffffffffu, rm0, 2));
        rm1 = fmaxf(rm1, __shfl_xor_sync(0xffffffffu, rm1, 1));
        rm1 = fmaxf(rm1, __shfl_xor_sync(0xffffffffu, rm1, 2));

        float mn0 = fmaxf(mx0, rm0), mn1 = fmaxf(mx1, rm1);
        float f0 = __expf(mx0 - mn0), f1 = __expf(mx1 - mn1);
        mx0 = mn0; mx1 = mn1;

        float rs0 = 0.0f, rs1 = 0.0f;
        #pragma unroll
        for (int ni = 0; ni < 8; ni++) {
            float p0 = __expf(s[ni][0] - mn0);
            float p1 = __expf(s[ni][1] - mn0);
            float p2 = __expf(s[ni][2] - mn1);
            float p3 = __expf(s[ni][3] - mn1);
            rs0 += p0 + p1; rs1 += p2 + p3;
            *(float2*)(Pw + gid * PQ + ni*8 + tig*2)       = make_float2(p0, p1);
            *(float2*)(Pw + (gid + 8) * PQ + ni*8 + tig*2) = make_float2(p2, p3);
        }
        rs0 += __shfl_xor_sync(0xffffffffu, rs0, 1);
        rs0 += __shfl_xor_sync(0xffffffffu, rs0, 2);
        rs1 += __shfl_xor_sync(0xffffffffu, rs1, 1);
        rs1 += __shfl_xor_sync(0xffffffffu, rs1, 2);
        l0 = l0 * f0 + rs0;
        l1 = l1 * f1 + rs1;

        #pragma unroll
        for (int ni = 0; ni < 8; ni++) {
            o[ni][0] *= f0; o[ni][1] *= f0;
            o[ni][2] *= f1; o[ni][3] *= f1;
        }
        __syncwarp();

        // ---- O += P V (16 x 64 per warp) ----
        #pragma unroll
        for (int kc = 0; kc < 8; kc++) {
            unsigned a0 = Pwu[gid * PQ + kc*8 + tig];
            unsigned a1 = Pwu[(gid + 8) * PQ + kc*8 + tig];
            unsigned a2 = Pwu[gid * PQ + kc*8 + tig + 4];
            unsigned a3 = Pwu[(gid + 8) * PQ + kc*8 + tig + 4];
            #pragma unroll
            for (int ni = 0; ni < 8; ni++) {
                int n = ni * 8 + gid;
                unsigned b0 = Vb[(kc*8 + tig) * PVV + n];
                unsigned b1 = Vb[(kc*8 + tig + 4) * PVV + n];
                mma_tf32(o[ni][0], o[ni][1], o[ni][2], o[ni][3],
                         a0, a1, a2, a3, b0, b1);
            }
        }
        __syncwarp();
    }

    // ---- normalize + write ----
    float i0 = 1.0f / l0, i1 = 1.0f / l1;
    float* c0row = ctx + (size_t)(b * SS + row0 + m0r) * EE + h * DD;
    float* c1row = ctx + (size_t)(b * SS + row0 + m0r + 8) * EE + h * DD;
    #pragma unroll
    for (int ni = 0; ni < 8; ni++) {
        int c = ni * 8 + tig * 2;
        *(float2*)(c0row + c) = make_float2(o[ni][0] * i0, o[ni][1] * i0);
        *(float2*)(c1row + c) = make_float2(o[ni][2] * i1, o[ni][3] * i1);
    }
}

// ---------------- launch ---------------------------------------------------------
extern "C" void kernel_launch(void* const* d_in, const int* in_sizes, int n_in,
                              void* d_out, int out_size) {
    (void)in_sizes; (void)n_in; (void)out_size;
    const float* x     = (const float*)d_in[0];
    const float* ln1_g = (const float*)d_in[1];
    const float* ln1_b = (const float*)d_in[2];
    const float* wq    = (const float*)d_in[3];
    const float* bq    = (const float*)d_in[4];
    const float* wk    = (const float*)d_in[5];
    const float* bk    = (const float*)d_in[6];
    const float* wv    = (const float*)d_in[7];
    const float* bv    = (const float*)d_in[8];
    const float* wo    = (const float*)d_in[9];
    const float* bo    = (const float*)d_in[10];
    const float* w1    = (const float*)d_in[11];
    const float* b1    = (const float*)d_in[12];
    const float* w2    = (const float*)d_in[13];
    const float* b2    = (const float*)d_in[14];
    const float* ln2_g = (const float*)d_in[15];
    const float* ln2_b = (const float*)d_in[16];
    float* out = (float*)d_out;

    float *y, *q, *k, *v, *ctx, *y2, *z, *hbuf;
    cudaGetSymbolAddress((void**)&y,    g_y);
    cudaGetSymbolAddress((void**)&q,    g_q);
    cudaGetSymbolAddress((void**)&k,    g_k);
    cudaGetSymbolAddress((void**)&v,    g_v);
    cudaGetSymbolAddress((void**)&ctx,  g_ctx);
    cudaGetSymbolAddress((void**)&y2,   g_y2);
    cudaGetSymbolAddress((void**)&z,    g_z);
    cudaGetSymbolAddress((void**)&hbuf, g_h);

    static bool attr_done = false;
    if (!attr_done) {
        cudaFuncSetAttribute(mm_tc<false,false>, cudaFuncAttributeMaxDynamicSharedMemorySize, SM_MM);
        cudaFuncSetAttribute(mm_tc<false,true>,  cudaFuncAttributeMaxDynamicSharedMemorySize, SM_MM);
        cudaFuncSetAttribute(mm_tc<true,false>,  cudaFuncAttributeMaxDynamicSharedMemorySize, SM_MM);
        cudaFuncSetAttribute(qkv_tc,   cudaFuncAttributeMaxDynamicSharedMemorySize, SM_MM);
        cudaFuncSetAttribute(flash_tc, cudaFuncAttributeMaxDynamicSharedMemorySize, SM_FLASH);
        attr_done = true;
    }

    dim3 blk(256);

    // 1. y = LN1(x)
    ln_kernel<<<MM, blk>>>(x, ln1_g, ln1_b, y);

    // 2. fused q,k,v projections
    dim3 g_qkv(EE / 128, MM / 128, 3);
    qkv_tc<<<g_qkv, blk, SM_MM>>>(y, wq, bq, q, wk, bk, k, wv, bv, v);

    // 3. flash attention (fused scores + softmax + PV)
    dim3 g_fl(SS / FM, BH);
    flash_tc<<<g_fl, blk, SM_FLASH>>>(q, k, v, ctx);

    // 4. y2 = x + ctx @ wo + bo
    dim3 g_e(EE / 128, MM / 128);
    mm_tc<false, true><<<g_e, blk, SM_MM>>>(ctx, wo, bo, x, y2, EE, EE);

    // 5. z = LN2(y2)
    ln_kernel<<<MM, blk>>>(y2, ln2_g, ln2_b, z);

    // 6. h = gelu(z @ w1 + b1)
    dim3 g_ff(FF / 128, MM / 128);
    mm_tc<true, false><<<g_ff, blk, SM_MM>>>(z, w1, b1, nullptr, hbuf, FF, EE);

    // 7. out = y2 + h @ w2 + b2
    mm_tc<false, true><<<g_e, blk, SM_MM>>>(hbuf, w2, b2, y2, out, EE, FF);
}

// round 7
// speedup vs baseline: 33.9296x; 1.0794x over previous
#include <cuda_runtime.h>
#include <math.h>

#define BB 2
#define SS 2048
#define EE 768
#define HH 12
#define DD 64
#define MM (BB*SS)      /* 4096 rows */
#define FF (4*EE)       /* 3072 */
#define BH (BB*HH)      /* 24 */

#define BK 16
#define STG 3
#define PA 20           /* [row][k] pad */
#define PB 136          /* [k][n] pad */

/* flash attention tiles */
#define FM 128          /* q rows per CTA */
#define FK 32           /* keys per iteration */
#define PQ 68           /* Q/P/K pitch */
#define PVV 72          /* V pitch */
#define FSTG 4

// dynamic smem sizes (bytes)
#define SM_MM    (STG*(128*PA + BK*PB)*4)
#define SM_MM64  (STG*(64*PA  + BK*PB)*4)
#define SM_FLASH ((128*PQ + FSTG*FK*PQ + FSTG*FK*PVV)*4)   /* 106496 */

// ---------------- scratch (device globals; no allocation allowed) ----------------
__device__ float g_y  [MM*EE];
__device__ float g_q  [MM*EE];
__device__ float g_k  [MM*EE];
__device__ float g_v  [MM*EE];
__device__ float g_ctx[MM*EE];
__device__ float g_y2 [MM*EE];
__device__ float g_z  [MM*EE];
__device__ float g_h  [MM*FF];

// ---------------- helpers ---------------------------------------------------------
__device__ __forceinline__ void mma_tf32(float& c0, float& c1, float& c2, float& c3,
                                         unsigned a0, unsigned a1, unsigned a2, unsigned a3,
                                         unsigned b0, unsigned b1) {
    asm volatile(
        "mma.sync.aligned.m16n8k8.row.col.f32.tf32.tf32.f32 "
        "{%0,%1,%2,%3}, {%4,%5,%6,%7}, {%8,%9}, {%0,%1,%2,%3};"
        : "+f"(c0), "+f"(c1), "+f"(c2), "+f"(c3)
        : "r"(a0), "r"(a1), "r"(a2), "r"(a3), "r"(b0), "r"(b1));
}

__device__ __forceinline__ void cp16(unsigned saddr, const void* g) {
    asm volatile("cp.async.cg.shared.global [%0], [%1], 16;" :: "r"(saddr), "l"(g));
}
__device__ __forceinline__ void cp_commit() { asm volatile("cp.async.commit_group;"); }
__device__ __forceinline__ void cp_wait0()  { asm volatile("cp.async.wait_group 0;"); }
__device__ __forceinline__ void cp_wait1()  { asm volatile("cp.async.wait_group 1;"); }
__device__ __forceinline__ void cp_wait2()  { asm volatile("cp.async.wait_group 2;"); }
__device__ __forceinline__ void cp_wait3()  { asm volatile("cp.async.wait_group 3;"); }

// ---------------- LayerNorm -------------------------------------------------------
__global__ void ln_kernel(const float* __restrict__ x, const float* __restrict__ gw,
                          const float* __restrict__ bw, float* __restrict__ out) {
    int row = blockIdx.x;
    int t = threadIdx.x;
    const float* xr = x + (size_t)row * EE;
    float v0 = xr[t], v1 = xr[t + 256], v2 = xr[t + 512];
    __shared__ float red[256];
    red[t] = v0 + v1 + v2;
    __syncthreads();
    #pragma unroll
    for (int o = 128; o > 0; o >>= 1) {
        if (t < o) red[t] += red[t + o];
        __syncthreads();
    }
    float mean = red[0] * (1.0f / EE);
    __syncthreads();
    float d0 = v0 - mean, d1 = v1 - mean, d2 = v2 - mean;
    red[t] = d0*d0 + d1*d1 + d2*d2;
    __syncthreads();
    #pragma unroll
    for (int o = 128; o > 0; o >>= 1) {
        if (t < o) red[t] += red[t + o];
        __syncthreads();
    }
    float rstd = rsqrtf(red[0] * (1.0f / EE) + 1e-5f);
    float* orow = out + (size_t)row * EE;
    orow[t]       = d0 * rstd * gw[t]       + bw[t];
    orow[t + 256] = d1 * rstd * gw[t + 256] + bw[t + 256];
    orow[t + 512] = d2 * rstd * gw[t + 512] + bw[t + 512];
}

// ---------------- GEMM epilogue helper --------------------------------------------
template<bool GELU, bool RES>
__device__ __forceinline__ void epi_write(float* C, const float* bias, const float* res,
                                          int N, int r0, int r1, int c,
                                          float v00, float v01, float v10, float v11) {
    float2 b2 = *(const float2*)(bias + c);
    v00 += b2.x; v01 += b2.y; v10 += b2.x; v11 += b2.y;
    if (RES) {
        float2 e0 = *(const float2*)(res + (size_t)r0 * N + c);
        float2 e1 = *(const float2*)(res + (size_t)r1 * N + c);
        v00 += e0.x; v01 += e0.y; v10 += e1.x; v11 += e1.y;
    }
    if (GELU) {
        v00 = v00 * 0.5f * (1.0f + erff(v00 * 0.70710678118654752f));
        v01 = v01 * 0.5f * (1.0f + erff(v01 * 0.70710678118654752f));
        v10 = v10 * 0.5f * (1.0f + erff(v10 * 0.70710678118654752f));
        v11 = v11 * 0.5f * (1.0f + erff(v11 * 0.70710678118654752f));
    }
    *(float2*)(C + (size_t)r0 * N + c) = make_float2(v00, v01);
    *(float2*)(C + (size_t)r1 * N + c) = make_float2(v10, v11);
}

// ---------------- GEMM core 128x128, BK=16, 3-stage cp.async ----------------------
template<bool GELU, bool RES>
__device__ __forceinline__ void
mm_body(const float* __restrict__ A, const float* __restrict__ W,
        const float* __restrict__ bias, const float* __restrict__ res,
        float* __restrict__ C, int N, int K, int row0, int col0, char* smem) {
    unsigned* As_ = (unsigned*)smem;
    unsigned* Bs_ = As_ + STG * 128 * PA;
    unsigned sA = (unsigned)__cvta_generic_to_shared(As_);
    unsigned sB = (unsigned)__cvta_generic_to_shared(Bs_);

    int tid  = threadIdx.x;
    int warp = tid >> 5, lane = tid & 31;
    int gid  = lane >> 2, tig = lane & 3;
    int wm   = warp & 1;
    int wn   = warp >> 1;

    int a_r = tid >> 2, a_c = (tid & 3) * 4;
    int b_r = tid >> 5, b_c = (tid & 31) * 4;

    float acc[4][4][4];
    #pragma unroll
    for (int i = 0; i < 4; i++)
        #pragma unroll
        for (int j = 0; j < 4; j++)
            #pragma unroll
            for (int r = 0; r < 4; r++) acc[i][j][r] = 0.0f;

    int NIT = K / BK;

    auto load_st = [&](int st, int k0) {
        #pragma unroll
        for (int i = 0; i < 2; i++) {
            int r = a_r + i * 64;
            cp16(sA + (unsigned)((st*128 + r)*PA + a_c)*4,
                 A + (size_t)(row0 + r) * K + k0 + a_c);
        }
        #pragma unroll
        for (int i = 0; i < 2; i++) {
            int r = b_r + i * 8;
            cp16(sB + (unsigned)((st*BK + r)*PB + b_c)*4,
                 W + (size_t)(k0 + r) * N + col0 + b_c);
        }
        cp_commit();
    };

    load_st(0, 0);
    if (NIT > 1) load_st(1, BK);

    for (int it = 0; it < NIT; it++) {
        if (it == NIT - 1) cp_wait0(); else cp_wait1();
        __syncthreads();

        if (it + 2 < NIT) load_st((it + 2) % STG, (it + 2) * BK);

        int buf = it % STG;
        const unsigned* Ab = As_ + buf * 128 * PA;
        const unsigned* Bb = Bs_ + buf * BK * PB;

        #pragma unroll
        for (int kk = 0; kk < BK; kk += 8) {
            unsigned af[4][4], bf[4][2];
            #pragma unroll
            for (int mi = 0; mi < 4; mi++) {
                int m = wm * 64 + mi * 16 + gid;
                af[mi][0] = Ab[m * PA + kk + tig];
                af[mi][1] = Ab[(m + 8) * PA + kk + tig];
                af[mi][2] = Ab[m * PA + kk + tig + 4];
                af[mi][3] = Ab[(m + 8) * PA + kk + tig + 4];
            }
            #pragma unroll
            for (int ni = 0; ni < 4; ni++) {
                int n = wn * 32 + ni * 8 + gid;
                bf[ni][0] = Bb[(kk + tig) * PB + n];
                bf[ni][1] = Bb[(kk + tig + 4) * PB + n];
            }
            #pragma unroll
            for (int mi = 0; mi < 4; mi++)
                #pragma unroll
                for (int ni = 0; ni < 4; ni++)
                    mma_tf32(acc[mi][ni][0], acc[mi][ni][1], acc[mi][ni][2], acc[mi][ni][3],
                             af[mi][0], af[mi][1], af[mi][2], af[mi][3],
                             bf[ni][0], bf[ni][1]);
        }
        __syncthreads();
    }

    #pragma unroll
    for (int mi = 0; mi < 4; mi++) {
        int r0 = row0 + wm * 64 + mi * 16 + gid;
        #pragma unroll
        for (int ni = 0; ni < 4; ni++) {
            int c = col0 + wn * 32 + ni * 8 + tig * 2;
            epi_write<GELU, RES>(C, bias, res, N, r0, r0 + 8, c,
                                 acc[mi][ni][0], acc[mi][ni][1],
                                 acc[mi][ni][2], acc[mi][ni][3]);
        }
    }
}

template<bool GELU, bool RES>
__global__ void __launch_bounds__(256)
mm_tc(const float* __restrict__ A, const float* __restrict__ W,
      const float* __restrict__ bias, const float* __restrict__ res,
      float* __restrict__ C, int N, int K) {
    extern __shared__ char smem[];
    mm_body<GELU, RES>(A, W, bias, res, C, N, K,
                       blockIdx.y * 128, blockIdx.x * 128, smem);
}

// ---------------- GEMM core 64x128, BK=16, 3-stage — higher occupancy -------------
template<bool GELU, bool RES>
__device__ __forceinline__ void
mm64_body(const float* __restrict__ A, const float* __restrict__ W,
          const float* __restrict__ bias, const float* __restrict__ res,
          float* __restrict__ C, int N, int K, int row0, int col0, char* smem) {
    unsigned* As_ = (unsigned*)smem;                  // [STG][64][PA]
    unsigned* Bs_ = As_ + STG * 64 * PA;              // [STG][BK][PB]
    unsigned sA = (unsigned)__cvta_generic_to_shared(As_);
    unsigned sB = (unsigned)__cvta_generic_to_shared(Bs_);

    int tid  = threadIdx.x;
    int warp = tid >> 5, lane = tid & 31;
    int gid  = lane >> 2, tig = lane & 3;
    int wm   = warp & 1;          // 0..1 -> 32 rows
    int wn   = warp >> 1;         // 0..3 -> 32 cols

    int a_r = tid >> 2, a_c = (tid & 3) * 4;    // 64 rows x 4 float4 chunks
    int b_r = tid >> 5, b_c = (tid & 31) * 4;

    float acc[2][4][4];
    #pragma unroll
    for (int i = 0; i < 2; i++)
        #pragma unroll
        for (int j = 0; j < 4; j++)
            #pragma unroll
            for (int r = 0; r < 4; r++) acc[i][j][r] = 0.0f;

    int NIT = K / BK;

    auto load_st = [&](int st, int k0) {
        cp16(sA + (unsigned)((st*64 + a_r)*PA + a_c)*4,
             A + (size_t)(row0 + a_r) * K + k0 + a_c);
        #pragma unroll
        for (int i = 0; i < 2; i++) {
            int r = b_r + i * 8;
            cp16(sB + (unsigned)((st*BK + r)*PB + b_c)*4,
                 W + (size_t)(k0 + r) * N + col0 + b_c);
        }
        cp_commit();
    };

    load_st(0, 0);
    if (NIT > 1) load_st(1, BK);

    for (int it = 0; it < NIT; it++) {
        if (it == NIT - 1) cp_wait0(); else cp_wait1();
        __syncthreads();

        if (it + 2 < NIT) load_st((it + 2) % STG, (it + 2) * BK);

        int buf = it % STG;
        const unsigned* Ab = As_ + buf * 64 * PA;
        const unsigned* Bb = Bs_ + buf * BK * PB;

        #pragma unroll
        for (int kk = 0; kk < BK; kk += 8) {
            unsigned af[2][4], bf[4][2];
            #pragma unroll
            for (int mi = 0; mi < 2; mi++) {
                int m = wm * 32 + mi * 16 + gid;
                af[mi][0] = Ab[m * PA + kk + tig];
                af[mi][1] = Ab[(m + 8) * PA + kk + tig];
                af[mi][2] = Ab[m * PA + kk + tig + 4];
                af[mi][3] = Ab[(m + 8) * PA + kk + tig + 4];
            }
            #pragma unroll
            for (int ni = 0; ni < 4; ni++) {
                int n = wn * 32 + ni * 8 + gid;
                bf[ni][0] = Bb[(kk + tig) * PB + n];
                bf[ni][1] = Bb[(kk + tig + 4) * PB + n];
            }
            #pragma unroll
            for (int mi = 0; mi < 2; mi++)
                #pragma unroll
                for (int ni = 0; ni < 4; ni++)
                    mma_tf32(acc[mi][ni][0], acc[mi][ni][1], acc[mi][ni][2], acc[mi][ni][3],
                             af[mi][0], af[mi][1], af[mi][2], af[mi][3],
                             bf[ni][0], bf[ni][1]);
        }
        __syncthreads();
    }

    #pragma unroll
    for (int mi = 0; mi < 2; mi++) {
        int r0 = row0 + wm * 32 + mi * 16 + gid;
        #pragma unroll
        for (int ni = 0; ni < 4; ni++) {
            int c = col0 + wn * 32 + ni * 8 + tig * 2;
            epi_write<GELU, RES>(C, bias, res, N, r0, r0 + 8, c,
                                 acc[mi][ni][0], acc[mi][ni][1],
                                 acc[mi][ni][2], acc[mi][ni][3]);
        }
    }
}

template<bool GELU, bool RES>
__global__ void __launch_bounds__(256, 3)
mm64_tc(const float* __restrict__ A, const float* __restrict__ W,
        const float* __restrict__ bias, const float* __restrict__ res,
        float* __restrict__ C, int N, int K) {
    extern __shared__ char smem[];
    mm64_body<GELU, RES>(A, W, bias, res, C, N, K,
                         blockIdx.y * 64, blockIdx.x * 128, smem);
}

__global__ void __launch_bounds__(256, 3)
qkv_tc(const float* __restrict__ y,
       const float* __restrict__ wq, const float* __restrict__ bq, float* __restrict__ q,
       const float* __restrict__ wk, const float* __restrict__ bk, float* __restrict__ k,
       const float* __restrict__ wv, const float* __restrict__ bv, float* __restrict__ v) {
    extern __shared__ char smem[];
    const float* W; const float* bias; float* C;
    if (blockIdx.z == 0)      { W = wq; bias = bq; C = q; }
    else if (blockIdx.z == 1) { W = wk; bias = bk; C = k; }
    else                      { W = wv; bias = bv; C = v; }
    mm64_body<false, false>(y, W, bias, nullptr, C, EE, EE,
                            blockIdx.y * 64, blockIdx.x * 128, smem);
}

// ---------------- Flash attention: fused scores+softmax+PV, 2 CTAs/SM -------------
__global__ void __launch_bounds__(256, 2)
flash_tc(const float* __restrict__ q, const float* __restrict__ k,
         const float* __restrict__ v, float* __restrict__ ctx) {
    extern __shared__ char smem[];
    float* QP = (float*)smem;                    // [128][PQ]  Q, then per-warp P
    float* Ks = QP + 128 * PQ;                   // [FSTG][FK][PQ]
    float* Vs = Ks + FSTG * FK * PQ;             // [FSTG][FK][PVV]
    unsigned sQ = (unsigned)__cvta_generic_to_shared(QP);
    unsigned sK = (unsigned)__cvta_generic_to_shared(Ks);
    unsigned sV = (unsigned)__cvta_generic_to_shared(Vs);

    int bh = blockIdx.y;
    int b = bh / HH, h = bh % HH;
    int row0 = blockIdx.x * FM;
    const float* qb = q + (size_t)b * SS * EE + h * DD;
    const float* kb = k + (size_t)b * SS * EE + h * DD;
    const float* vb = v + (size_t)b * SS * EE + h * DD;

    int tid  = threadIdx.x;
    int warp = tid >> 5, lane = tid & 31;
    int gid  = lane >> 2, tig = lane & 3;

    int l_r = tid >> 4, l_c = (tid & 15) * 4;

    // group 0: Q tile (128 x 64)
    #pragma unroll
    for (int i = 0; i < 8; i++) {
        int r = l_r + i * 16;
        cp16(sQ + (unsigned)(r * PQ + l_c) * 4, qb + (size_t)(row0 + r) * EE + l_c);
    }
    cp_commit();

    auto load_kv = [&](int st, int k0) {
        #pragma unroll
        for (int i = 0; i < 2; i++) {
            int r = l_r + i * 16;
            cp16(sK + (unsigned)((st*FK + r) * PQ + l_c) * 4,
                 kb + (size_t)(k0 + r) * EE + l_c);
            cp16(sV + (unsigned)((st*FK + r) * PVV + l_c) * 4,
                 vb + (size_t)(k0 + r) * EE + l_c);
        }
        cp_commit();
    };
    load_kv(0, 0);
    load_kv(1, FK);
    load_kv(2, 2 * FK);

    cp_wait3();           // Q ready
    __syncthreads();

    int m0r = warp * 16 + gid;
    const unsigned* QPu = (const unsigned*)QP;
    unsigned qf[8][4];
    #pragma unroll
    for (int kc = 0; kc < 8; kc++) {
        qf[kc][0] = QPu[m0r * PQ + kc*8 + tig];
        qf[kc][1] = QPu[(m0r + 8) * PQ + kc*8 + tig];
        qf[kc][2] = QPu[m0r * PQ + kc*8 + tig + 4];
        qf[kc][3] = QPu[(m0r + 8) * PQ + kc*8 + tig + 4];
    }
    __syncwarp();

    float* Pw = QP + (warp * 16) * PQ;           // warp-private P strip [16][PQ]
    const unsigned* Pwu = (const unsigned*)Pw;

    float o[8][4];
    #pragma unroll
    for (int ni = 0; ni < 8; ni++)
        #pragma unroll
        for (int r = 0; r < 4; r++) o[ni][r] = 0.0f;
    float mx0 = -1e30f, mx1 = -1e30f, l0 = 0.0f, l1 = 0.0f;
    const float scale = rsqrtf((float)EE);

    const int NIT = SS / FK;   // 64
    for (int it = 0; it < NIT; it++) {
        if (it >= NIT - 3) cp_wait0(); else cp_wait2();
        __syncthreads();
        if (it + 3 < NIT) load_kv((it + 3) % FSTG, (it + 3) * FK);

        int buf = it % FSTG;
        const unsigned* Kb = (const unsigned*)(Ks + buf * FK * PQ);
        const unsigned* Vb = (const unsigned*)(Vs + buf * FK * PVV);

        // ---- S = Q K^T (16 x 32 per warp) ----
        float s[4][4];
        #pragma unroll
        for (int ni = 0; ni < 4; ni++)
            #pragma unroll
            for (int r = 0; r < 4; r++) s[ni][r] = 0.0f;

        #pragma unroll
        for (int kc = 0; kc < 8; kc++) {
            #pragma unroll
            for (int ni = 0; ni < 4; ni++) {
                int n = ni * 8 + gid;
                unsigned b0 = Kb[n * PQ + kc*8 + tig];
                unsigned b1 = Kb[n * PQ + kc*8 + tig + 4];
                mma_tf32(s[ni][0], s[ni][1], s[ni][2], s[ni][3],
                         qf[kc][0], qf[kc][1], qf[kc][2], qf[kc][3], b0, b1);
            }
        }

        // ---- online softmax ----
        float rm0 = -1e30f, rm1 = -1e30f;
        #pragma unroll
        for (int ni = 0; ni < 4; ni++) {
            s[ni][0] *= scale; s[ni][1] *= scale;
            s[ni][2] *= scale; s[ni][3] *= scale;
            rm0 = fmaxf(rm0, fmaxf(s[ni][0], s[ni][1]));
            rm1 = fmaxf(rm1, fmaxf(s[ni][2], s[ni][3]));
        }
        rm0 = fmaxf(rm0, __shfl_xor_sync(0xffffffffu, rm0, 1));
        rm0 = fmaxf(rm0, __shfl_xor_sync(0xffffffffu, rm0, 2));
        rm1 = fmaxf(rm1, __shfl_xor_sync(0xffffffffu, rm1, 1));
        rm1 = fmaxf(rm1, __shfl_xor_sync(0xffffffffu, rm1, 2));

        float mn0 = fmaxf(mx0, rm0), mn1 = fmaxf(mx1, rm1);
        float f0 = __expf(mx0 - mn0), f1 = __expf(mx1 - mn1);
        mx0 = mn0; mx1 = mn1;

        float rs0 = 0.0f, rs1 = 0.0f;
        #pragma unroll
        for (int ni = 0; ni < 4; ni++) {
            float p0 = __expf(s[ni][0] - mn0);
            float p1 = __expf(s[ni][1] - mn0);
            float p2 = __expf(s[ni][2] - mn1);
            float p3 = __expf(s[ni][3] - mn1);
            rs0 += p0 + p1; rs1 += p2 + p3;
            *(float2*)(Pw + gid * PQ + ni*8 + tig*2)       = make_float2(p0, p1);
            *(float2*)(Pw + (gid + 8) * PQ + ni*8 + tig*2) = make_float2(p2, p3);
        }
        rs0 += __shfl_xor_sync(0xffffffffu, rs0, 1);
        rs0 += __shfl_xor_sync(0xffffffffu, rs0, 2);
        rs1 += __shfl_xor_sync(0xffffffffu, rs1, 1);
        rs1 += __shfl_xor_sync(0xffffffffu, rs1, 2);
        l0 = l0 * f0 + rs0;
        l1 = l1 * f1 + rs1;

        #pragma unroll
        for (int ni = 0; ni < 8; ni++) {
            o[ni][0] *= f0; o[ni][1] *= f0;
            o[ni][2] *= f1; o[ni][3] *= f1;
        }
        __syncwarp();

        // ---- O += P V (16 x 64 per warp, K=32) ----
        #pragma unroll
        for (int kc = 0; kc < 4; kc++) {
            unsigned a0 = Pwu[gid * PQ + kc*8 + tig];
            unsigned a1 = Pwu[(gid + 8) * PQ + kc*8 + tig];
            unsigned a2 = Pwu[gid * PQ + kc*8 + tig + 4];
            unsigned a3 = Pwu[(gid + 8) * PQ + kc*8 + tig + 4];
            #pragma unroll
            for (int ni = 0; ni < 8; ni++) {
                int n = ni * 8 + gid;
                unsigned b0 = Vb[(kc*8 + tig) * PVV + n];
                unsigned b1 = Vb[(kc*8 + tig + 4) * PVV + n];
                mma_tf32(o[ni][0], o[ni][1], o[ni][2], o[ni][3],
                         a0, a1, a2, a3, b0, b1);
            }
        }
        __syncwarp();
    }

    // ---- normalize + write ----
    float i0 = 1.0f / l0, i1 = 1.0f / l1;
    float* c0row = ctx + (size_t)(b * SS + row0 + m0r) * EE + h * DD;
    float* c1row = ctx + (size_t)(b * SS + row0 + m0r + 8) * EE + h * DD;
    #pragma unroll
    for (int ni = 0; ni < 8; ni++) {
        int c = ni * 8 + tig * 2;
        *(float2*)(c0row + c) = make_float2(o[ni][0] * i0, o[ni][1] * i0);
        *(float2*)(c1row + c) = make_float2(o[ni][2] * i1, o[ni][3] * i1);
    }
}

// ---------------- launch ---------------------------------------------------------
extern "C" void kernel_launch(void* const* d_in, const int* in_sizes, int n_in,
                              void* d_out, int out_size) {
    (void)in_sizes; (void)n_in; (void)out_size;
    const float* x     = (const float*)d_in[0];
    const float* ln1_g = (const float*)d_in[1];
    const float* ln1_b = (const float*)d_in[2];
    const float* wq    = (const float*)d_in[3];
    const float* bq    = (const float*)d_in[4];
    const float* wk    = (const float*)d_in[5];
    const float* bk    = (const float*)d_in[6];
    const float* wv    = (const float*)d_in[7];
    const float* bv    = (const float*)d_in[8];
    const float* wo    = (const float*)d_in[9];
    const float* bo    = (const float*)d_in[10];
    const float* w1    = (const float*)d_in[11];
    const float* b1    = (const float*)d_in[12];
    const float* w2    = (const float*)d_in[13];
    const float* b2    = (const float*)d_in[14];
    const float* ln2_g = (const float*)d_in[15];
    const float* ln2_b = (const float*)d_in[16];
    float* out = (float*)d_out;

    float *y, *q, *k, *v, *ctx, *y2, *z, *hbuf;
    cudaGetSymbolAddress((void**)&y,    g_y);
    cudaGetSymbolAddress((void**)&q,    g_q);
    cudaGetSymbolAddress((void**)&k,    g_k);
    cudaGetSymbolAddress((void**)&v,    g_v);
    cudaGetSymbolAddress((void**)&ctx,  g_ctx);
    cudaGetSymbolAddress((void**)&y2,   g_y2);
    cudaGetSymbolAddress((void**)&z,    g_z);
    cudaGetSymbolAddress((void**)&hbuf, g_h);

    static bool attr_done = false;
    if (!attr_done) {
        cudaFuncSetAttribute(mm_tc<true,false>,    cudaFuncAttributeMaxDynamicSharedMemorySize, SM_MM);
        cudaFuncSetAttribute(mm64_tc<false,true>,  cudaFuncAttributeMaxDynamicSharedMemorySize, SM_MM64);
        cudaFuncSetAttribute(qkv_tc,   cudaFuncAttributeMaxDynamicSharedMemorySize, SM_MM64);
        cudaFuncSetAttribute(flash_tc, cudaFuncAttributeMaxDynamicSharedMemorySize, SM_FLASH);
        attr_done = true;
    }

    dim3 blk(256);

    // 1. y = LN1(x)
    ln_kernel<<<MM, blk>>>(x, ln1_g, ln1_b, y);

    // 2. fused q,k,v projections (64-row tiles: 6 x 64 x 3 = 1152 blocks)
    dim3 g_qkv(EE / 128, MM / 64, 3);
    qkv_tc<<<g_qkv, blk, SM_MM64>>>(y, wq, bq, q, wk, bk, k, wv, bv, v);

    // 3. flash attention
    dim3 g_fl(SS / FM, BH);
    flash_tc<<<g_fl, blk, SM_FLASH>>>(q, k, v, ctx);

    // 4. y2 = x + ctx @ wo + bo   (64-row tiles: 384 blocks)
    dim3 g_e64(EE / 128, MM / 64);
    mm64_tc<false, true><<<g_e64, blk, SM_MM64>>>(ctx, wo, bo, x, y2, EE, EE);

    // 5. z = LN2(y2)
    ln_kernel<<<MM, blk>>>(y2, ln2_g, ln2_b, z);

    // 6. h = gelu(z @ w1 + b1)    (128 tiles: 768 blocks, already 2/SM)
    dim3 g_ff(FF / 128, MM / 128);
    mm_tc<true, false><<<g_ff, blk, SM_MM>>>(z, w1, b1, nullptr, hbuf, FF, EE);

    // 7. out = y2 + h @ w2 + b2   (64-row tiles: 384 blocks)
    mm64_tc<false, true><<<g_e64, blk, SM_MM64>>>(hbuf, w2, b2, y2, out, EE, FF);
}

// round 8
// speedup vs baseline: 35.4511x; 1.0448x over previous
#include <cuda_runtime.h>
#include <math.h>

#define BB 2
#define SS 2048
#define EE 768
#define HH 12
#define DD 64
#define MM (BB*SS)      /* 4096 rows */
#define FF (4*EE)       /* 3072 */
#define BH (BB*HH)      /* 24 */

#define BK 16
#define STG 3
#define PA 20           /* [row][k] pad */
#define PB 136          /* [k][n] pad */

/* flash attention tiles */
#define FM 128
#define FK 32
#define PQ 68
#define PVV 72
#define FSTG 4

// dynamic smem sizes (bytes)
#define SM_MM4   (STG*(128*PA + BK*PB)*4)                  /* 56832 */
#define SM_FLASH ((128*PQ + FSTG*FK*PQ + FSTG*FK*PVV)*4)   /* 106496 */

// ---------------- scratch (device globals; no allocation allowed) ----------------
__device__ float g_y  [MM*EE];
__device__ float g_q  [MM*EE];
__device__ float g_k  [MM*EE];
__device__ float g_v  [MM*EE];
__device__ float g_ctx[MM*EE];
__device__ float g_y2 [MM*EE];
__device__ float g_z  [MM*EE];
__device__ float g_h  [MM*FF];

// ---------------- helpers ---------------------------------------------------------
__device__ __forceinline__ void mma_tf32(float& c0, float& c1, float& c2, float& c3,
                                         unsigned a0, unsigned a1, unsigned a2, unsigned a3,
                                         unsigned b0, unsigned b1) {
    asm volatile(
        "mma.sync.aligned.m16n8k8.row.col.f32.tf32.tf32.f32 "
        "{%0,%1,%2,%3}, {%4,%5,%6,%7}, {%8,%9}, {%0,%1,%2,%3};"
        : "+f"(c0), "+f"(c1), "+f"(c2), "+f"(c3)
        : "r"(a0), "r"(a1), "r"(a2), "r"(a3), "r"(b0), "r"(b1));
}

__device__ __forceinline__ void cp16(unsigned saddr, const void* g) {
    asm volatile("cp.async.cg.shared.global [%0], [%1], 16;" :: "r"(saddr), "l"(g));
}
__device__ __forceinline__ void cp_commit() { asm volatile("cp.async.commit_group;"); }
__device__ __forceinline__ void cp_wait0()  { asm volatile("cp.async.wait_group 0;"); }
__device__ __forceinline__ void cp_wait1()  { asm volatile("cp.async.wait_group 1;"); }
__device__ __forceinline__ void cp_wait2()  { asm volatile("cp.async.wait_group 2;"); }
__device__ __forceinline__ void cp_wait3()  { asm volatile("cp.async.wait_group 3;"); }

// ---------------- LayerNorm -------------------------------------------------------
__global__ void ln_kernel(const float* __restrict__ x, const float* __restrict__ gw,
                          const float* __restrict__ bw, float* __restrict__ out) {
    int row = blockIdx.x;
    int t = threadIdx.x;
    const float* xr = x + (size_t)row * EE;
    float v0 = xr[t], v1 = xr[t + 256], v2 = xr[t + 512];
    __shared__ float red[256];
    red[t] = v0 + v1 + v2;
    __syncthreads();
    #pragma unroll
    for (int o = 128; o > 0; o >>= 1) {
        if (t < o) red[t] += red[t + o];
        __syncthreads();
    }
    float mean = red[0] * (1.0f / EE);
    __syncthreads();
    float d0 = v0 - mean, d1 = v1 - mean, d2 = v2 - mean;
    red[t] = d0*d0 + d1*d1 + d2*d2;
    __syncthreads();
    #pragma unroll
    for (int o = 128; o > 0; o >>= 1) {
        if (t < o) red[t] += red[t + o];
        __syncthreads();
    }
    float rstd = rsqrtf(red[0] * (1.0f / EE) + 1e-5f);
    float* orow = out + (size_t)row * EE;
    orow[t]       = d0 * rstd * gw[t]       + bw[t];
    orow[t + 256] = d1 * rstd * gw[t + 256] + bw[t + 256];
    orow[t + 512] = d2 * rstd * gw[t + 512] + bw[t + 512];
}

// ---------------- GEMM epilogue helper --------------------------------------------
template<bool GELU, bool RES>
__device__ __forceinline__ void epi_write(float* C, const float* bias, const float* res,
                                          int N, int r0, int r1, int c,
                                          float v00, float v01, float v10, float v11) {
    float2 b2 = *(const float2*)(bias + c);
    v00 += b2.x; v01 += b2.y; v10 += b2.x; v11 += b2.y;
    if (RES) {
        float2 e0 = *(const float2*)(res + (size_t)r0 * N + c);
        float2 e1 = *(const float2*)(res + (size_t)r1 * N + c);
        v00 += e0.x; v01 += e0.y; v10 += e1.x; v11 += e1.y;
    }
    if (GELU) {
        v00 = v00 * 0.5f * (1.0f + erff(v00 * 0.70710678118654752f));
        v01 = v01 * 0.5f * (1.0f + erff(v01 * 0.70710678118654752f));
        v10 = v10 * 0.5f * (1.0f + erff(v10 * 0.70710678118654752f));
        v11 = v11 * 0.5f * (1.0f + erff(v11 * 0.70710678118654752f));
    }
    *(float2*)(C + (size_t)r0 * N + c) = make_float2(v00, v01);
    *(float2*)(C + (size_t)r1 * N + c) = make_float2(v10, v11);
}

// ---------------- GEMM core 128x128, 4 warps (2x2), warp tile 64x64 ---------------
// Per k8-slice per warp: 16 A-LDS + 16 B-LDS + 32 MMAs (1:1 LDS:MMA).
template<bool GELU, bool RES>
__device__ __forceinline__ void
mm4_body(const float* __restrict__ A, const float* __restrict__ W,
         const float* __restrict__ bias, const float* __restrict__ res,
         float* __restrict__ C, int N, int K, int row0, int col0, char* smem) {
    unsigned* As_ = (unsigned*)smem;                  // [STG][128][PA]
    unsigned* Bs_ = As_ + STG * 128 * PA;             // [STG][BK][PB]
    unsigned sA = (unsigned)__cvta_generic_to_shared(As_);
    unsigned sB = (unsigned)__cvta_generic_to_shared(Bs_);

    int tid  = threadIdx.x;                 // 128 threads
    int warp = tid >> 5, lane = tid & 31;
    int gid  = lane >> 2, tig = lane & 3;
    int wm   = warp & 1;                    // 0..1 -> 64 rows
    int wn   = warp >> 1;                   // 0..1 -> 64 cols

    float acc[4][8][4];
    #pragma unroll
    for (int i = 0; i < 4; i++)
        #pragma unroll
        for (int j = 0; j < 8; j++)
            #pragma unroll
            for (int r = 0; r < 4; r++) acc[i][j][r] = 0.0f;

    int NIT = K / BK;

    auto load_st = [&](int st, int k0) {
        // A tile 128x16: 512 float4 slots, 4 per thread
        #pragma unroll
        for (int i = 0; i < 4; i++) {
            int slot = tid + i * 128;
            int r = slot >> 2, c4 = (slot & 3) * 4;
            cp16(sA + (unsigned)((st*128 + r)*PA + c4)*4,
                 A + (size_t)(row0 + r) * K + k0 + c4);
        }
        // B tile 16x128: 512 float4 slots, 4 per thread
        #pragma unroll
        for (int i = 0; i < 4; i++) {
            int slot = tid + i * 128;
            int r = slot >> 5, c4 = (slot & 31) * 4;
            cp16(sB + (unsigned)((st*BK + r)*PB + c4)*4,
                 W + (size_t)(k0 + r) * N + col0 + c4);
        }
        cp_commit();
    };

    load_st(0, 0);
    if (NIT > 1) load_st(1, BK);

    for (int it = 0; it < NIT; it++) {
        if (it == NIT - 1) cp_wait0(); else cp_wait1();
        __syncthreads();

        if (it + 2 < NIT) load_st((it + 2) % STG, (it + 2) * BK);

        int buf = it % STG;
        const unsigned* Ab = As_ + buf * 128 * PA;
        const unsigned* Bb = Bs_ + buf * BK * PB;

        #pragma unroll
        for (int kk = 0; kk < BK; kk += 8) {
            unsigned af[4][4], bf[8][2];
            #pragma unroll
            for (int mi = 0; mi < 4; mi++) {
                int m = wm * 64 + mi * 16 + gid;
                af[mi][0] = Ab[m * PA + kk + tig];
                af[mi][1] = Ab[(m + 8) * PA + kk + tig];
                af[mi][2] = Ab[m * PA + kk + tig + 4];
                af[mi][3] = Ab[(m + 8) * PA + kk + tig + 4];
            }
            #pragma unroll
            for (int ni = 0; ni < 8; ni++) {
                int n = wn * 64 + ni * 8 + gid;
                bf[ni][0] = Bb[(kk + tig) * PB + n];
                bf[ni][1] = Bb[(kk + tig + 4) * PB + n];
            }
            #pragma unroll
            for (int mi = 0; mi < 4; mi++)
                #pragma unroll
                for (int ni = 0; ni < 8; ni++)
                    mma_tf32(acc[mi][ni][0], acc[mi][ni][1], acc[mi][ni][2], acc[mi][ni][3],
                             af[mi][0], af[mi][1], af[mi][2], af[mi][3],
                             bf[ni][0], bf[ni][1]);
        }
        __syncthreads();
    }

    #pragma unroll
    for (int mi = 0; mi < 4; mi++) {
        int r0 = row0 + wm * 64 + mi * 16 + gid;
        #pragma unroll
        for (int ni = 0; ni < 8; ni++) {
            int c = col0 + wn * 64 + ni * 8 + tig * 2;
            epi_write<GELU, RES>(C, bias, res, N, r0, r0 + 8, c,
                                 acc[mi][ni][0], acc[mi][ni][1],
                                 acc[mi][ni][2], acc[mi][ni][3]);
        }
    }
}

template<bool GELU, bool RES>
__global__ void __launch_bounds__(128, 2)
mm4_tc(const float* __restrict__ A, const float* __restrict__ W,
       const float* __restrict__ bias, const float* __restrict__ res,
       float* __restrict__ C, int N, int K) {
    extern __shared__ char smem[];
    mm4_body<GELU, RES>(A, W, bias, res, C, N, K,
                        blockIdx.y * 128, blockIdx.x * 128, smem);
}

__global__ void __launch_bounds__(128, 2)
qkv4_tc(const float* __restrict__ y,
        const float* __restrict__ wq, const float* __restrict__ bq, float* __restrict__ q,
        const float* __restrict__ wk, const float* __restrict__ bk, float* __restrict__ k,
        const float* __restrict__ wv, const float* __restrict__ bv, float* __restrict__ v) {
    extern __shared__ char smem[];
    const float* W; const float* bias; float* C;
    if (blockIdx.z == 0)      { W = wq; bias = bq; C = q; }
    else if (blockIdx.z == 1) { W = wk; bias = bk; C = k; }
    else                      { W = wv; bias = bv; C = v; }
    mm4_body<false, false>(y, W, bias, nullptr, C, EE, EE,
                           blockIdx.y * 128, blockIdx.x * 128, smem);
}

// ---------------- Flash attention: fused scores+softmax+PV, 2 CTAs/SM -------------
__global__ void __launch_bounds__(256, 2)
flash_tc(const float* __restrict__ q, const float* __restrict__ k,
         const float* __restrict__ v, float* __restrict__ ctx) {
    extern __shared__ char smem[];
    float* QP = (float*)smem;                    // [128][PQ]
    float* Ks = QP + 128 * PQ;                   // [FSTG][FK][PQ]
    float* Vs = Ks + FSTG * FK * PQ;             // [FSTG][FK][PVV]
    unsigned sQ = (unsigned)__cvta_generic_to_shared(QP);
    unsigned sK = (unsigned)__cvta_generic_to_shared(Ks);
    unsigned sV = (unsigned)__cvta_generic_to_shared(Vs);

    int bh = blockIdx.y;
    int b = bh / HH, h = bh % HH;
    int row0 = blockIdx.x * FM;
    const float* qb = q + (size_t)b * SS * EE + h * DD;
    const float* kb = k + (size_t)b * SS * EE + h * DD;
    const float* vb = v + (size_t)b * SS * EE + h * DD;

    int tid  = threadIdx.x;
    int warp = tid >> 5, lane = tid & 31;
    int gid  = lane >> 2, tig = lane & 3;

    int l_r = tid >> 4, l_c = (tid & 15) * 4;

    #pragma unroll
    for (int i = 0; i < 8; i++) {
        int r = l_r + i * 16;
        cp16(sQ + (unsigned)(r * PQ + l_c) * 4, qb + (size_t)(row0 + r) * EE + l_c);
    }
    cp_commit();

    auto load_kv = [&](int st, int k0) {
        #pragma unroll
        for (int i = 0; i < 2; i++) {
            int r = l_r + i * 16;
            cp16(sK + (unsigned)((st*FK + r) * PQ + l_c) * 4,
                 kb + (size_t)(k0 + r) * EE + l_c);
            cp16(sV + (unsigned)((st*FK + r) * PVV + l_c) * 4,
                 vb + (size_t)(k0 + r) * EE + l_c);
        }
        cp_commit();
    };
    load_kv(0, 0);
    load_kv(1, FK);
    load_kv(2, 2 * FK);

    cp_wait3();
    __syncthreads();

    int m0r = warp * 16 + gid;
    const unsigned* QPu = (const unsigned*)QP;
    unsigned qf[8][4];
    #pragma unroll
    for (int kc = 0; kc < 8; kc++) {
        qf[kc][0] = QPu[m0r * PQ + kc*8 + tig];
        qf[kc][1] = QPu[(m0r + 8) * PQ + kc*8 + tig];
        qf[kc][2] = QPu[m0r * PQ + kc*8 + tig + 4];
        qf[kc][3] = QPu[(m0r + 8) * PQ + kc*8 + tig + 4];
    }
    __syncwarp();

    float* Pw = QP + (warp * 16) * PQ;
    const unsigned* Pwu = (const unsigned*)Pw;

    float o[8][4];
    #pragma unroll
    for (int ni = 0; ni < 8; ni++)
        #pragma unroll
        for (int r = 0; r < 4; r++) o[ni][r] = 0.0f;
    float mx0 = -1e30f, mx1 = -1e30f, l0 = 0.0f, l1 = 0.0f;
    const float scale = rsqrtf((float)EE);

    const int NIT = SS / FK;   // 64
    for (int it = 0; it < NIT; it++) {
        if (it >= NIT - 3) cp_wait0(); else cp_wait2();
        __syncthreads();
        if (it + 3 < NIT) load_kv((it + 3) % FSTG, (it + 3) * FK);

        int buf = it % FSTG;
        const unsigned* Kb = (const unsigned*)(Ks + buf * FK * PQ);
        const unsigned* Vb = (const unsigned*)(Vs + buf * FK * PVV);

        float s[4][4];
        #pragma unroll
        for (int ni = 0; ni < 4; ni++)
            #pragma unroll
            for (int r = 0; r < 4; r++) s[ni][r] = 0.0f;

        #pragma unroll
        for (int kc = 0; kc < 8; kc++) {
            #pragma unroll
            for (int ni = 0; ni < 4; ni++) {
                int n = ni * 8 + gid;
                unsigned b0 = Kb[n * PQ + kc*8 + tig];
                unsigned b1 = Kb[n * PQ + kc*8 + tig + 4];
                mma_tf32(s[ni][0], s[ni][1], s[ni][2], s[ni][3],
                         qf[kc][0], qf[kc][1], qf[kc][2], qf[kc][3], b0, b1);
            }
        }

        float rm0 = -1e30f, rm1 = -1e30f;
        #pragma unroll
        for (int ni = 0; ni < 4; ni++) {
            s[ni][0] *= scale; s[ni][1] *= scale;
            s[ni][2] *= scale; s[ni][3] *= scale;
            rm0 = fmaxf(rm0, fmaxf(s[ni][0], s[ni][1]));
            rm1 = fmaxf(rm1, fmaxf(s[ni][2], s[ni][3]));
        }
        rm0 = fmaxf(rm0, __shfl_xor_sync(0xffffffffu, rm0, 1));
        rm0 = fmaxf(rm0, __shfl_xor_sync(0xffffffffu, rm0, 2));
        rm1 = fmaxf(rm1, __shfl_xor_sync(0xffffffffu, rm1, 1));
        rm1 = fmaxf(rm1, __shfl_xor_sync(0xffffffffu, rm1, 2));

        float mn0 = fmaxf(mx0, rm0), mn1 = fmaxf(mx1, rm1);
        float f0 = __expf(mx0 - mn0), f1 = __expf(mx1 - mn1);
        mx0 = mn0; mx1 = mn1;

        float rs0 = 0.0f, rs1 = 0.0f;
        #pragma unroll
        for (int ni = 0; ni < 4; ni++) {
            float p0 = __expf(s[ni][0] - mn0);
            float p1 = __expf(s[ni][1] - mn0);
            float p2 = __expf(s[ni][2] - mn1);
            float p3 = __expf(s[ni][3] - mn1);
            rs0 += p0 + p1; rs1 += p2 + p3;
            *(float2*)(Pw + gid * PQ + ni*8 + tig*2)       = make_float2(p0, p1);
            *(float2*)(Pw + (gid + 8) * PQ + ni*8 + tig*2) = make_float2(p2, p3);
        }
        rs0 += __shfl_xor_sync(0xffffffffu, rs0, 1);
        rs0 += __shfl_xor_sync(0xffffffffu, rs0, 2);
        rs1 += __shfl_xor_sync(0xffffffffu, rs1, 1);
        rs1 += __shfl_xor_sync(0xffffffffu, rs1, 2);
        l0 = l0 * f0 + rs0;
        l1 = l1 * f1 + rs1;

        #pragma unroll
        for (int ni = 0; ni < 8; ni++) {
            o[ni][0] *= f0; o[ni][1] *= f0;
            o[ni][2] *= f1; o[ni][3] *= f1;
        }
        __syncwarp();

        #pragma unroll
        for (int kc = 0; kc < 4; kc++) {
            unsigned a0 = Pwu[gid * PQ + kc*8 + tig];
            unsigned a1 = Pwu[(gid + 8) * PQ + kc*8 + tig];
            unsigned a2 = Pwu[gid * PQ + kc*8 + tig + 4];
            unsigned a3 = Pwu[(gid + 8) * PQ + kc*8 + tig + 4];
            #pragma unroll
            for (int ni = 0; ni < 8; ni++) {
                int n = ni * 8 + gid;
                unsigned b0 = Vb[(kc*8 + tig) * PVV + n];
                unsigned b1 = Vb[(kc*8 + tig + 4) * PVV + n];
                mma_tf32(o[ni][0], o[ni][1], o[ni][2], o[ni][3],
                         a0, a1, a2, a3, b0, b1);
            }
        }
        __syncwarp();
    }

    float i0 = 1.0f / l0, i1 = 1.0f / l1;
    float* c0row = ctx + (size_t)(b * SS + row0 + m0r) * EE + h * DD;
    float* c1row = ctx + (size_t)(b * SS + row0 + m0r + 8) * EE + h * DD;
    #pragma unroll
    for (int ni = 0; ni < 8; ni++) {
        int c = ni * 8 + tig * 2;
        *(float2*)(c0row + c) = make_float2(o[ni][0] * i0, o[ni][1] * i0);
        *(float2*)(c1row + c) = make_float2(o[ni][2] * i1, o[ni][3] * i1);
    }
}

// ---------------- launch ---------------------------------------------------------
extern "C" void kernel_launch(void* const* d_in, const int* in_sizes, int n_in,
                              void* d_out, int out_size) {
    (void)in_sizes; (void)n_in; (void)out_size;
    const float* x     = (const float*)d_in[0];
    const float* ln1_g = (const float*)d_in[1];
    const float* ln1_b = (const float*)d_in[2];
    const float* wq    = (const float*)d_in[3];
    const float* bq    = (const float*)d_in[4];
    const float* wk    = (const float*)d_in[5];
    const float* bk    = (const float*)d_in[6];
    const float* wv    = (const float*)d_in[7];
    const float* bv    = (const float*)d_in[8];
    const float* wo    = (const float*)d_in[9];
    const float* bo    = (const float*)d_in[10];
    const float* w1    = (const float*)d_in[11];
    const float* b1    = (const float*)d_in[12];
    const float* w2    = (const float*)d_in[13];
    const float* b2    = (const float*)d_in[14];
    const float* ln2_g = (const float*)d_in[15];
    const float* ln2_b = (const float*)d_in[16];
    float* out = (float*)d_out;

    float *y, *q, *k, *v, *ctx, *y2, *z, *hbuf;
    cudaGetSymbolAddress((void**)&y,    g_y);
    cudaGetSymbolAddress((void**)&q,    g_q);
    cudaGetSymbolAddress((void**)&k,    g_k);
    cudaGetSymbolAddress((void**)&v,    g_v);
    cudaGetSymbolAddress((void**)&ctx,  g_ctx);
    cudaGetSymbolAddress((void**)&y2,   g_y2);
    cudaGetSymbolAddress((void**)&z,    g_z);
    cudaGetSymbolAddress((void**)&hbuf, g_h);

    static bool attr_done = false;
    if (!attr_done) {
        cudaFuncSetAttribute(mm4_tc<false,true>, cudaFuncAttributeMaxDynamicSharedMemorySize, SM_MM4);
        cudaFuncSetAttribute(mm4_tc<true,false>, cudaFuncAttributeMaxDynamicSharedMemorySize, SM_MM4);
        cudaFuncSetAttribute(qkv4_tc,  cudaFuncAttributeMaxDynamicSharedMemorySize, SM_MM4);
        cudaFuncSetAttribute(flash_tc, cudaFuncAttributeMaxDynamicSharedMemorySize, SM_FLASH);
        attr_done = true;
    }

    dim3 blk128(128);
    dim3 blk256(256);

    // 1. y = LN1(x)
    ln_kernel<<<MM, blk256>>>(x, ln1_g, ln1_b, y);

    // 2. fused q,k,v projections (128x128 tiles: 6 x 32 x 3 = 576 blocks)
    dim3 g_qkv(EE / 128, MM / 128, 3);
    qkv4_tc<<<g_qkv, blk128, SM_MM4>>>(y, wq, bq, q, wk, bk, k, wv, bv, v);

    // 3. flash attention
    dim3 g_fl(SS / FM, BH);
    flash_tc<<<g_fl, blk256, SM_FLASH>>>(q, k, v, ctx);

    // 4. y2 = x + ctx @ wo + bo
    dim3 g_e(EE / 128, MM / 128);
    mm4_tc<false, true><<<g_e, blk128, SM_MM4>>>(ctx, wo, bo, x, y2, EE, EE);

    // 5. z = LN2(y2)
    ln_kernel<<<MM, blk256>>>(y2, ln2_g, ln2_b, z);

    // 6. h = gelu(z @ w1 + b1)
    dim3 g_ff(FF / 128, MM / 128);
    mm4_tc<true, false><<<g_ff, blk128, SM_MM4>>>(z, w1, b1, nullptr, hbuf, FF, EE);

    // 7. out = y2 + h @ w2 + b2
    mm4_tc<false, true><<<g_e, blk128, SM_MM4>>>(hbuf, w2, b2, y2, out, EE, FF);
}

// round 9
// speedup vs baseline: 36.5129x; 1.0300x over previous
#include <cuda_runtime.h>
#include <math.h>

#define BB 2
#define SS 2048
#define EE 768
#define HH 12
#define DD 64
#define MM (BB*SS)      /* 4096 rows */
#define FF (4*EE)       /* 3072 */
#define BH (BB*HH)      /* 24 */

#define BK 16
#define STG 3
#define PA 20           /* [row][k] pad */
#define PB 136          /* [k][n] pad */

/* flash attention tiles */
#define FM 128
#define FK 32
#define PQ 68
#define PVV 72
#define FSTG 4

// dynamic smem sizes (bytes)
#define SM_MM2   (STG*(64*PA + BK*PB)*4)                   /* 41472 */
#define SM_FLASH ((128*PQ + FSTG*FK*PQ + FSTG*FK*PVV)*4)   /* 106496 */

// ---------------- scratch (device globals; no allocation allowed) ----------------
__device__ float g_y  [MM*EE];
__device__ float g_q  [MM*EE];
__device__ float g_k  [MM*EE];
__device__ float g_v  [MM*EE];
__device__ float g_ctx[MM*EE];
__device__ float g_y2 [MM*EE];
__device__ float g_z  [MM*EE];
__device__ float g_h  [MM*FF];

// ---------------- helpers ---------------------------------------------------------
__device__ __forceinline__ void mma_tf32(float& c0, float& c1, float& c2, float& c3,
                                         unsigned a0, unsigned a1, unsigned a2, unsigned a3,
                                         unsigned b0, unsigned b1) {
    asm volatile(
        "mma.sync.aligned.m16n8k8.row.col.f32.tf32.tf32.f32 "
        "{%0,%1,%2,%3}, {%4,%5,%6,%7}, {%8,%9}, {%0,%1,%2,%3};"
        : "+f"(c0), "+f"(c1), "+f"(c2), "+f"(c3)
        : "r"(a0), "r"(a1), "r"(a2), "r"(a3), "r"(b0), "r"(b1));
}

__device__ __forceinline__ void cp16(unsigned saddr, const void* g) {
    asm volatile("cp.async.cg.shared.global [%0], [%1], 16;" :: "r"(saddr), "l"(g));
}
__device__ __forceinline__ void cp_commit() { asm volatile("cp.async.commit_group;"); }
__device__ __forceinline__ void cp_wait0()  { asm volatile("cp.async.wait_group 0;"); }
__device__ __forceinline__ void cp_wait1()  { asm volatile("cp.async.wait_group 1;"); }
__device__ __forceinline__ void cp_wait2()  { asm volatile("cp.async.wait_group 2;"); }
__device__ __forceinline__ void cp_wait3()  { asm volatile("cp.async.wait_group 3;"); }

// ---------------- LayerNorm -------------------------------------------------------
__global__ void ln_kernel(const float* __restrict__ x, const float* __restrict__ gw,
                          const float* __restrict__ bw, float* __restrict__ out) {
    int row = blockIdx.x;
    int t = threadIdx.x;
    const float* xr = x + (size_t)row * EE;
    float v0 = xr[t], v1 = xr[t + 256], v2 = xr[t + 512];
    __shared__ float red[256];
    red[t] = v0 + v1 + v2;
    __syncthreads();
    #pragma unroll
    for (int o = 128; o > 0; o >>= 1) {
        if (t < o) red[t] += red[t + o];
        __syncthreads();
    }
    float mean = red[0] * (1.0f / EE);
    __syncthreads();
    float d0 = v0 - mean, d1 = v1 - mean, d2 = v2 - mean;
    red[t] = d0*d0 + d1*d1 + d2*d2;
    __syncthreads();
    #pragma unroll
    for (int o = 128; o > 0; o >>= 1) {
        if (t < o) red[t] += red[t + o];
        __syncthreads();
    }
    float rstd = rsqrtf(red[0] * (1.0f / EE) + 1e-5f);
    float* orow = out + (size_t)row * EE;
    orow[t]       = d0 * rstd * gw[t]       + bw[t];
    orow[t + 256] = d1 * rstd * gw[t + 256] + bw[t + 256];
    orow[t + 512] = d2 * rstd * gw[t + 512] + bw[t + 512];
}

// ---------------- GEMM epilogue helper --------------------------------------------
template<bool GELU, bool RES>
__device__ __forceinline__ void epi_write(float* C, const float* bias, const float* res,
                                          int N, int r0, int r1, int c,
                                          float v00, float v01, float v10, float v11) {
    float2 b2 = *(const float2*)(bias + c);
    v00 += b2.x; v01 += b2.y; v10 += b2.x; v11 += b2.y;
    if (RES) {
        float2 e0 = *(const float2*)(res + (size_t)r0 * N + c);
        float2 e1 = *(const float2*)(res + (size_t)r1 * N + c);
        v00 += e0.x; v01 += e0.y; v10 += e1.x; v11 += e1.y;
    }
    if (GELU) {
        v00 = v00 * 0.5f * (1.0f + erff(v00 * 0.70710678118654752f));
        v01 = v01 * 0.5f * (1.0f + erff(v01 * 0.70710678118654752f));
        v10 = v10 * 0.5f * (1.0f + erff(v10 * 0.70710678118654752f));
        v11 = v11 * 0.5f * (1.0f + erff(v11 * 0.70710678118654752f));
    }
    *(float2*)(C + (size_t)r0 * N + c) = make_float2(v00, v01);
    *(float2*)(C + (size_t)r1 * N + c) = make_float2(v10, v11);
}

// ---------------- GEMM core 64x128 CTA, 4 warps (2x2), warp tile 32x64 ------------
// Per k8 per warp: 8 A-LDS + 16 B-LDS + 16 MMAs (1.5:1). acc = 64 regs.
template<bool GELU, bool RES>
__device__ __forceinline__ void
mm2_body(const float* __restrict__ A, const float* __restrict__ W,
         const float* __restrict__ bias, const float* __restrict__ res,
         float* __restrict__ C, int N, int K, int row0, int col0, char* smem) {
    unsigned* As_ = (unsigned*)smem;                  // [STG][64][PA]
    unsigned* Bs_ = As_ + STG * 64 * PA;              // [STG][BK][PB]
    unsigned sA = (unsigned)__cvta_generic_to_shared(As_);
    unsigned sB = (unsigned)__cvta_generic_to_shared(Bs_);

    int tid  = threadIdx.x;                 // 128 threads
    int warp = tid >> 5, lane = tid & 31;
    int gid  = lane >> 2, tig = lane & 3;
    int wm   = warp & 1;                    // 0..1 -> 32 rows
    int wn   = warp >> 1;                   // 0..1 -> 64 cols

    float acc[2][8][4];
    #pragma unroll
    for (int i = 0; i < 2; i++)
        #pragma unroll
        for (int j = 0; j < 8; j++)
            #pragma unroll
            for (int r = 0; r < 4; r++) acc[i][j][r] = 0.0f;

    int NIT = K / BK;

    auto load_st = [&](int st, int k0) {
        // A tile 64x16: 256 float4 slots, 2 per thread
        #pragma unroll
        for (int i = 0; i < 2; i++) {
            int slot = tid + i * 128;
            int r = slot >> 2, c4 = (slot & 3) * 4;
            cp16(sA + (unsigned)((st*64 + r)*PA + c4)*4,
                 A + (size_t)(row0 + r) * K + k0 + c4);
        }
        // B tile 16x128: 512 float4 slots, 4 per thread
        #pragma unroll
        for (int i = 0; i < 4; i++) {
            int slot = tid + i * 128;
            int r = slot >> 5, c4 = (slot & 31) * 4;
            cp16(sB + (unsigned)((st*BK + r)*PB + c4)*4,
                 W + (size_t)(k0 + r) * N + col0 + c4);
        }
        cp_commit();
    };

    load_st(0, 0);
    if (NIT > 1) load_st(1, BK);

    for (int it = 0; it < NIT; it++) {
        if (it == NIT - 1) cp_wait0(); else cp_wait1();
        __syncthreads();

        if (it + 2 < NIT) load_st((it + 2) % STG, (it + 2) * BK);

        int buf = it % STG;
        const unsigned* Ab = As_ + buf * 64 * PA;
        const unsigned* Bb = Bs_ + buf * BK * PB;

        #pragma unroll
        for (int kk = 0; kk < BK; kk += 8) {
            unsigned af[2][4], bf[8][2];
            #pragma unroll
            for (int mi = 0; mi < 2; mi++) {
                int m = wm * 32 + mi * 16 + gid;
                af[mi][0] = Ab[m * PA + kk + tig];
                af[mi][1] = Ab[(m + 8) * PA + kk + tig];
                af[mi][2] = Ab[m * PA + kk + tig + 4];
                af[mi][3] = Ab[(m + 8) * PA + kk + tig + 4];
            }
            #pragma unroll
            for (int ni = 0; ni < 8; ni++) {
                int n = wn * 64 + ni * 8 + gid;
                bf[ni][0] = Bb[(kk + tig) * PB + n];
                bf[ni][1] = Bb[(kk + tig + 4) * PB + n];
            }
            #pragma unroll
            for (int mi = 0; mi < 2; mi++)
                #pragma unroll
                for (int ni = 0; ni < 8; ni++)
                    mma_tf32(acc[mi][ni][0], acc[mi][ni][1], acc[mi][ni][2], acc[mi][ni][3],
                             af[mi][0], af[mi][1], af[mi][2], af[mi][3],
                             bf[ni][0], bf[ni][1]);
        }
        __syncthreads();
    }

    #pragma unroll
    for (int mi = 0; mi < 2; mi++) {
        int r0 = row0 + wm * 32 + mi * 16 + gid;
        #pragma unroll
        for (int ni = 0; ni < 8; ni++) {
            int c = col0 + wn * 64 + ni * 8 + tig * 2;
            epi_write<GELU, RES>(C, bias, res, N, r0, r0 + 8, c,
                                 acc[mi][ni][0], acc[mi][ni][1],
                                 acc[mi][ni][2], acc[mi][ni][3]);
        }
    }
}

template<bool GELU, bool RES>
__global__ void __launch_bounds__(128, 3)
mm2_tc(const float* __restrict__ A, const float* __restrict__ W,
       const float* __restrict__ bias, const float* __restrict__ res,
       float* __restrict__ C, int N, int K) {
    extern __shared__ char smem[];
    mm2_body<GELU, RES>(A, W, bias, res, C, N, K,
                        blockIdx.y * 64, blockIdx.x * 128, smem);
}

__global__ void __launch_bounds__(128, 3)
qkv2_tc(const float* __restrict__ y,
        const float* __restrict__ wq, const float* __restrict__ bq, float* __restrict__ q,
        const float* __restrict__ wk, const float* __restrict__ bk, float* __restrict__ k,
        const float* __restrict__ wv, const float* __restrict__ bv, float* __restrict__ v) {
    extern __shared__ char smem[];
    const float* W; const float* bias; float* C;
    if (blockIdx.z == 0)      { W = wq; bias = bq; C = q; }
    else if (blockIdx.z == 1) { W = wk; bias = bk; C = k; }
    else                      { W = wv; bias = bv; C = v; }
    mm2_body<false, false>(y, W, bias, nullptr, C, EE, EE,
                           blockIdx.y * 64, blockIdx.x * 128, smem);
}

// ---------------- Flash attention: fused scores+softmax+PV, 2 CTAs/SM -------------
__global__ void __launch_bounds__(256, 2)
flash_tc(const float* __restrict__ q, const float* __restrict__ k,
         const float* __restrict__ v, float* __restrict__ ctx) {
    extern __shared__ char smem[];
    float* QP = (float*)smem;                    // [128][PQ]
    float* Ks = QP + 128 * PQ;                   // [FSTG][FK][PQ]
    float* Vs = Ks + FSTG * FK * PQ;             // [FSTG][FK][PVV]
    unsigned sQ = (unsigned)__cvta_generic_to_shared(QP);
    unsigned sK = (unsigned)__cvta_generic_to_shared(Ks);
    unsigned sV = (unsigned)__cvta_generic_to_shared(Vs);

    int bh = blockIdx.y;
    int b = bh / HH, h = bh % HH;
    int row0 = blockIdx.x * FM;
    const float* qb = q + (size_t)b * SS * EE + h * DD;
    const float* kb = k + (size_t)b * SS * EE + h * DD;
    const float* vb = v + (size_t)b * SS * EE + h * DD;

    int tid  = threadIdx.x;
    int warp = tid >> 5, lane = tid & 31;
    int gid  = lane >> 2, tig = lane & 3;

    int l_r = tid >> 4, l_c = (tid & 15) * 4;

    #pragma unroll
    for (int i = 0; i < 8; i++) {
        int r = l_r + i * 16;
        cp16(sQ + (unsigned)(r * PQ + l_c) * 4, qb + (size_t)(row0 + r) * EE + l_c);
    }
    cp_commit();

    auto load_kv = [&](int st, int k0) {
        #pragma unroll
        for (int i = 0; i < 2; i++) {
            int r = l_r + i * 16;
            cp16(sK + (unsigned)((st*FK + r) * PQ + l_c) * 4,
                 kb + (size_t)(k0 + r) * EE + l_c);
            cp16(sV + (unsigned)((st*FK + r) * PVV + l_c) * 4,
                 vb + (size_t)(k0 + r) * EE + l_c);
        }
        cp_commit();
    };
    load_kv(0, 0);
    load_kv(1, FK);
    load_kv(2, 2 * FK);

    cp_wait3();
    __syncthreads();

    int m0r = warp * 16 + gid;
    const unsigned* QPu = (const unsigned*)QP;
    unsigned qf[8][4];
    #pragma unroll
    for (int kc = 0; kc < 8; kc++) {
        qf[kc][0] = QPu[m0r * PQ + kc*8 + tig];
        qf[kc][1] = QPu[(m0r + 8) * PQ + kc*8 + tig];
        qf[kc][2] = QPu[m0r * PQ + kc*8 + tig + 4];
        qf[kc][3] = QPu[(m0r + 8) * PQ + kc*8 + tig + 4];
    }
    __syncwarp();

    float* Pw = QP + (warp * 16) * PQ;
    const unsigned* Pwu = (const unsigned*)Pw;

    float o[8][4];
    #pragma unroll
    for (int ni = 0; ni < 8; ni++)
        #pragma unroll
        for (int r = 0; r < 4; r++) o[ni][r] = 0.0f;
    float mx0 = -1e30f, mx1 = -1e30f, l0 = 0.0f, l1 = 0.0f;
    const float scale = rsqrtf((float)EE);

    const int NIT = SS / FK;   // 64
    for (int it = 0; it < NIT; it++) {
        if (it >= NIT - 3) cp_wait0(); else cp_wait2();
        __syncthreads();
        if (it + 3 < NIT) load_kv((it + 3) % FSTG, (it + 3) * FK);

        int buf = it % FSTG;
        const unsigned* Kb = (const unsigned*)(Ks + buf * FK * PQ);
        const unsigned* Vb = (const unsigned*)(Vs + buf * FK * PVV);

        float s[4][4];
        #pragma unroll
        for (int ni = 0; ni < 4; ni++)
            #pragma unroll
            for (int r = 0; r < 4; r++) s[ni][r] = 0.0f;

        #pragma unroll
        for (int kc = 0; kc < 8; kc++) {
            #pragma unroll
            for (int ni = 0; ni < 4; ni++) {
                int n = ni * 8 + gid;
                unsigned b0 = Kb[n * PQ + kc*8 + tig];
                unsigned b1 = Kb[n * PQ + kc*8 + tig + 4];
                mma_tf32(s[ni][0], s[ni][1], s[ni][2], s[ni][3],
                         qf[kc][0], qf[kc][1], qf[kc][2], qf[kc][3], b0, b1);
            }
        }

        float rm0 = -1e30f, rm1 = -1e30f;
        #pragma unroll
        for (int ni = 0; ni < 4; ni++) {
            s[ni][0] *= scale; s[ni][1] *= scale;
            s[ni][2] *= scale; s[ni][3] *= scale;
            rm0 = fmaxf(rm0, fmaxf(s[ni][0], s[ni][1]));
            rm1 = fmaxf(rm1, fmaxf(s[ni][2], s[ni][3]));
        }
        rm0 = fmaxf(rm0, __shfl_xor_sync(0xffffffffu, rm0, 1));
        rm0 = fmaxf(rm0, __shfl_xor_sync(0xffffffffu, rm0, 2));
        rm1 = fmaxf(rm1, __shfl_xor_sync(0xffffffffu, rm1, 1));
        rm1 = fmaxf(rm1, __shfl_xor_sync(0xffffffffu, rm1, 2));

        float mn0 = fmaxf(mx0, rm0), mn1 = fmaxf(mx1, rm1);
        float f0 = __expf(mx0 - mn0), f1 = __expf(mx1 - mn1);
        mx0 = mn0; mx1 = mn1;

        float rs0 = 0.0f, rs1 = 0.0f;
        #pragma unroll
        for (int ni = 0; ni < 4; ni++) {
            float p0 = __expf(s[ni][0] - mn0);
            float p1 = __expf(s[ni][1] - mn0);
            float p2 = __expf(s[ni][2] - mn1);
            float p3 = __expf(s[ni][3] - mn1);
            rs0 += p0 + p1; rs1 += p2 + p3;
            *(float2*)(Pw + gid * PQ + ni*8 + tig*2)       = make_float2(p0, p1);
            *(float2*)(Pw + (gid + 8) * PQ + ni*8 + tig*2) = make_float2(p2, p3);
        }
        rs0 += __shfl_xor_sync(0xffffffffu, rs0, 1);
        rs0 += __shfl_xor_sync(0xffffffffu, rs0, 2);
        rs1 += __shfl_xor_sync(0xffffffffu, rs1, 1);
        rs1 += __shfl_xor_sync(0xffffffffu, rs1, 2);
        l0 = l0 * f0 + rs0;
        l1 = l1 * f1 + rs1;

        #pragma unroll
        for (int ni = 0; ni < 8; ni++) {
            o[ni][0] *= f0; o[ni][1] *= f0;
            o[ni][2] *= f1; o[ni][3] *= f1;
        }
        __syncwarp();

        #pragma unroll
        for (int kc = 0; kc < 4; kc++) {
            unsigned a0 = Pwu[gid * PQ + kc*8 + tig];
            unsigned a1 = Pwu[(gid + 8) * PQ + kc*8 + tig];
            unsigned a2 = Pwu[gid * PQ + kc*8 + tig + 4];
            unsigned a3 = Pwu[(gid + 8) * PQ + kc*8 + tig + 4];
            #pragma unroll
            for (int ni = 0; ni < 8; ni++) {
                int n = ni * 8 + gid;
                unsigned b0 = Vb[(kc*8 + tig) * PVV + n];
                unsigned b1 = Vb[(kc*8 + tig + 4) * PVV + n];
                mma_tf32(o[ni][0], o[ni][1], o[ni][2], o[ni][3],
                         a0, a1, a2, a3, b0, b1);
            }
        }
        __syncwarp();
    }

    float i0 = 1.0f / l0, i1 = 1.0f / l1;
    float* c0row = ctx + (size_t)(b * SS + row0 + m0r) * EE + h * DD;
    float* c1row = ctx + (size_t)(b * SS + row0 + m0r + 8) * EE + h * DD;
    #pragma unroll
    for (int ni = 0; ni < 8; ni++) {
        int c = ni * 8 + tig * 2;
        *(float2*)(c0row + c) = make_float2(o[ni][0] * i0, o[ni][1] * i0);
        *(float2*)(c1row + c) = make_float2(o[ni][2] * i1, o[ni][3] * i1);
    }
}

// ---------------- launch ---------------------------------------------------------
extern "C" void kernel_launch(void* const* d_in, const int* in_sizes, int n_in,
                              void* d_out, int out_size) {
    (void)in_sizes; (void)n_in; (void)out_size;
    const float* x     = (const float*)d_in[0];
    const float* ln1_g = (const float*)d_in[1];
    const float* ln1_b = (const float*)d_in[2];
    const float* wq    = (const float*)d_in[3];
    const float* bq    = (const float*)d_in[4];
    const float* wk    = (const float*)d_in[5];
    const float* bk    = (const float*)d_in[6];
    const float* wv    = (const float*)d_in[7];
    const float* bv    = (const float*)d_in[8];
    const float* wo    = (const float*)d_in[9];
    const float* bo    = (const float*)d_in[10];
    const float* w1    = (const float*)d_in[11];
    const float* b1    = (const float*)d_in[12];
    const float* w2    = (const float*)d_in[13];
    const float* b2    = (const float*)d_in[14];
    const float* ln2_g = (const float*)d_in[15];
    const float* ln2_b = (const float*)d_in[16];
    float* out = (float*)d_out;

    float *y, *q, *k, *v, *ctx, *y2, *z, *hbuf;
    cudaGetSymbolAddress((void**)&y,    g_y);
    cudaGetSymbolAddress((void**)&q,    g_q);
    cudaGetSymbolAddress((void**)&k,    g_k);
    cudaGetSymbolAddress((void**)&v,    g_v);
    cudaGetSymbolAddress((void**)&ctx,  g_ctx);
    cudaGetSymbolAddress((void**)&y2,   g_y2);
    cudaGetSymbolAddress((void**)&z,    g_z);
    cudaGetSymbolAddress((void**)&hbuf, g_h);

    static bool attr_done = false;
    if (!attr_done) {
        cudaFuncSetAttribute(mm2_tc<false,true>, cudaFuncAttributeMaxDynamicSharedMemorySize, SM_MM2);
        cudaFuncSetAttribute(mm2_tc<true,false>, cudaFuncAttributeMaxDynamicSharedMemorySize, SM_MM2);
        cudaFuncSetAttribute(qkv2_tc,  cudaFuncAttributeMaxDynamicSharedMemorySize, SM_MM2);
        cudaFuncSetAttribute(flash_tc, cudaFuncAttributeMaxDynamicSharedMemorySize, SM_FLASH);
        attr_done = true;
    }

    dim3 blk128(128);
    dim3 blk256(256);

    // 1. y = LN1(x)
    ln_kernel<<<MM, blk256>>>(x, ln1_g, ln1_b, y);

    // 2. fused q,k,v projections (64x128 tiles: 6 x 64 x 3 = 1152 blocks)
    dim3 g_qkv(EE / 128, MM / 64, 3);
    qkv2_tc<<<g_qkv, blk128, SM_MM2>>>(y, wq, bq, q, wk, bk, k, wv, bv, v);

    // 3. flash attention
    dim3 g_fl(SS / FM, BH);
    flash_tc<<<g_fl, blk256, SM_FLASH>>>(q, k, v, ctx);

    // 4. y2 = x + ctx @ wo + bo   (384 blocks)
    dim3 g_e(EE / 128, MM / 64);
    mm2_tc<false, true><<<g_e, blk128, SM_MM2>>>(ctx, wo, bo, x, y2, EE, EE);

    // 5. z = LN2(y2)
    ln_kernel<<<MM, blk256>>>(y2, ln2_g, ln2_b, z);

    // 6. h = gelu(z @ w1 + b1)    (1536 blocks)
    dim3 g_ff(FF / 128, MM / 64);
    mm2_tc<true, false><<<g_ff, blk128, SM_MM2>>>(z, w1, b1, nullptr, hbuf, FF, EE);

    // 7. out = y2 + h @ w2 + b2   (384 blocks)
    mm2_tc<false, true><<<g_e, blk128, SM_MM2>>>(hbuf, w2, b2, y2, out, EE, FF);
}

// round 11
// speedup vs baseline: 37.8719x; 1.0372x over previous
#include <cuda_runtime.h>
#include <math.h>

#define BB 2
#define SS 2048
#define EE 768
#define HH 12
#define DD 64
#define MM (BB*SS)      /* 4096 rows */
#define FF (4*EE)       /* 3072 */
#define BH (BB*HH)      /* 24 */

#define BK 32           /* k-slab per iteration */
#define PA 36           /* A [row][k] pitch: 36 mod 32 = 4 -> 4*gid+tig distinct */
#define PB 136          /* B [k][n] pitch: 136 mod 32 = 8 -> 8*tig+gid distinct */

/* flash attention tiles */
#define FM 128
#define FK 32
#define PQ 68
#define PVV 72
#define FSTG 4

// dynamic smem sizes (bytes)
#define SM_MM3   (2*(64*PA + BK*PB)*4)                     /* 53248 */
#define SM_FLASH ((128*PQ + FSTG*FK*PQ + FSTG*FK*PVV)*4)   /* 106496 */

// ---------------- scratch (device globals; no allocation allowed) ----------------
__device__ float g_y  [MM*EE];
__device__ float g_q  [MM*EE];
__device__ float g_k  [MM*EE];
__device__ float g_v  [MM*EE];
__device__ float g_ctx[MM*EE];
__device__ float g_y2 [MM*EE];
__device__ float g_z  [MM*EE];
__device__ float g_h  [MM*FF];

// ---------------- helpers ---------------------------------------------------------
__device__ __forceinline__ void mma_tf32(float& c0, float& c1, float& c2, float& c3,
                                         unsigned a0, unsigned a1, unsigned a2, unsigned a3,
                                         unsigned b0, unsigned b1) {
    asm volatile(
        "mma.sync.aligned.m16n8k8.row.col.f32.tf32.tf32.f32 "
        "{%0,%1,%2,%3}, {%4,%5,%6,%7}, {%8,%9}, {%0,%1,%2,%3};"
        : "+f"(c0), "+f"(c1), "+f"(c2), "+f"(c3)
        : "r"(a0), "r"(a1), "r"(a2), "r"(a3), "r"(b0), "r"(b1));
}

__device__ __forceinline__ void cp16(unsigned saddr, const void* g) {
    asm volatile("cp.async.cg.shared.global [%0], [%1], 16;" :: "r"(saddr), "l"(g));
}
__device__ __forceinline__ void cp_commit() { asm volatile("cp.async.commit_group;"); }
__device__ __forceinline__ void cp_wait0()  { asm volatile("cp.async.wait_group 0;"); }
__device__ __forceinline__ void cp_wait2()  { asm volatile("cp.async.wait_group 2;"); }
__device__ __forceinline__ void cp_wait3()  { asm volatile("cp.async.wait_group 3;"); }

// ---------------- LayerNorm -------------------------------------------------------
__global__ void ln_kernel(const float* __restrict__ x, const float* __restrict__ gw,
                          const float* __restrict__ bw, float* __restrict__ out) {
    int row = blockIdx.x;
    int t = threadIdx.x;
    const float* xr = x + (size_t)row * EE;
    float v0 = xr[t], v1 = xr[t + 256], v2 = xr[t + 512];
    __shared__ float red[256];
    red[t] = v0 + v1 + v2;
    __syncthreads();
    #pragma unroll
    for (int o = 128; o > 0; o >>= 1) {
        if (t < o) red[t] += red[t + o];
        __syncthreads();
    }
    float mean = red[0] * (1.0f / EE);
    __syncthreads();
    float d0 = v0 - mean, d1 = v1 - mean, d2 = v2 - mean;
    red[t] = d0*d0 + d1*d1 + d2*d2;
    __syncthreads();
    #pragma unroll
    for (int o = 128; o > 0; o >>= 1) {
        if (t < o) red[t] += red[t + o];
        __syncthreads();
    }
    float rstd = rsqrtf(red[0] * (1.0f / EE) + 1e-5f);
    float* orow = out + (size_t)row * EE;
    orow[t]       = d0 * rstd * gw[t]       + bw[t];
    orow[t + 256] = d1 * rstd * gw[t + 256] + bw[t + 256];
    orow[t + 512] = d2 * rstd * gw[t + 512] + bw[t + 512];
}

// ---------------- GEMM epilogue helper --------------------------------------------
template<bool GELU, bool RES>
__device__ __forceinline__ void epi_write(float* C, const float* bias, const float* res,
                                          int N, int r0, int r1, int c,
                                          float v00, float v01, float v10, float v11) {
    float2 b2 = *(const float2*)(bias + c);
    v00 += b2.x; v01 += b2.y; v10 += b2.x; v11 += b2.y;
    if (RES) {
        float2 e0 = *(const float2*)(res + (size_t)r0 * N + c);
        float2 e1 = *(const float2*)(res + (size_t)r1 * N + c);
        v00 += e0.x; v01 += e0.y; v10 += e1.x; v11 += e1.y;
    }
    if (GELU) {
        v00 = v00 * 0.5f * (1.0f + erff(v00 * 0.70710678118654752f));
        v01 = v01 * 0.5f * (1.0f + erff(v01 * 0.70710678118654752f));
        v10 = v10 * 0.5f * (1.0f + erff(v10 * 0.70710678118654752f));
        v11 = v11 * 0.5f * (1.0f + erff(v11 * 0.70710678118654752f));
    }
    *(float2*)(C + (size_t)r0 * N + c) = make_float2(v00, v01);
    *(float2*)(C + (size_t)r1 * N + c) = make_float2(v10, v11);
}

// ---------------- GEMM core 64x128 CTA, 4 warps (2x2), warp tile 32x64 ------------
// BK=32, 2-stage double buffer, ONE barrier per k-slab.
template<bool GELU, bool RES>
__device__ __forceinline__ void
mm3_body(const float* __restrict__ A, const float* __restrict__ W,
         const float* __restrict__ bias, const float* __restrict__ res,
         float* __restrict__ C, int N, int K, int row0, int col0, char* smem) {
    unsigned* As_ = (unsigned*)smem;                  // [2][64][PA]
    unsigned* Bs_ = As_ + 2 * 64 * PA;                // [2][BK][PB]
    unsigned sA = (unsigned)__cvta_generic_to_shared(As_);
    unsigned sB = (unsigned)__cvta_generic_to_shared(Bs_);

    int tid  = threadIdx.x;                 // 128 threads
    int warp = tid >> 5, lane = tid & 31;
    int gid  = lane >> 2, tig = lane & 3;
    int wm   = warp & 1;                    // 0..1 -> 32 rows
    int wn   = warp >> 1;                   // 0..1 -> 64 cols

    float acc[2][8][4];
    #pragma unroll
    for (int i = 0; i < 2; i++)
        #pragma unroll
        for (int j = 0; j < 8; j++)
            #pragma unroll
            for (int r = 0; r < 4; r++) acc[i][j][r] = 0.0f;

    int NIT = K / BK;

    auto load_st = [&](int st, int k0) {
        // A tile 64x32: 512 float4 chunks, 4 per thread
        #pragma unroll
        for (int i = 0; i < 4; i++) {
            int slot = tid + i * 128;
            int r = slot >> 3, c4 = (slot & 7) * 4;
            cp16(sA + (unsigned)((st*64 + r)*PA + c4)*4,
                 A + (size_t)(row0 + r) * K + k0 + c4);
        }
        // B tile 32x128: 1024 float4 chunks, 8 per thread
        #pragma unroll
        for (int i = 0; i < 8; i++) {
            int slot = tid + i * 128;
            int r = slot >> 5, c4 = (slot & 31) * 4;
            cp16(sB + (unsigned)((st*BK + r)*PB + c4)*4,
                 W + (size_t)(k0 + r) * N + col0 + c4);
        }
        cp_commit();
    };

    load_st(0, 0);

    for (int it = 0; it < NIT; it++) {
        cp_wait0();
        __syncthreads();

        // issue next slab while computing this one (prev buf consumed in it-1,
        // all warps passed the barrier above, so overwrite is safe)
        if (it + 1 < NIT) load_st((it + 1) & 1, (it + 1) * BK);

        int buf = it & 1;
        const unsigned* Ab = As_ + buf * 64 * PA;
        const unsigned* Bb = Bs_ + buf * BK * PB;

        #pragma unroll
        for (int kk = 0; kk < BK; kk += 8) {
            unsigned af[2][4], bf[8][2];
            #pragma unroll
            for (int mi = 0; mi < 2; mi++) {
                int m = wm * 32 + mi * 16 + gid;
                af[mi][0] = Ab[m * PA + kk + tig];
                af[mi][1] = Ab[(m + 8) * PA + kk + tig];
                af[mi][2] = Ab[m * PA + kk + tig + 4];
                af[mi][3] = Ab[(m + 8) * PA + kk + tig + 4];
            }
            #pragma unroll
            for (int ni = 0; ni < 8; ni++) {
                int n = wn * 64 + ni * 8 + gid;
                bf[ni][0] = Bb[(kk + tig) * PB + n];
                bf[ni][1] = Bb[(kk + tig + 4) * PB + n];
            }
            #pragma unroll
            for (int mi = 0; mi < 2; mi++)
                #pragma unroll
                for (int ni = 0; ni < 8; ni++)
                    mma_tf32(acc[mi][ni][0], acc[mi][ni][1], acc[mi][ni][2], acc[mi][ni][3],
                             af[mi][0], af[mi][1], af[mi][2], af[mi][3],
                             bf[ni][0], bf[ni][1]);
        }
    }

    #pragma unroll
    for (int mi = 0; mi < 2; mi++) {
        int r0 = row0 + wm * 32 + mi * 16 + gid;
        #pragma unroll
        for (int ni = 0; ni < 8; ni++) {
            int c = col0 + wn * 64 + ni * 8 + tig * 2;
            epi_write<GELU, RES>(C, bias, res, N, r0, r0 + 8, c,
                                 acc[mi][ni][0], acc[mi][ni][1],
                                 acc[mi][ni][2], acc[mi][ni][3]);
        }
    }
}

template<bool GELU, bool RES>
__global__ void __launch_bounds__(128, 3)
mm3_tc(const float* __restrict__ A, const float* __restrict__ W,
       const float* __restrict__ bias, const float* __restrict__ res,
       float* __restrict__ C, int N, int K) {
    extern __shared__ char smem[];
    mm3_body<GELU, RES>(A, W, bias, res, C, N, K,
                        blockIdx.y * 64, blockIdx.x * 128, smem);
}

__global__ void __launch_bounds__(128, 3)
qkv3_tc(const float* __restrict__ y,
        const float* __restrict__ wq, const float* __restrict__ bq, float* __restrict__ q,
        const float* __restrict__ wk, const float* __restrict__ bk, float* __restrict__ k,
        const float* __restrict__ wv, const float* __restrict__ bv, float* __restrict__ v) {
    extern __shared__ char smem[];
    const float* W; const float* bias; float* C;
    if (blockIdx.z == 0)      { W = wq; bias = bq; C = q; }
    else if (blockIdx.z == 1) { W = wk; bias = bk; C = k; }
    else                      { W = wv; bias = bv; C = v; }
    mm3_body<false, false>(y, W, bias, nullptr, C, EE, EE,
                           blockIdx.y * 64, blockIdx.x * 128, smem);
}

// ---------------- Flash attention: fused scores+softmax+PV, 2 CTAs/SM -------------
__global__ void __launch_bounds__(256, 2)
flash_tc(const float* __restrict__ q, const float* __restrict__ k,
         const float* __restrict__ v, float* __restrict__ ctx) {
    extern __shared__ char smem[];
    float* QP = (float*)smem;                    // [128][PQ]
    float* Ks = QP + 128 * PQ;                   // [FSTG][FK][PQ]
    float* Vs = Ks + FSTG * FK * PQ;             // [FSTG][FK][PVV]
    unsigned sQ = (unsigned)__cvta_generic_to_shared(QP);
    unsigned sK = (unsigned)__cvta_generic_to_shared(Ks);
    unsigned sV = (unsigned)__cvta_generic_to_shared(Vs);

    int bh = blockIdx.y;
    int b = bh / HH, h = bh % HH;
    int row0 = blockIdx.x * FM;
    const float* qb = q + (size_t)b * SS * EE + h * DD;
    const float* kb = k + (size_t)b * SS * EE + h * DD;
    const float* vb = v + (size_t)b * SS * EE + h * DD;

    int tid  = threadIdx.x;
    int warp = tid >> 5, lane = tid & 31;
    int gid  = lane >> 2, tig = lane & 3;

    int l_r = tid >> 4, l_c = (tid & 15) * 4;

    #pragma unroll
    for (int i = 0; i < 8; i++) {
        int r = l_r + i * 16;
        cp16(sQ + (unsigned)(r * PQ + l_c) * 4, qb + (size_t)(row0 + r) * EE + l_c);
    }
    cp_commit();

    auto load_kv = [&](int st, int k0) {
        #pragma unroll
        for (int i = 0; i < 2; i++) {
            int r = l_r + i * 16;
            cp16(sK + (unsigned)((st*FK + r) * PQ + l_c) * 4,
                 kb + (size_t)(k0 + r) * EE + l_c);
            cp16(sV + (unsigned)((st*FK + r) * PVV + l_c) * 4,
                 vb + (size_t)(k0 + r) * EE + l_c);
        }
        cp_commit();
    };
    load_kv(0, 0);
    load_kv(1, FK);
    load_kv(2, 2 * FK);

    cp_wait3();
    __syncthreads();

    int m0r = warp * 16 + gid;
    const unsigned* QPu = (const unsigned*)QP;
    unsigned qf[8][4];
    #pragma unroll
    for (int kc = 0; kc < 8; kc++) {
        qf[kc][0] = QPu[m0r * PQ + kc*8 + tig];
        qf[kc][1] = QPu[(m0r + 8) * PQ + kc*8 + tig];
        qf[kc][2] = QPu[m0r * PQ + kc*8 + tig + 4];
        qf[kc][3] = QPu[(m0r + 8) * PQ + kc*8 + tig + 4];
    }
    __syncwarp();

    float* Pw = QP + (warp * 16) * PQ;
    const unsigned* Pwu = (const unsigned*)Pw;

    float o[8][4];
    #pragma unroll
    for (int ni = 0; ni < 8; ni++)
        #pragma unroll
        for (int r = 0; r < 4; r++) o[ni][r] = 0.0f;
    float mx0 = -1e30f, mx1 = -1e30f, l0 = 0.0f, l1 = 0.0f;
    const float scale = rsqrtf((float)EE);

    const int NIT = SS / FK;   // 64
    for (int it = 0; it < NIT; it++) {
        if (it >= NIT - 3) cp_wait0(); else cp_wait2();
        __syncthreads();
        if (it + 3 < NIT) load_kv((it + 3) % FSTG, (it + 3) * FK);

        int buf = it % FSTG;
        const unsigned* Kb = (const unsigned*)(Ks + buf * FK * PQ);
        const unsigned* Vb = (const unsigned*)(Vs + buf * FK * PVV);

        float s[4][4];
        #pragma unroll
        for (int ni = 0; ni < 4; ni++)
            #pragma unroll
            for (int r = 0; r < 4; r++) s[ni][r] = 0.0f;

        #pragma unroll
        for (int kc = 0; kc < 8; kc++) {
            #pragma unroll
            for (int ni = 0; ni < 4; ni++) {
                int n = ni * 8 + gid;
                unsigned b0 = Kb[n * PQ + kc*8 + tig];
                unsigned b1 = Kb[n * PQ + kc*8 + tig + 4];
                mma_tf32(s[ni][0], s[ni][1], s[ni][2], s[ni][3],
                         qf[kc][0], qf[kc][1], qf[kc][2], qf[kc][3], b0, b1);
            }
        }

        float rm0 = -1e30f, rm1 = -1e30f;
        #pragma unroll
        for (int ni = 0; ni < 4; ni++) {
            s[ni][0] *= scale; s[ni][1] *= scale;
            s[ni][2] *= scale; s[ni][3] *= scale;
            rm0 = fmaxf(rm0, fmaxf(s[ni][0], s[ni][1]));
            rm1 = fmaxf(rm1, fmaxf(s[ni][2], s[ni][3]));
        }
        rm0 = fmaxf(rm0, __shfl_xor_sync(0xffffffffu, rm0, 1));
        rm0 = fmaxf(rm0, __shfl_xor_sync(0xffffffffu, rm0, 2));
        rm1 = fmaxf(rm1, __shfl_xor_sync(0xffffffffu, rm1, 1));
        rm1 = fmaxf(rm1, __shfl_xor_sync(0xffffffffu, rm1, 2));

        float mn0 = fmaxf(mx0, rm0), mn1 = fmaxf(mx1, rm1);
        float f0 = __expf(mx0 - mn0), f1 = __expf(mx1 - mn1);
        mx0 = mn0; mx1 = mn1;

        float rs0 = 0.0f, rs1 = 0.0f;
        #pragma unroll
        for (int ni = 0; ni < 4; ni++) {
            float p0 = __expf(s[ni][0] - mn0);
            float p1 = __expf(s[ni][1] - mn0);
            float p2 = __expf(s[ni][2] - mn1);
            float p3 = __expf(s[ni][3] - mn1);
            rs0 += p0 + p1; rs1 += p2 + p3;
            *(float2*)(Pw + gid * PQ + ni*8 + tig*2)       = make_float2(p0, p1);
            *(float2*)(Pw + (gid + 8) * PQ + ni*8 + tig*2) = make_float2(p2, p3);
        }
        rs0 += __shfl_xor_sync(0xffffffffu, rs0, 1);
        rs0 += __shfl_xor_sync(0xffffffffu, rs0, 2);
        rs1 += __shfl_xor_sync(0xffffffffu, rs1, 1);
        rs1 += __shfl_xor_sync(0xffffffffu, rs1, 2);
        l0 = l0 * f0 + rs0;
        l1 = l1 * f1 + rs1;

        #pragma unroll
        for (int ni = 0; ni < 8; ni++) {
            o[ni][0] *= f0; o[ni][1] *= f0;
            o[ni][2] *= f1; o[ni][3] *= f1;
        }
        __syncwarp();

        #pragma unroll
        for (int kc = 0; kc < 4; kc++) {
            unsigned a0 = Pwu[gid * PQ + kc*8 + tig];
            unsigned a1 = Pwu[(gid + 8) * PQ + kc*8 + tig];
            unsigned a2 = Pwu[gid * PQ + kc*8 + tig + 4];
            unsigned a3 = Pwu[(gid + 8) * PQ + kc*8 + tig + 4];
            #pragma unroll
            for (int ni = 0; ni < 8; ni++) {
                int n = ni * 8 + gid;
                unsigned b0 = Vb[(kc*8 + tig) * PVV + n];
                unsigned b1 = Vb[(kc*8 + tig + 4) * PVV + n];
                mma_tf32(o[ni][0], o[ni][1], o[ni][2], o[ni][3],
                         a0, a1, a2, a3, b0, b1);
            }
        }
        __syncwarp();
    }

    float i0 = 1.0f / l0, i1 = 1.0f / l1;
    float* c0row = ctx + (size_t)(b * SS + row0 + m0r) * EE + h * DD;
    float* c1row = ctx + (size_t)(b * SS + row0 + m0r + 8) * EE + h * DD;
    #pragma unroll
    for (int ni = 0; ni < 8; ni++) {
        int c = ni * 8 + tig * 2;
        *(float2*)(c0row + c) = make_float2(o[ni][0] * i0, o[ni][1] * i0);
        *(float2*)(c1row + c) = make_float2(o[ni][2] * i1, o[ni][3] * i1);
    }
}

// ---------------- launch ---------------------------------------------------------
extern "C" void kernel_launch(void* const* d_in, const int* in_sizes, int n_in,
                              void* d_out, int out_size) {
    (void)in_sizes; (void)n_in; (void)out_size;
    const float* x     = (const float*)d_in[0];
    const float* ln1_g = (const float*)d_in[1];
    const float* ln1_b = (const float*)d_in[2];
    const float* wq    = (const float*)d_in[3];
    const float* bq    = (const float*)d_in[4];
    const float* wk    = (const float*)d_in[5];
    const float* bk    = (const float*)d_in[6];
    const float* wv    = (const float*)d_in[7];
    const float* bv    = (const float*)d_in[8];
    const float* wo    = (const float*)d_in[9];
    const float* bo    = (const float*)d_in[10];
    const float* w1    = (const float*)d_in[11];
    const float* b1    = (const float*)d_in[12];
    const float* w2    = (const float*)d_in[13];
    const float* b2    = (const float*)d_in[14];
    const float* ln2_g = (const float*)d_in[15];
    const float* ln2_b = (const float*)d_in[16];
    float* out = (float*)d_out;

    float *y, *q, *k, *v, *ctx, *y2, *z, *hbuf;
    cudaGetSymbolAddress((void**)&y,    g_y);
    cudaGetSymbolAddress((void**)&q,    g_q);
    cudaGetSymbolAddress((void**)&k,    g_k);
    cudaGetSymbolAddress((void**)&v,    g_v);
    cudaGetSymbolAddress((void**)&ctx,  g_ctx);
    cudaGetSymbolAddress((void**)&y2,   g_y2);
    cudaGetSymbolAddress((void**)&z,    g_z);
    cudaGetSymbolAddress((void**)&hbuf, g_h);

    static bool attr_done = false;
    if (!attr_done) {
        cudaFuncSetAttribute(mm3_tc<false,true>, cudaFuncAttributeMaxDynamicSharedMemorySize, SM_MM3);
        cudaFuncSetAttribute(mm3_tc<true,false>, cudaFuncAttributeMaxDynamicSharedMemorySize, SM_MM3);
        cudaFuncSetAttribute(qkv3_tc,  cudaFuncAttributeMaxDynamicSharedMemorySize, SM_MM3);
        cudaFuncSetAttribute(flash_tc, cudaFuncAttributeMaxDynamicSharedMemorySize, SM_FLASH);
        attr_done = true;
    }

    dim3 blk128(128);
    dim3 blk256(256);

    // 1. y = LN1(x)
    ln_kernel<<<MM, blk256>>>(x, ln1_g, ln1_b, y);

    // 2. fused q,k,v projections (64x128 tiles: 6 x 64 x 3 = 1152 blocks)
    dim3 g_qkv(EE / 128, MM / 64, 3);
    qkv3_tc<<<g_qkv, blk128, SM_MM3>>>(y, wq, bq, q, wk, bk, k, wv, bv, v);

    // 3. flash attention
    dim3 g_fl(SS / FM, BH);
    flash_tc<<<g_fl, blk256, SM_FLASH>>>(q, k, v, ctx);

    // 4. y2 = x + ctx @ wo + bo   (384 blocks)
    dim3 g_e(EE / 128, MM / 64);
    mm3_tc<false, true><<<g_e, blk128, SM_MM3>>>(ctx, wo, bo, x, y2, EE, EE);

    // 5. z = LN2(y2)
    ln_kernel<<<MM, blk256>>>(y2, ln2_g, ln2_b, z);

    // 6. h = gelu(z @ w1 + b1)    (1536 blocks)
    dim3 g_ff(FF / 128, MM / 64);
    mm3_tc<true, false><<<g_ff, blk128, SM_MM3>>>(z, w1, b1, nullptr, hbuf, FF, EE);

    // 7. out = y2 + h @ w2 + b2   (384 blocks)
    mm3_tc<false, true><<<g_e, blk128, SM_MM3>>>(hbuf, w2, b2, y2, out, EE, FF);
}

// round 12
// speedup vs baseline: 46.9035x; 1.2385x over previous
#include <cuda_runtime.h>
#include <cuda_fp16.h>
#include <math.h>

#define BB 2
#define SS 2048
#define EE 768
#define HH 12
#define DD 64
#define MM (BB*SS)      /* 4096 rows */
#define FF (4*EE)       /* 3072 */
#define BH (BB*HH)      /* 24 */

#define BK 32           /* k halves per slab */
#define PAW 20          /* [row][k] pitch in half2 WORDS: 16 data + 4 pad; 20*gid mod 32 distinct */

/* flash attention tiles (tf32 path, unchanged) */
#define FM 128
#define FK 32
#define PQ 68
#define PVV 72
#define FSTG 4

// dynamic smem sizes (bytes)
#define SM_MMH   (2*(64*PAW + 128*PAW)*4)                  /* 30720 */
#define SM_FLASH ((128*PQ + FSTG*FK*PQ + FSTG*FK*PVV)*4)   /* 106496 */

// ---------------- scratch (device globals; no allocation allowed) ----------------
__device__ __half g_y  [MM*EE];      /* LN1 out (half, feeds QKV) */
__device__ float  g_q  [MM*EE];
__device__ float  g_k  [MM*EE];
__device__ float  g_v  [MM*EE];
__device__ __half g_ctx[MM*EE];      /* flash out (half, feeds wo) */
__device__ float  g_y2 [MM*EE];
__device__ __half g_z  [MM*EE];      /* LN2 out (half, feeds FF1) */
__device__ __half g_h  [MM*FF];      /* FF1 out (half, feeds FF2) */
/* converted + transposed weights: [N][K] halves */
__device__ __half g_wtq[EE*EE];
__device__ __half g_wtk[EE*EE];
__device__ __half g_wtv[EE*EE];
__device__ __half g_wto[EE*EE];
__device__ __half g_wt1[FF*EE];
__device__ __half g_wt2[EE*FF];

// ---------------- helpers ---------------------------------------------------------
__device__ __forceinline__ void mma_f16(float& c0, float& c1, float& c2, float& c3,
                                        unsigned a0, unsigned a1, unsigned a2, unsigned a3,
                                        unsigned b0, unsigned b1) {
    asm volatile(
        "mma.sync.aligned.m16n8k16.row.col.f32.f16.f16.f32 "
        "{%0,%1,%2,%3}, {%4,%5,%6,%7}, {%8,%9}, {%0,%1,%2,%3};"
        : "+f"(c0), "+f"(c1), "+f"(c2), "+f"(c3)
        : "r"(a0), "r"(a1), "r"(a2), "r"(a3), "r"(b0), "r"(b1));
}
__device__ __forceinline__ void mma_tf32(float& c0, float& c1, float& c2, float& c3,
                                         unsigned a0, unsigned a1, unsigned a2, unsigned a3,
                                         unsigned b0, unsigned b1) {
    asm volatile(
        "mma.sync.aligned.m16n8k8.row.col.f32.tf32.tf32.f32 "
        "{%0,%1,%2,%3}, {%4,%5,%6,%7}, {%8,%9}, {%0,%1,%2,%3};"
        : "+f"(c0), "+f"(c1), "+f"(c2), "+f"(c3)
        : "r"(a0), "r"(a1), "r"(a2), "r"(a3), "r"(b0), "r"(b1));
}

__device__ __forceinline__ void cp16(unsigned saddr, const void* g) {
    asm volatile("cp.async.cg.shared.global [%0], [%1], 16;" :: "r"(saddr), "l"(g));
}
__device__ __forceinline__ void cp_commit() { asm volatile("cp.async.commit_group;"); }
__device__ __forceinline__ void cp_wait0()  { asm volatile("cp.async.wait_group 0;"); }
__device__ __forceinline__ void cp_wait2()  { asm volatile("cp.async.wait_group 2;"); }
__device__ __forceinline__ void cp_wait3()  { asm volatile("cp.async.wait_group 3;"); }

// ---------------- weight convert + transpose: dst_h[C][R] = (half)src[R][C]^T -----
__global__ void cvt_t(const float* __restrict__ src, __half* __restrict__ dst,
                      int R, int C) {
    __shared__ float t[32][33];
    int bx = blockIdx.x * 32;   // col base in src
    int by = blockIdx.y * 32;   // row base in src
    int x = threadIdx.x, y0 = threadIdx.y;
    #pragma unroll
    for (int i = 0; i < 32; i += 8)
        t[y0 + i][x] = src[(size_t)(by + y0 + i) * C + bx + x];
    __syncthreads();
    #pragma unroll
    for (int i = 0; i < 32; i += 8)
        dst[(size_t)(bx + y0 + i) * R + by + x] = __float2half(t[x][y0 + i]);
}

// ---------------- LayerNorm (fp32 in, half out) ------------------------------------
__global__ void ln_kernel(const float* __restrict__ x, const float* __restrict__ gw,
                          const float* __restrict__ bw, __half* __restrict__ out) {
    int row = blockIdx.x;
    int t = threadIdx.x;
    const float* xr = x + (size_t)row * EE;
    float v0 = xr[t], v1 = xr[t + 256], v2 = xr[t + 512];
    __shared__ float red[256];
    red[t] = v0 + v1 + v2;
    __syncthreads();
    #pragma unroll
    for (int o = 128; o > 0; o >>= 1) {
        if (t < o) red[t] += red[t + o];
        __syncthreads();
    }
    float mean = red[0] * (1.0f / EE);
    __syncthreads();
    float d0 = v0 - mean, d1 = v1 - mean, d2 = v2 - mean;
    red[t] = d0*d0 + d1*d1 + d2*d2;
    __syncthreads();
    #pragma unroll
    for (int o = 128; o > 0; o >>= 1) {
        if (t < o) red[t] += red[t + o];
        __syncthreads();
    }
    float rstd = rsqrtf(red[0] * (1.0f / EE) + 1e-5f);
    __half* orow = out + (size_t)row * EE;
    orow[t]       = __float2half(d0 * rstd * gw[t]       + bw[t]);
    orow[t + 256] = __float2half(d1 * rstd * gw[t + 256] + bw[t + 256]);
    orow[t + 512] = __float2half(d2 * rstd * gw[t + 512] + bw[t + 512]);
}

// ---------------- fp16 GEMM core 64x128 CTA, 4 warps (2x2), warp tile 32x64 -------
// A: half [M][K]; Wt: half [N][K] (pre-transposed). Both smem tiles [row][k] as
// half2 words, pitch PAW. Every fragment register = one LDS.32. BK=32 halves,
// 2-stage double buffer, one barrier per slab, two k16 MMA groups per slab.
template<bool GELU, bool RES, bool OUTH>
__device__ __forceinline__ void
mmh_body(const __half* __restrict__ A, const __half* __restrict__ Wt,
         const float* __restrict__ bias, const float* __restrict__ res,
         void* __restrict__ Cv, int N, int K, int row0, int col0, char* smem) {
    unsigned* As_ = (unsigned*)smem;                  // [2][64][PAW]
    unsigned* Bs_ = As_ + 2 * 64 * PAW;               // [2][128][PAW]
    unsigned sA = (unsigned)__cvta_generic_to_shared(As_);
    unsigned sB = (unsigned)__cvta_generic_to_shared(Bs_);

    int tid  = threadIdx.x;                 // 128 threads
    int warp = tid >> 5, lane = tid & 31;
    int gid  = lane >> 2, tig = lane & 3;
    int wm   = warp & 1;                    // 0..1 -> 32 rows
    int wn   = warp >> 1;                   // 0..1 -> 64 cols

    float acc[2][8][4];
    #pragma unroll
    for (int i = 0; i < 2; i++)
        #pragma unroll
        for (int j = 0; j < 8; j++)
            #pragma unroll
            for (int r = 0; r < 4; r++) acc[i][j][r] = 0.0f;

    int NIT = K / BK;

    auto load_st = [&](int st, int k0) {
        // A tile 64 rows x 32 halves = 256 cp16 chunks (2/thread)
        #pragma unroll
        for (int i = 0; i < 2; i++) {
            int slot = tid + i * 128;
            int r = slot >> 2, cw = (slot & 3) * 4;     // word offset 0,4,8,12
            cp16(sA + (unsigned)((st*64 + r)*PAW + cw)*4,
                 A + (size_t)(row0 + r) * K + k0 + (slot & 3) * 8);
        }
        // B tile 128 rows x 32 halves = 512 chunks (4/thread)
        #pragma unroll
        for (int i = 0; i < 4; i++) {
            int slot = tid + i * 128;
            int r = slot >> 2, cw = (slot & 3) * 4;
            cp16(sB + (unsigned)((st*128 + r)*PAW + cw)*4,
                 Wt + (size_t)(col0 + r) * K + k0 + (slot & 3) * 8);
        }
        cp_commit();
    };

    load_st(0, 0);

    for (int it = 0; it < NIT; it++) {
        cp_wait0();
        __syncthreads();

        if (it + 1 < NIT) load_st((it + 1) & 1, (it + 1) * BK);

        int buf = it & 1;
        const unsigned* Ab = As_ + buf * 64 * PAW;
        const unsigned* Bb = Bs_ + buf * 128 * PAW;

        #pragma unroll
        for (int kk2 = 0; kk2 < 2; kk2++) {            // two k16 groups
            int kw = kk2 * 8;                          // word offset
            unsigned af[2][4], bf[8][2];
            #pragma unroll
            for (int mi = 0; mi < 2; mi++) {
                int m = wm * 32 + mi * 16 + gid;
                af[mi][0] = Ab[m * PAW + kw + tig];
                af[mi][1] = Ab[(m + 8) * PAW + kw + tig];
                af[mi][2] = Ab[m * PAW + kw + tig + 4];
                af[mi][3] = Ab[(m + 8) * PAW + kw + tig + 4];
            }
            #pragma unroll
            for (int ni = 0; ni < 8; ni++) {
                int n = wn * 64 + ni * 8 + gid;
                bf[ni][0] = Bb[n * PAW + kw + tig];
                bf[ni][1] = Bb[n * PAW + kw + tig + 4];
            }
            #pragma unroll
            for (int mi = 0; mi < 2; mi++)
                #pragma unroll
                for (int ni = 0; ni < 8; ni++)
                    mma_f16(acc[mi][ni][0], acc[mi][ni][1], acc[mi][ni][2], acc[mi][ni][3],
                            af[mi][0], af[mi][1], af[mi][2], af[mi][3],
                            bf[ni][0], bf[ni][1]);
        }
    }

    // epilogue (fp32 math)
    #pragma unroll
    for (int mi = 0; mi < 2; mi++) {
        int r0 = row0 + wm * 32 + mi * 16 + gid;
        int r1 = r0 + 8;
        #pragma unroll
        for (int ni = 0; ni < 8; ni++) {
            int c = col0 + wn * 64 + ni * 8 + tig * 2;
            float2 b2 = *(const float2*)(bias + c);
            float v00 = acc[mi][ni][0] + b2.x;
            float v01 = acc[mi][ni][1] + b2.y;
            float v10 = acc[mi][ni][2] + b2.x;
            float v11 = acc[mi][ni][3] + b2.y;
            if (RES) {
                float2 e0 = *(const float2*)(res + (size_t)r0 * N + c);
                float2 e1 = *(const float2*)(res + (size_t)r1 * N + c);
                v00 += e0.x; v01 += e0.y; v10 += e1.x; v11 += e1.y;
            }
            if (GELU) {
                v00 = v00 * 0.5f * (1.0f + erff(v00 * 0.70710678118654752f));
                v01 = v01 * 0.5f * (1.0f + erff(v01 * 0.70710678118654752f));
                v10 = v10 * 0.5f * (1.0f + erff(v10 * 0.70710678118654752f));
                v11 = v11 * 0.5f * (1.0f + erff(v11 * 0.70710678118654752f));
            }
            if (OUTH) {
                __half2* C = (__half2*)Cv;
                C[((size_t)r0 * N + c) / 2] = __floats2half2_rn(v00, v01);
                C[((size_t)r1 * N + c) / 2] = __floats2half2_rn(v10, v11);
            } else {
                float* C = (float*)Cv;
                *(float2*)(C + (size_t)r0 * N + c) = make_float2(v00, v01);
                *(float2*)(C + (size_t)r1 * N + c) = make_float2(v10, v11);
            }
        }
    }
}

template<bool GELU, bool RES, bool OUTH>
__global__ void __launch_bounds__(128, 3)
mmh_tc(const __half* __restrict__ A, const __half* __restrict__ Wt,
       const float* __restrict__ bias, const float* __restrict__ res,
       void* __restrict__ C, int N, int K) {
    extern __shared__ char smem[];
    mmh_body<GELU, RES, OUTH>(A, Wt, bias, res, C, N, K,
                              blockIdx.y * 64, blockIdx.x * 128, smem);
}

__global__ void __launch_bounds__(128, 3)
qkvh_tc(const __half* __restrict__ y,
        const __half* __restrict__ wtq, const float* __restrict__ bq, float* __restrict__ q,
        const __half* __restrict__ wtk, const float* __restrict__ bk, float* __restrict__ k,
        const __half* __restrict__ wtv, const float* __restrict__ bv, float* __restrict__ v) {
    extern __shared__ char smem[];
    const __half* Wt; const float* bias; float* C;
    if (blockIdx.z == 0)      { Wt = wtq; bias = bq; C = q; }
    else if (blockIdx.z == 1) { Wt = wtk; bias = bk; C = k; }
    else                      { Wt = wtv; bias = bv; C = v; }
    mmh_body<false, false, false>(y, Wt, bias, nullptr, C, EE, EE,
                                  blockIdx.y * 64, blockIdx.x * 128, smem);
}

// ---------------- Flash attention (tf32, fp32 q/k/v in, half ctx out) --------------
__global__ void __launch_bounds__(256, 2)
flash_tc(const float* __restrict__ q, const float* __restrict__ k,
         const float* __restrict__ v, __half* __restrict__ ctx) {
    extern __shared__ char smem[];
    float* QP = (float*)smem;                    // [128][PQ]
    float* Ks = QP + 128 * PQ;                   // [FSTG][FK][PQ]
    float* Vs = Ks + FSTG * FK * PQ;             // [FSTG][FK][PVV]
    unsigned sQ = (unsigned)__cvta_generic_to_shared(QP);
    unsigned sK = (unsigned)__cvta_generic_to_shared(Ks);
    unsigned sV = (unsigned)__cvta_generic_to_shared(Vs);

    int bh = blockIdx.y;
    int b = bh / HH, h = bh % HH;
    int row0 = blockIdx.x * FM;
    const float* qb = q + (size_t)b * SS * EE + h * DD;
    const float* kb = k + (size_t)b * SS * EE + h * DD;
    const float* vb = v + (size_t)b * SS * EE + h * DD;

    int tid  = threadIdx.x;
    int warp = tid >> 5, lane = tid & 31;
    int gid  = lane >> 2, tig = lane & 3;

    int l_r = tid >> 4, l_c = (tid & 15) * 4;

    #pragma unroll
    for (int i = 0; i < 8; i++) {
        int r = l_r + i * 16;
        cp16(sQ + (unsigned)(r * PQ + l_c) * 4, qb + (size_t)(row0 + r) * EE + l_c);
    }
    cp_commit();

    auto load_kv = [&](int st, int k0) {
        #pragma unroll
        for (int i = 0; i < 2; i++) {
            int r = l_r + i * 16;
            cp16(sK + (unsigned)((st*FK + r) * PQ + l_c) * 4,
                 kb + (size_t)(k0 + r) * EE + l_c);
            cp16(sV + (unsigned)((st*FK + r) * PVV + l_c) * 4,
                 vb + (size_t)(k0 + r) * EE + l_c);
        }
        cp_commit();
    };
    load_kv(0, 0);
    load_kv(1, FK);
    load_kv(2, 2 * FK);

    cp_wait3();
    __syncthreads();

    int m0r = warp * 16 + gid;
    const unsigned* QPu = (const unsigned*)QP;
    unsigned qf[8][4];
    #pragma unroll
    for (int kc = 0; kc < 8; kc++) {
        qf[kc][0] = QPu[m0r * PQ + kc*8 + tig];
        qf[kc][1] = QPu[(m0r + 8) * PQ + kc*8 + tig];
        qf[kc][2] = QPu[m0r * PQ + kc*8 + tig + 4];
        qf[kc][3] = QPu[(m0r + 8) * PQ + kc*8 + tig + 4];
    }
    __syncwarp();

    float* Pw = QP + (warp * 16) * PQ;
    const unsigned* Pwu = (const unsigned*)Pw;

    float o[8][4];
    #pragma unroll
    for (int ni = 0; ni < 8; ni++)
        #pragma unroll
        for (int r = 0; r < 4; r++) o[ni][r] = 0.0f;
    float mx0 = -1e30f, mx1 = -1e30f, l0 = 0.0f, l1 = 0.0f;
    const float scale = rsqrtf((float)EE);

    const int NIT = SS / FK;   // 64
    for (int it = 0; it < NIT; it++) {
        if (it >= NIT - 3) cp_wait0(); else cp_wait2();
        __syncthreads();
        if (it + 3 < NIT) load_kv((it + 3) % FSTG, (it + 3) * FK);

        int buf = it % FSTG;
        const unsigned* Kb = (const unsigned*)(Ks + buf * FK * PQ);
        const unsigned* Vb = (const unsigned*)(Vs + buf * FK * PVV);

        float s[4][4];
        #pragma unroll
        for (int ni = 0; ni < 4; ni++)
            #pragma unroll
            for (int r = 0; r < 4; r++) s[ni][r] = 0.0f;

        #pragma unroll
        for (int kc = 0; kc < 8; kc++) {
            #pragma unroll
            for (int ni = 0; ni < 4; ni++) {
                int n = ni * 8 + gid;
                unsigned b0 = Kb[n * PQ + kc*8 + tig];
                unsigned b1 = Kb[n * PQ + kc*8 + tig + 4];
                mma_tf32(s[ni][0], s[ni][1], s[ni][2], s[ni][3],
                         qf[kc][0], qf[kc][1], qf[kc][2], qf[kc][3], b0, b1);
            }
        }

        float rm0 = -1e30f, rm1 = -1e30f;
        #pragma unroll
        for (int ni = 0; ni < 4; ni++) {
            s[ni][0] *= scale; s[ni][1] *= scale;
            s[ni][2] *= scale; s[ni][3] *= scale;
            rm0 = fmaxf(rm0, fmaxf(s[ni][0], s[ni][1]));
            rm1 = fmaxf(rm1, fmaxf(s[ni][2], s[ni][3]));
        }
        rm0 = fmaxf(rm0, __shfl_xor_sync(0xffffffffu, rm0, 1));
        rm0 = fmaxf(rm0, __shfl_xor_sync(0xffffffffu, rm0, 2));
        rm1 = fmaxf(rm1, __shfl_xor_sync(0xffffffffu, rm1, 1));
        rm1 = fmaxf(rm1, __shfl_xor_sync(0xffffffffu, rm1, 2));

        float mn0 = fmaxf(mx0, rm0), mn1 = fmaxf(mx1, rm1);
        float f0 = __expf(mx0 - mn0), f1 = __expf(mx1 - mn1);
        mx0 = mn0; mx1 = mn1;

        float rs0 = 0.0f, rs1 = 0.0f;
        #pragma unroll
        for (int ni = 0; ni < 4; ni++) {
            float p0 = __expf(s[ni][0] - mn0);
            float p1 = __expf(s[ni][1] - mn0);
            float p2 = __expf(s[ni][2] - mn1);
            float p3 = __expf(s[ni][3] - mn1);
            rs0 += p0 + p1; rs1 += p2 + p3;
            *(float2*)(Pw + gid * PQ + ni*8 + tig*2)       = make_float2(p0, p1);
            *(float2*)(Pw + (gid + 8) * PQ + ni*8 + tig*2) = make_float2(p2, p3);
        }
        rs0 += __shfl_xor_sync(0xffffffffu, rs0, 1);
        rs0 += __shfl_xor_sync(0xffffffffu, rs0, 2);
        rs1 += __shfl_xor_sync(0xffffffffu, rs1, 1);
        rs1 += __shfl_xor_sync(0xffffffffu, rs1, 2);
        l0 = l0 * f0 + rs0;
        l1 = l1 * f1 + rs1;

        #pragma unroll
        for (int ni = 0; ni < 8; ni++) {
            o[ni][0] *= f0; o[ni][1] *= f0;
            o[ni][2] *= f1; o[ni][3] *= f1;
        }
        __syncwarp();

        #pragma unroll
        for (int kc = 0; kc < 4; kc++) {
            unsigned a0 = Pwu[gid * PQ + kc*8 + tig];
            unsigned a1 = Pwu[(gid + 8) * PQ + kc*8 + tig];
            unsigned a2 = Pwu[gid * PQ + kc*8 + tig + 4];
            unsigned a3 = Pwu[(gid + 8) * PQ + kc*8 + tig + 4];
            #pragma unroll
            for (int ni = 0; ni < 8; ni++) {
                int n = ni * 8 + gid;
                unsigned b0 = Vb[(kc*8 + tig) * PVV + n];
                unsigned b1 = Vb[(kc*8 + tig + 4) * PVV + n];
                mma_tf32(o[ni][0], o[ni][1], o[ni][2], o[ni][3],
                         a0, a1, a2, a3, b0, b1);
            }
        }
        __syncwarp();
    }

    float i0 = 1.0f / l0, i1 = 1.0f / l1;
    __half2* c0row = (__half2*)(ctx + (size_t)(b * SS + row0 + m0r) * EE + h * DD);
    __half2* c1row = (__half2*)(ctx + (size_t)(b * SS + row0 + m0r + 8) * EE + h * DD);
    #pragma unroll
    for (int ni = 0; ni < 8; ni++) {
        int c2 = (ni * 8 + tig * 2) / 2;
        c0row[c2] = __floats2half2_rn(o[ni][0] * i0, o[ni][1] * i0);
        c1row[c2] = __floats2half2_rn(o[ni][2] * i1, o[ni][3] * i1);
    }
}

// ---------------- launch ------------------------------------------------------------
extern "C" void kernel_launch(void* const* d_in, const int* in_sizes, int n_in,
                              void* d_out, int out_size) {
    (void)in_sizes; (void)n_in; (void)out_size;
    const float* x     = (const float*)d_in[0];
    const float* ln1_g = (const float*)d_in[1];
    const float* ln1_b = (const float*)d_in[2];
    const float* wq    = (const float*)d_in[3];
    const float* bq    = (const float*)d_in[4];
    const float* wk    = (const float*)d_in[5];
    const float* bk    = (const float*)d_in[6];
    const float* wv    = (const float*)d_in[7];
    const float* bv    = (const float*)d_in[8];
    const float* wo    = (const float*)d_in[9];
    const float* bo    = (const float*)d_in[10];
    const float* w1    = (const float*)d_in[11];
    const float* b1    = (const float*)d_in[12];
    const float* w2    = (const float*)d_in[13];
    const float* b2    = (const float*)d_in[14];
    const float* ln2_g = (const float*)d_in[15];
    const float* ln2_b = (const float*)d_in[16];
    float* out = (float*)d_out;

    __half *y, *ctx, *z, *hbuf;
    float *q, *k, *v, *y2;
    __half *wtq, *wtk, *wtv, *wto, *wt1, *wt2;
    cudaGetSymbolAddress((void**)&y,    g_y);
    cudaGetSymbolAddress((void**)&q,    g_q);
    cudaGetSymbolAddress((void**)&k,    g_k);
    cudaGetSymbolAddress((void**)&v,    g_v);
    cudaGetSymbolAddress((void**)&ctx,  g_ctx);
    cudaGetSymbolAddress((void**)&y2,   g_y2);
    cudaGetSymbolAddress((void**)&z,    g_z);
    cudaGetSymbolAddress((void**)&hbuf, g_h);
    cudaGetSymbolAddress((void**)&wtq,  g_wtq);
    cudaGetSymbolAddress((void**)&wtk,  g_wtk);
    cudaGetSymbolAddress((void**)&wtv,  g_wtv);
    cudaGetSymbolAddress((void**)&wto,  g_wto);
    cudaGetSymbolAddress((void**)&wt1,  g_wt1);
    cudaGetSymbolAddress((void**)&wt2,  g_wt2);

    static bool attr_done = false;
    if (!attr_done) {
        cudaFuncSetAttribute((const void*)mmh_tc<false,true,false>,
                             cudaFuncAttributeMaxDynamicSharedMemorySize, SM_MMH);
        cudaFuncSetAttribute((const void*)mmh_tc<true,false,true>,
                             cudaFuncAttributeMaxDynamicSharedMemorySize, SM_MMH);
        cudaFuncSetAttribute((const void*)qkvh_tc,
                             cudaFuncAttributeMaxDynamicSharedMemorySize, SM_MMH);
        cudaFuncSetAttribute((const void*)flash_tc,
                             cudaFuncAttributeMaxDynamicSharedMemorySize, SM_FLASH);
        attr_done = true;
    }

    dim3 blk128(128);
    dim3 blk256(256);
    dim3 tb(32, 8);

    // 0. convert+transpose weights to half [N][K]
    cvt_t<<<dim3(EE/32, EE/32), tb>>>(wq, wtq, EE, EE);
    cvt_t<<<dim3(EE/32, EE/32), tb>>>(wk, wtk, EE, EE);
    cvt_t<<<dim3(EE/32, EE/32), tb>>>(wv, wtv, EE, EE);
    cvt_t<<<dim3(EE/32, EE/32), tb>>>(wo, wto, EE, EE);
    cvt_t<<<dim3(FF/32, EE/32), tb>>>(w1, wt1, EE, FF);
    cvt_t<<<dim3(EE/32, FF/32), tb>>>(w2, wt2, FF, EE);

    // 1. y = LN1(x)  (half out)
    ln_kernel<<<MM, blk256>>>(x, ln1_g, ln1_b, y);

    // 2. fused q,k,v projections (fp16 MMA, fp32 out)
    dim3 g_qkv(EE / 128, MM / 64, 3);
    qkvh_tc<<<g_qkv, blk128, SM_MMH>>>(y, wtq, bq, q, wtk, bk, k, wtv, bv, v);

    // 3. flash attention (tf32; half ctx out)
    dim3 g_fl(SS / FM, BH);
    flash_tc<<<g_fl, blk256, SM_FLASH>>>(q, k, v, ctx);

    // 4. y2 = x + ctx @ wo + bo   (fp16 MMA, fp32 out)
    dim3 g_e(EE / 128, MM / 64);
    mmh_tc<false, true, false><<<g_e, blk128, SM_MMH>>>(ctx, wto, bo, x, y2, EE, EE);

    // 5. z = LN2(y2)  (half out)
    ln_kernel<<<MM, blk256>>>(y2, ln2_g, ln2_b, z);

    // 6. h = gelu(z @ w1 + b1)   (fp16 MMA, half out)
    dim3 g_ff(FF / 128, MM / 64);
    mmh_tc<true, false, true><<<g_ff, blk128, SM_MMH>>>(z, wt1, b1, nullptr, hbuf, FF, EE);

    // 7. out = y2 + h @ w2 + b2  (fp16 MMA, fp32 out)
    mmh_tc<false, true, false><<<g_e, blk128, SM_MMH>>>(hbuf, wt2, b2, y2, out, EE, FF);
}

// round 13
// speedup vs baseline: 57.2846x; 1.2213x over previous
#include <cuda_runtime.h>
#include <cuda_fp16.h>
#include <math.h>

#define BB 2
#define SS 2048
#define EE 768
#define HH 12
#define DD 64
#define MM (BB*SS)      /* 4096 rows */
#define FF (4*EE)       /* 3072 */
#define BH (BB*HH)      /* 24 */

#define BK 32           /* k halves per GEMM slab */
#define PAW 20          /* GEMM [row][k] pitch in half2 words */

/* flash (fp16) tiles */
#define FM 128          /* q rows per CTA */
#define FK 64           /* keys per iteration */
#define PQW 36          /* [row][k] pitch in half2 words: 32 data + 4 pad */
#define FSTG 3

// dynamic smem sizes (bytes)
#define SM_MMH   (2*(64*PAW + 128*PAW)*4)                  /* 30720 */
#define SM_FLASH ((128*PQW + FSTG*FK*PQW + FSTG*FK*PQW)*4) /* 73728 */

// ---------------- scratch (device globals; no allocation allowed) ----------------
__device__ __half g_y  [MM*EE];      /* LN1 out */
__device__ __half g_q  [MM*EE];
__device__ __half g_k  [MM*EE];
__device__ __half g_v  [MM*EE];
__device__ __half g_vt [BH*DD*SS];   /* V transposed per head: [bh][d][s] */
__device__ __half g_ctx[MM*EE];
__device__ float  g_y2 [MM*EE];
__device__ __half g_z  [MM*EE];
__device__ __half g_h  [MM*FF];
/* converted + transposed weights: [N][K] halves */
__device__ __half g_wtq[EE*EE];
__device__ __half g_wtk[EE*EE];
__device__ __half g_wtv[EE*EE];
__device__ __half g_wto[EE*EE];
__device__ __half g_wt1[FF*EE];
__device__ __half g_wt2[EE*FF];

// ---------------- helpers ---------------------------------------------------------
__device__ __forceinline__ void mma_f16(float& c0, float& c1, float& c2, float& c3,
                                        unsigned a0, unsigned a1, unsigned a2, unsigned a3,
                                        unsigned b0, unsigned b1) {
    asm volatile(
        "mma.sync.aligned.m16n8k16.row.col.f32.f16.f16.f32 "
        "{%0,%1,%2,%3}, {%4,%5,%6,%7}, {%8,%9}, {%0,%1,%2,%3};"
        : "+f"(c0), "+f"(c1), "+f"(c2), "+f"(c3)
        : "r"(a0), "r"(a1), "r"(a2), "r"(a3), "r"(b0), "r"(b1));
}

__device__ __forceinline__ void cp16(unsigned saddr, const void* g) {
    asm volatile("cp.async.cg.shared.global [%0], [%1], 16;" :: "r"(saddr), "l"(g));
}
__device__ __forceinline__ void cp_commit() { asm volatile("cp.async.commit_group;"); }
__device__ __forceinline__ void cp_wait0()  { asm volatile("cp.async.wait_group 0;"); }
__device__ __forceinline__ void cp_wait1()  { asm volatile("cp.async.wait_group 1;"); }
__device__ __forceinline__ void cp_wait2()  { asm volatile("cp.async.wait_group 2;"); }

// ---------------- weight convert + transpose --------------------------------------
__global__ void cvt_t(const float* __restrict__ src, __half* __restrict__ dst,
                      int R, int C) {
    __shared__ float t[32][33];
    int bx = blockIdx.x * 32;
    int by = blockIdx.y * 32;
    int x = threadIdx.x, y0 = threadIdx.y;
    #pragma unroll
    for (int i = 0; i < 32; i += 8)
        t[y0 + i][x] = src[(size_t)(by + y0 + i) * C + bx + x];
    __syncthreads();
    #pragma unroll
    for (int i = 0; i < 32; i += 8)
        dst[(size_t)(bx + y0 + i) * R + by + x] = __float2half(t[x][y0 + i]);
}

// batched square (EE x EE) convert+transpose: z selects which weight
__global__ void cvt_t4(const float* __restrict__ s0, __half* __restrict__ d0,
                       const float* __restrict__ s1, __half* __restrict__ d1,
                       const float* __restrict__ s2, __half* __restrict__ d2,
                       const float* __restrict__ s3, __half* __restrict__ d3) {
    __shared__ float t[32][33];
    const float* src; __half* dst;
    if (blockIdx.z == 0)      { src = s0; dst = d0; }
    else if (blockIdx.z == 1) { src = s1; dst = d1; }
    else if (blockIdx.z == 2) { src = s2; dst = d2; }
    else                      { src = s3; dst = d3; }
    int bx = blockIdx.x * 32;
    int by = blockIdx.y * 32;
    int x = threadIdx.x, y0 = threadIdx.y;
    #pragma unroll
    for (int i = 0; i < 32; i += 8)
        t[y0 + i][x] = src[(size_t)(by + y0 + i) * EE + bx + x];
    __syncthreads();
    #pragma unroll
    for (int i = 0; i < 32; i += 8)
        dst[(size_t)(bx + y0 + i) * EE + by + x] = __float2half(t[x][y0 + i]);
}

// ---------------- V transpose per head: vt[bh][d][s] = v[b][s][h*64+d] ------------
__global__ void vtrans(const __half* __restrict__ v, __half* __restrict__ vt) {
    __shared__ __half t[32][33];
    int bh = blockIdx.z;
    int b = bh / HH, h = bh % HH;
    int s0 = blockIdx.x * 32;
    int d0 = blockIdx.y * 32;
    int x = threadIdx.x, y0 = threadIdx.y;
    #pragma unroll
    for (int i = 0; i < 32; i += 8)
        t[y0 + i][x] = v[(size_t)(b * SS + s0 + y0 + i) * EE + h * DD + d0 + x];
    __syncthreads();
    #pragma unroll
    for (int i = 0; i < 32; i += 8)
        vt[(size_t)bh * DD * SS + (size_t)(d0 + y0 + i) * SS + s0 + x] = t[x][y0 + i];
}

// ---------------- LayerNorm (fp32 in, half out) ------------------------------------
__global__ void ln_kernel(const float* __restrict__ x, const float* __restrict__ gw,
                          const float* __restrict__ bw, __half* __restrict__ out) {
    int row = blockIdx.x;
    int t = threadIdx.x;
    const float* xr = x + (size_t)row * EE;
    float v0 = xr[t], v1 = xr[t + 256], v2 = xr[t + 512];
    __shared__ float red[256];
    red[t] = v0 + v1 + v2;
    __syncthreads();
    #pragma unroll
    for (int o = 128; o > 0; o >>= 1) {
        if (t < o) red[t] += red[t + o];
        __syncthreads();
    }
    float mean = red[0] * (1.0f / EE);
    __syncthreads();
    float d0 = v0 - mean, d1 = v1 - mean, d2 = v2 - mean;
    red[t] = d0*d0 + d1*d1 + d2*d2;
    __syncthreads();
    #pragma unroll
    for (int o = 128; o > 0; o >>= 1) {
        if (t < o) red[t] += red[t + o];
        __syncthreads();
    }
    float rstd = rsqrtf(red[0] * (1.0f / EE) + 1e-5f);
    __half* orow = out + (size_t)row * EE;
    orow[t]       = __float2half(d0 * rstd * gw[t]       + bw[t]);
    orow[t + 256] = __float2half(d1 * rstd * gw[t + 256] + bw[t + 256]);
    orow[t + 512] = __float2half(d2 * rstd * gw[t + 512] + bw[t + 512]);
}

// ---------------- fp16 GEMM core 64x128 CTA, 4 warps (2x2), warp tile 32x64 -------
template<bool GELU, bool RES, bool OUTH>
__device__ __forceinline__ void
mmh_body(const __half* __restrict__ A, const __half* __restrict__ Wt,
         const float* __restrict__ bias, const float* __restrict__ res,
         void* __restrict__ Cv, int N, int K, int row0, int col0, char* smem) {
    unsigned* As_ = (unsigned*)smem;                  // [2][64][PAW]
    unsigned* Bs_ = As_ + 2 * 64 * PAW;               // [2][128][PAW]
    unsigned sA = (unsigned)__cvta_generic_to_shared(As_);
    unsigned sB = (unsigned)__cvta_generic_to_shared(Bs_);

    int tid  = threadIdx.x;
    int warp = tid >> 5, lane = tid & 31;
    int gid  = lane >> 2, tig = lane & 3;
    int wm   = warp & 1;
    int wn   = warp >> 1;

    float acc[2][8][4];
    #pragma unroll
    for (int i = 0; i < 2; i++)
        #pragma unroll
        for (int j = 0; j < 8; j++)
            #pragma unroll
            for (int r = 0; r < 4; r++) acc[i][j][r] = 0.0f;

    int NIT = K / BK;

    auto load_st = [&](int st, int k0) {
        #pragma unroll
        for (int i = 0; i < 2; i++) {
            int slot = tid + i * 128;
            int r = slot >> 2, cw = (slot & 3) * 4;
            cp16(sA + (unsigned)((st*64 + r)*PAW + cw)*4,
                 A + (size_t)(row0 + r) * K + k0 + (slot & 3) * 8);
        }
        #pragma unroll
        for (int i = 0; i < 4; i++) {
            int slot = tid + i * 128;
            int r = slot >> 2, cw = (slot & 3) * 4;
            cp16(sB + (unsigned)((st*128 + r)*PAW + cw)*4,
                 Wt + (size_t)(col0 + r) * K + k0 + (slot & 3) * 8);
        }
        cp_commit();
    };

    load_st(0, 0);

    for (int it = 0; it < NIT; it++) {
        cp_wait0();
        __syncthreads();

        if (it + 1 < NIT) load_st((it + 1) & 1, (it + 1) * BK);

        int buf = it & 1;
        const unsigned* Ab = As_ + buf * 64 * PAW;
        const unsigned* Bb = Bs_ + buf * 128 * PAW;

        #pragma unroll
        for (int kk2 = 0; kk2 < 2; kk2++) {
            int kw = kk2 * 8;
            unsigned af[2][4], bf[8][2];
            #pragma unroll
            for (int mi = 0; mi < 2; mi++) {
                int m = wm * 32 + mi * 16 + gid;
                af[mi][0] = Ab[m * PAW + kw + tig];
                af[mi][1] = Ab[(m + 8) * PAW + kw + tig];
                af[mi][2] = Ab[m * PAW + kw + tig + 4];
                af[mi][3] = Ab[(m + 8) * PAW + kw + tig + 4];
            }
            #pragma unroll
            for (int ni = 0; ni < 8; ni++) {
                int n = wn * 64 + ni * 8 + gid;
                bf[ni][0] = Bb[n * PAW + kw + tig];
                bf[ni][1] = Bb[n * PAW + kw + tig + 4];
            }
            #pragma unroll
            for (int mi = 0; mi < 2; mi++)
                #pragma unroll
                for (int ni = 0; ni < 8; ni++)
                    mma_f16(acc[mi][ni][0], acc[mi][ni][1], acc[mi][ni][2], acc[mi][ni][3],
                            af[mi][0], af[mi][1], af[mi][2], af[mi][3],
                            bf[ni][0], bf[ni][1]);
        }
    }

    #pragma unroll
    for (int mi = 0; mi < 2; mi++) {
        int r0 = row0 + wm * 32 + mi * 16 + gid;
        int r1 = r0 + 8;
        #pragma unroll
        for (int ni = 0; ni < 8; ni++) {
            int c = col0 + wn * 64 + ni * 8 + tig * 2;
            float2 b2 = *(const float2*)(bias + c);
            float v00 = acc[mi][ni][0] + b2.x;
            float v01 = acc[mi][ni][1] + b2.y;
            float v10 = acc[mi][ni][2] + b2.x;
            float v11 = acc[mi][ni][3] + b2.y;
            if (RES) {
                float2 e0 = *(const float2*)(res + (size_t)r0 * N + c);
                float2 e1 = *(const float2*)(res + (size_t)r1 * N + c);
                v00 += e0.x; v01 += e0.y; v10 += e1.x; v11 += e1.y;
            }
            if (GELU) {
                v00 = v00 * 0.5f * (1.0f + erff(v00 * 0.70710678118654752f));
                v01 = v01 * 0.5f * (1.0f + erff(v01 * 0.70710678118654752f));
                v10 = v10 * 0.5f * (1.0f + erff(v10 * 0.70710678118654752f));
                v11 = v11 * 0.5f * (1.0f + erff(v11 * 0.70710678118654752f));
            }
            if (OUTH) {
                __half2* C = (__half2*)Cv;
                C[((size_t)r0 * N + c) / 2] = __floats2half2_rn(v00, v01);
                C[((size_t)r1 * N + c) / 2] = __floats2half2_rn(v10, v11);
            } else {
                float* C = (float*)Cv;
                *(float2*)(C + (size_t)r0 * N + c) = make_float2(v00, v01);
                *(float2*)(C + (size_t)r1 * N + c) = make_float2(v10, v11);
            }
        }
    }
}

template<bool GELU, bool RES, bool OUTH>
__global__ void __launch_bounds__(128, 3)
mmh_tc(const __half* __restrict__ A, const __half* __restrict__ Wt,
       const float* __restrict__ bias, const float* __restrict__ res,
       void* __restrict__ C, int N, int K) {
    extern __shared__ char smem[];
    mmh_body<GELU, RES, OUTH>(A, Wt, bias, res, C, N, K,
                              blockIdx.y * 64, blockIdx.x * 128, smem);
}

__global__ void __launch_bounds__(128, 3)
qkvh_tc(const __half* __restrict__ y,
        const __half* __restrict__ wtq, const float* __restrict__ bq, __half* __restrict__ q,
        const __half* __restrict__ wtk, const float* __restrict__ bk, __half* __restrict__ k,
        const __half* __restrict__ wtv, const float* __restrict__ bv, __half* __restrict__ v) {
    extern __shared__ char smem[];
    const __half* Wt; const float* bias; __half* C;
    if (blockIdx.z == 0)      { Wt = wtq; bias = bq; C = q; }
    else if (blockIdx.z == 1) { Wt = wtk; bias = bk; C = k; }
    else                      { Wt = wtv; bias = bv; C = v; }
    mmh_body<false, false, true>(y, Wt, bias, nullptr, C, EE, EE,
                                 blockIdx.y * 64, blockIdx.x * 128, smem);
}

// ---------------- Flash attention, fp16 MMA throughout -----------------------------
// Q [m][k] half, K [n][k] half, Vt [n=d][k=key] half. P half in smem (reuses Q rows).
__global__ void __launch_bounds__(256, 2)
flash_h(const __half* __restrict__ q, const __half* __restrict__ k,
        const __half* __restrict__ vt, __half* __restrict__ ctx) {
    extern __shared__ char smem[];
    unsigned* Qw = (unsigned*)smem;                  // [128][PQW]
    unsigned* Kw = Qw + 128 * PQW;                   // [FSTG][FK][PQW]
    unsigned* Vw = Kw + FSTG * FK * PQW;             // [FSTG][DD][PQW] (keys in words)
    unsigned sQ = (unsigned)__cvta_generic_to_shared(Qw);
    unsigned sK = (unsigned)__cvta_generic_to_shared(Kw);
    unsigned sV = (unsigned)__cvta_generic_to_shared(Vw);

    int bh = blockIdx.y;
    int b = bh / HH, h = bh % HH;
    int row0 = blockIdx.x * FM;
    const __half* qb  = q  + (size_t)b * SS * EE + h * DD;
    const __half* kb  = k  + (size_t)b * SS * EE + h * DD;
    const __half* vtb = vt + (size_t)bh * DD * SS;

    int tid  = threadIdx.x;
    int warp = tid >> 5, lane = tid & 31;
    int gid  = lane >> 2, tig = lane & 3;

    // Q tile: 128 rows x 8 cp16-chunks = 1024 slots, 4/thread
    #pragma unroll
    for (int i = 0; i < 4; i++) {
        int slot = tid + i * 256;
        int r = slot >> 3, cw = (slot & 7) * 4;
        cp16(sQ + (unsigned)(r * PQW + cw) * 4, qb + (size_t)(row0 + r) * EE + (slot & 7) * 8);
    }
    cp_commit();

    auto load_kv = [&](int st, int k0) {
        // K: 64 key-rows x 8 chunks = 512 slots, 2/thread
        #pragma unroll
        for (int i = 0; i < 2; i++) {
            int slot = tid + i * 256;
            int r = slot >> 3, cw = (slot & 7) * 4;
            cp16(sK + (unsigned)((st*FK + r) * PQW + cw) * 4,
                 kb + (size_t)(k0 + r) * EE + (slot & 7) * 8);
        }
        // Vt: 64 d-rows x 8 chunks (64 keys) = 512 slots, 2/thread
        #pragma unroll
        for (int i = 0; i < 2; i++) {
            int slot = tid + i * 256;
            int r = slot >> 3, cw = (slot & 7) * 4;
            cp16(sV + (unsigned)((st*DD + r) * PQW + cw) * 4,
                 vtb + (size_t)r * SS + k0 + (slot & 7) * 8);
        }
        cp_commit();
    };
    load_kv(0, 0);
    load_kv(1, FK);

    cp_wait2();          // Q ready
    __syncthreads();

    // preload Q fragments (4 k16 groups x 4 regs)
    int m0r = warp * 16 + gid;
    unsigned qf[4][4];
    #pragma unroll
    for (int kc = 0; kc < 4; kc++) {
        qf[kc][0] = Qw[m0r * PQW + kc*8 + tig];
        qf[kc][1] = Qw[(m0r + 8) * PQW + kc*8 + tig];
        qf[kc][2] = Qw[m0r * PQW + kc*8 + tig + 4];
        qf[kc][3] = Qw[(m0r + 8) * PQW + kc*8 + tig + 4];
    }
    __syncwarp();

    unsigned* Pw = Qw + (warp * 16) * PQW;     // warp-private P strip [16][PQW] words

    float o[8][4];
    #pragma unroll
    for (int ni = 0; ni < 8; ni++)
        #pragma unroll
        for (int r = 0; r < 4; r++) o[ni][r] = 0.0f;
    float mx0 = -1e30f, mx1 = -1e30f, l0 = 0.0f, l1 = 0.0f;
    const float scale = rsqrtf((float)EE);

    const int NIT = SS / FK;   // 32
    for (int it = 0; it < NIT; it++) {
        if (it >= NIT - 2) cp_wait0(); else cp_wait1();
        __syncthreads();
        if (it + 2 < NIT) load_kv((it + 2) % FSTG, (it + 2) * FK);

        int buf = it % FSTG;
        const unsigned* Kb = Kw + buf * FK * PQW;
        const unsigned* Vb = Vw + buf * DD * PQW;

        // ---- S = Q K^T (16 x 64 per warp, fp16 k16) ----
        float s[8][4];
        #pragma unroll
        for (int ni = 0; ni < 8; ni++)
            #pragma unroll
            for (int r = 0; r < 4; r++) s[ni][r] = 0.0f;

        #pragma unroll
        for (int kc = 0; kc < 4; kc++) {
            #pragma unroll
            for (int ni = 0; ni < 8; ni++) {
                int n = ni * 8 + gid;
                unsigned b0 = Kb[n * PQW + kc*8 + tig];
                unsigned b1 = Kb[n * PQW + kc*8 + tig + 4];
                mma_f16(s[ni][0], s[ni][1], s[ni][2], s[ni][3],
                        qf[kc][0], qf[kc][1], qf[kc][2], qf[kc][3], b0, b1);
            }
        }

        // ---- online softmax ----
        float rm0 = -1e30f, rm1 = -1e30f;
        #pragma unroll
        for (int ni = 0; ni < 8; ni++) {
            s[ni][0] *= scale; s[ni][1] *= scale;
            s[ni][2] *= scale; s[ni][3] *= scale;
            rm0 = fmaxf(rm0, fmaxf(s[ni][0], s[ni][1]));
            rm1 = fmaxf(rm1, fmaxf(s[ni][2], s[ni][3]));
        }
        rm0 = fmaxf(rm0, __shfl_xor_sync(0xffffffffu, rm0, 1));
        rm0 = fmaxf(rm0, __shfl_xor_sync(0xffffffffu, rm0, 2));
        rm1 = fmaxf(rm1, __shfl_xor_sync(0xffffffffu, rm1, 1));
        rm1 = fmaxf(rm1, __shfl_xor_sync(0xffffffffu, rm1, 2));

        float mn0 = fmaxf(mx0, rm0), mn1 = fmaxf(mx1, rm1);
        float f0 = __expf(mx0 - mn0), f1 = __expf(mx1 - mn1);
        mx0 = mn0; mx1 = mn1;

        float rs0 = 0.0f, rs1 = 0.0f;
        #pragma unroll
        for (int ni = 0; ni < 8; ni++) {
            float p0 = __expf(s[ni][0] - mn0);
            float p1 = __expf(s[ni][1] - mn0);
            float p2 = __expf(s[ni][2] - mn1);
            float p3 = __expf(s[ni][3] - mn1);
            rs0 += p0 + p1; rs1 += p2 + p3;
            __half2 h0 = __floats2half2_rn(p0, p1);
            __half2 h1 = __floats2half2_rn(p2, p3);
            Pw[gid * PQW + ni*4 + tig]       = *(unsigned*)&h0;
            Pw[(gid + 8) * PQW + ni*4 + tig] = *(unsigned*)&h1;
        }
        rs0 += __shfl_xor_sync(0xffffffffu, rs0, 1);
        rs0 += __shfl_xor_sync(0xffffffffu, rs0, 2);
        rs1 += __shfl_xor_sync(0xffffffffu, rs1, 1);
        rs1 += __shfl_xor_sync(0xffffffffu, rs1, 2);
        l0 = l0 * f0 + rs0;
        l1 = l1 * f1 + rs1;

        #pragma unroll
        for (int ni = 0; ni < 8; ni++) {
            o[ni][0] *= f0; o[ni][1] *= f0;
            o[ni][2] *= f1; o[ni][3] *= f1;
        }
        __syncwarp();

        // ---- O += P V (16 x 64 per warp, k=64 keys, fp16) ----
        #pragma unroll
        for (int kc = 0; kc < 4; kc++) {
            unsigned a0 = Pw[gid * PQW + kc*8 + tig];
            unsigned a1 = Pw[(gid + 8) * PQW + kc*8 + tig];
            unsigned a2 = Pw[gid * PQW + kc*8 + tig + 4];
            unsigned a3 = Pw[(gid + 8) * PQW + kc*8 + tig + 4];
            #pragma unroll
            for (int ni = 0; ni < 8; ni++) {
                int n = ni * 8 + gid;
                unsigned b0 = Vb[n * PQW + kc*8 + tig];
                unsigned b1 = Vb[n * PQW + kc*8 + tig + 4];
                mma_f16(o[ni][0], o[ni][1], o[ni][2], o[ni][3],
                        a0, a1, a2, a3, b0, b1);
            }
        }
        __syncwarp();
    }

    float i0 = 1.0f / l0, i1 = 1.0f / l1;
    __half2* c0row = (__half2*)(ctx + (size_t)(b * SS + row0 + m0r) * EE + h * DD);
    __half2* c1row = (__half2*)(ctx + (size_t)(b * SS + row0 + m0r + 8) * EE + h * DD);
    #pragma unroll
    for (int ni = 0; ni < 8; ni++) {
        int c2 = (ni * 8 + tig * 2) / 2;
        c0row[c2] = __floats2half2_rn(o[ni][0] * i0, o[ni][1] * i0);
        c1row[c2] = __floats2half2_rn(o[ni][2] * i1, o[ni][3] * i1);
    }
}

// ---------------- launch ------------------------------------------------------------
extern "C" void kernel_launch(void* const* d_in, const int* in_sizes, int n_in,
                              void* d_out, int out_size) {
    (void)in_sizes; (void)n_in; (void)out_size;
    const float* x     = (const float*)d_in[0];
    const float* ln1_g = (const float*)d_in[1];
    const float* ln1_b = (const float*)d_in[2];
    const float* wq    = (const float*)d_in[3];
    const float* bq    = (const float*)d_in[4];
    const float* wk    = (const float*)d_in[5];
    const float* bk    = (const float*)d_in[6];
    const float* wv    = (const float*)d_in[7];
    const float* bv    = (const float*)d_in[8];
    const float* wo    = (const float*)d_in[9];
    const float* bo    = (const float*)d_in[10];
    const float* w1    = (const float*)d_in[11];
    const float* b1    = (const float*)d_in[12];
    const float* w2    = (const float*)d_in[13];
    const float* b2    = (const float*)d_in[14];
    const float* ln2_g = (const float*)d_in[15];
    const float* ln2_b = (const float*)d_in[16];
    float* out = (float*)d_out;

    __half *y, *q, *k, *v, *vt, *ctx, *z, *hbuf;
    float *y2;
    __half *wtq, *wtk, *wtv, *wto, *wt1, *wt2;
    cudaGetSymbolAddress((void**)&y,    g_y);
    cudaGetSymbolAddress((void**)&q,    g_q);
    cudaGetSymbolAddress((void**)&k,    g_k);
    cudaGetSymbolAddress((void**)&v,    g_v);
    cudaGetSymbolAddress((void**)&vt,   g_vt);
    cudaGetSymbolAddress((void**)&ctx,  g_ctx);
    cudaGetSymbolAddress((void**)&y2,   g_y2);
    cudaGetSymbolAddress((void**)&z,    g_z);
    cudaGetSymbolAddress((void**)&hbuf, g_h);
    cudaGetSymbolAddress((void**)&wtq,  g_wtq);
    cudaGetSymbolAddress((void**)&wtk,  g_wtk);
    cudaGetSymbolAddress((void**)&wtv,  g_wtv);
    cudaGetSymbolAddress((void**)&wto,  g_wto);
    cudaGetSymbolAddress((void**)&wt1,  g_wt1);
    cudaGetSymbolAddress((void**)&wt2,  g_wt2);

    static bool attr_done = false;
    if (!attr_done) {
        cudaFuncSetAttribute((const void*)mmh_tc<false,true,false>,
                             cudaFuncAttributeMaxDynamicSharedMemorySize, SM_MMH);
        cudaFuncSetAttribute((const void*)mmh_tc<true,false,true>,
                             cudaFuncAttributeMaxDynamicSharedMemorySize, SM_MMH);
        cudaFuncSetAttribute((const void*)qkvh_tc,
                             cudaFuncAttributeMaxDynamicSharedMemorySize, SM_MMH);
        cudaFuncSetAttribute((const void*)flash_h,
                             cudaFuncAttributeMaxDynamicSharedMemorySize, SM_FLASH);
        attr_done = true;
    }

    dim3 blk128(128);
    dim3 blk256(256);
    dim3 tb(32, 8);

    // 0. convert+transpose weights to half [N][K]
    cvt_t4<<<dim3(EE/32, EE/32, 4), tb>>>(wq, wtq, wk, wtk, wv, wtv, wo, wto);
    cvt_t<<<dim3(FF/32, EE/32), tb>>>(w1, wt1, EE, FF);
    cvt_t<<<dim3(EE/32, FF/32), tb>>>(w2, wt2, FF, EE);

    // 1. y = LN1(x)
    ln_kernel<<<MM, blk256>>>(x, ln1_g, ln1_b, y);

    // 2. q,k,v projections (fp16 MMA, half out)
    dim3 g_qkv(EE / 128, MM / 64, 3);
    qkvh_tc<<<g_qkv, blk128, SM_MMH>>>(y, wtq, bq, q, wtk, bk, k, wtv, bv, v);

    // 2b. transpose V per head for the PV MMA
    vtrans<<<dim3(SS/32, DD/32, BH), tb>>>(v, vt);

    // 3. flash attention (fp16)
    dim3 g_fl(SS / FM, BH);
    flash_h<<<g_fl, blk256, SM_FLASH>>>(q, k, vt, ctx);

    // 4. y2 = x + ctx @ wo + bo
    dim3 g_e(EE / 128, MM / 64);
    mmh_tc<false, true, false><<<g_e, blk128, SM_MMH>>>(ctx, wto, bo, x, y2, EE, EE);

    // 5. z = LN2(y2)
    ln_kernel<<<MM, blk256>>>(y2, ln2_g, ln2_b, z);

    // 6. h = gelu(z @ w1 + b1)
    dim3 g_ff(FF / 128, MM / 64);
    mmh_tc<true, false, true><<<g_ff, blk128, SM_MMH>>>(z, wt1, b1, nullptr, hbuf, FF, EE);

    // 7. out = y2 + h @ w2 + b2
    mmh_tc<false, true, false><<<g_e, blk128, SM_MMH>>>(hbuf, wt2, b2, y2, out, EE, FF);
}

// round 14
// speedup vs baseline: 63.4406x; 1.1075x over previous
#include <cuda_runtime.h>
#include <cuda_fp16.h>
#include <math.h>

#define BB 2
#define SS 2048
#define EE 768
#define HH 12
#define DD 64
#define MM (BB*SS)      /* 4096 rows */
#define FF (4*EE)       /* 3072 */
#define BH (BB*HH)      /* 24 */

#define BK 64           /* k halves per GEMM slab */
#define PAW 36          /* GEMM [row][k] pitch in half2 words: 32 data + 4 pad */

/* flash (fp16) tiles */
#define FM 128
#define FK 64
#define PQW 36
#define FSTG 3

// dynamic smem sizes (bytes)
#define SM_MMH   (2*(64*PAW + 128*PAW)*4)                  /* 55296 */
#define SM_FLASH ((128*PQW + FSTG*FK*PQW + FSTG*FK*PQW)*4) /* 73728 */

// ---------------- scratch (device globals; no allocation allowed) ----------------
__device__ __half g_y  [MM*EE];
__device__ __half g_q  [MM*EE];
__device__ __half g_k  [MM*EE];
__device__ __half g_v  [MM*EE];
__device__ __half g_vt [BH*DD*SS];
__device__ __half g_ctx[MM*EE];
__device__ float  g_y2 [MM*EE];
__device__ __half g_z  [MM*EE];
__device__ __half g_h  [MM*FF];
__device__ __half g_wtq[EE*EE];
__device__ __half g_wtk[EE*EE];
__device__ __half g_wtv[EE*EE];
__device__ __half g_wto[EE*EE];
__device__ __half g_wt1[FF*EE];
__device__ __half g_wt2[EE*FF];

// ---------------- helpers ---------------------------------------------------------
__device__ __forceinline__ void mma_f16(float& c0, float& c1, float& c2, float& c3,
                                        unsigned a0, unsigned a1, unsigned a2, unsigned a3,
                                        unsigned b0, unsigned b1) {
    asm volatile(
        "mma.sync.aligned.m16n8k16.row.col.f32.f16.f16.f32 "
        "{%0,%1,%2,%3}, {%4,%5,%6,%7}, {%8,%9}, {%0,%1,%2,%3};"
        : "+f"(c0), "+f"(c1), "+f"(c2), "+f"(c3)
        : "r"(a0), "r"(a1), "r"(a2), "r"(a3), "r"(b0), "r"(b1));
}

__device__ __forceinline__ void cp16(unsigned saddr, const void* g) {
    asm volatile("cp.async.cg.shared.global [%0], [%1], 16;" :: "r"(saddr), "l"(g));
}
__device__ __forceinline__ void cp_commit() { asm volatile("cp.async.commit_group;"); }
__device__ __forceinline__ void cp_wait0()  { asm volatile("cp.async.wait_group 0;"); }
__device__ __forceinline__ void cp_wait1()  { asm volatile("cp.async.wait_group 1;"); }
__device__ __forceinline__ void cp_wait2()  { asm volatile("cp.async.wait_group 2;"); }

// ---------------- weight convert + transpose --------------------------------------
__global__ void cvt_t4(const float* __restrict__ s0, __half* __restrict__ d0,
                       const float* __restrict__ s1, __half* __restrict__ d1,
                       const float* __restrict__ s2, __half* __restrict__ d2,
                       const float* __restrict__ s3, __half* __restrict__ d3) {
    __shared__ float t[32][33];
    const float* src; __half* dst;
    if (blockIdx.z == 0)      { src = s0; dst = d0; }
    else if (blockIdx.z == 1) { src = s1; dst = d1; }
    else if (blockIdx.z == 2) { src = s2; dst = d2; }
    else                      { src = s3; dst = d3; }
    int bx = blockIdx.x * 32;
    int by = blockIdx.y * 32;
    int x = threadIdx.x, y0 = threadIdx.y;
    #pragma unroll
    for (int i = 0; i < 32; i += 8)
        t[y0 + i][x] = src[(size_t)(by + y0 + i) * EE + bx + x];
    __syncthreads();
    #pragma unroll
    for (int i = 0; i < 32; i += 8)
        dst[(size_t)(bx + y0 + i) * EE + by + x] = __float2half(t[x][y0 + i]);
}

// batched FF converts: z=0 -> w1 (EE x FF), z=1 -> w2 (FF x EE)
__global__ void cvt_tff(const float* __restrict__ w1, __half* __restrict__ wt1,
                        const float* __restrict__ w2, __half* __restrict__ wt2) {
    __shared__ float t[32][33];
    const float* src; __half* dst; int R, C;
    if (blockIdx.z == 0) { src = w1; dst = wt1; R = EE; C = FF; }
    else                 { src = w2; dst = wt2; R = FF; C = EE; }
    int bx = blockIdx.x * 32;   // col in src
    int by = blockIdx.y * 32;   // row in src
    if (bx >= C || by >= R) return;
    int x = threadIdx.x, y0 = threadIdx.y;
    #pragma unroll
    for (int i = 0; i < 32; i += 8)
        t[y0 + i][x] = src[(size_t)(by + y0 + i) * C + bx + x];
    __syncthreads();
    #pragma unroll
    for (int i = 0; i < 32; i += 8)
        dst[(size_t)(bx + y0 + i) * R + by + x] = __float2half(t[x][y0 + i]);
}

// ---------------- V transpose per head: vt[bh][d][s] = v[b][s][h*64+d] ------------
__global__ void vtrans(const __half* __restrict__ v, __half* __restrict__ vt) {
    __shared__ __half t[32][33];
    int bh = blockIdx.z;
    int b = bh / HH, h = bh % HH;
    int s0 = blockIdx.x * 32;
    int d0 = blockIdx.y * 32;
    int x = threadIdx.x, y0 = threadIdx.y;
    #pragma unroll
    for (int i = 0; i < 32; i += 8)
        t[y0 + i][x] = v[(size_t)(b * SS + s0 + y0 + i) * EE + h * DD + d0 + x];
    __syncthreads();
    #pragma unroll
    for (int i = 0; i < 32; i += 8)
        vt[(size_t)bh * DD * SS + (size_t)(d0 + y0 + i) * SS + s0 + x] = t[x][y0 + i];
}

// ---------------- LayerNorm: float4 loads, single-pass sum/sumsq, shuffle reduce ---
__global__ void ln_kernel(const float* __restrict__ x, const float* __restrict__ gw,
                          const float* __restrict__ bw, __half* __restrict__ out) {
    int row = blockIdx.x;
    int t = threadIdx.x;                 // 256 threads, 192 active for data
    int warp = t >> 5, lane = t & 31;
    __shared__ float ws1[8], ws2[8], bc[2];

    float4 xv = make_float4(0.f, 0.f, 0.f, 0.f);
    if (t < 192)
        xv = *(const float4*)(x + (size_t)row * EE + t * 4);
    float s1 = xv.x + xv.y + xv.z + xv.w;
    float s2 = xv.x*xv.x + xv.y*xv.y + xv.z*xv.z + xv.w*xv.w;
    #pragma unroll
    for (int o = 16; o > 0; o >>= 1) {
        s1 += __shfl_xor_sync(0xffffffffu, s1, o);
        s2 += __shfl_xor_sync(0xffffffffu, s2, o);
    }
    if (lane == 0) { ws1[warp] = s1; ws2[warp] = s2; }
    __syncthreads();
    if (t == 0) {
        float a = 0.f, b = 0.f;
        #pragma unroll
        for (int i = 0; i < 8; i++) { a += ws1[i]; b += ws2[i]; }
        float mean = a * (1.0f / EE);
        float var  = b * (1.0f / EE) - mean * mean;
        bc[0] = mean;
        bc[1] = rsqrtf(var + 1e-5f);
    }
    __syncthreads();
    if (t < 192) {
        float mean = bc[0], rstd = bc[1];
        float4 gv = *(const float4*)(gw + t * 4);
        float4 bv = *(const float4*)(bw + t * 4);
        float o0 = (xv.x - mean) * rstd * gv.x + bv.x;
        float o1 = (xv.y - mean) * rstd * gv.y + bv.y;
        float o2 = (xv.z - mean) * rstd * gv.z + bv.z;
        float o3 = (xv.w - mean) * rstd * gv.w + bv.w;
        __half2 h0 = __floats2half2_rn(o0, o1);
        __half2 h1 = __floats2half2_rn(o2, o3);
        uint2 pk; pk.x = *(unsigned*)&h0; pk.y = *(unsigned*)&h1;
        *(uint2*)(out + (size_t)row * EE + t * 4) = pk;
    }
}

// ---------------- fp16 GEMM core 64x128 CTA, 4 warps (2x2), warp tile 32x64 -------
// BK=64 halves per slab, 4 k16 groups per slab, one barrier per slab.
template<bool GELU, bool RES, bool OUTH>
__device__ __forceinline__ void
mmh_body(const __half* __restrict__ A, const __half* __restrict__ Wt,
         const float* __restrict__ bias, const float* __restrict__ res,
         void* __restrict__ Cv, int N, int K, int row0, int col0, char* smem) {
    unsigned* As_ = (unsigned*)smem;                  // [2][64][PAW]
    unsigned* Bs_ = As_ + 2 * 64 * PAW;               // [2][128][PAW]
    unsigned sA = (unsigned)__cvta_generic_to_shared(As_);
    unsigned sB = (unsigned)__cvta_generic_to_shared(Bs_);

    int tid  = threadIdx.x;
    int warp = tid >> 5, lane = tid & 31;
    int gid  = lane >> 2, tig = lane & 3;
    int wm   = warp & 1;
    int wn   = warp >> 1;

    float acc[2][8][4];
    #pragma unroll
    for (int i = 0; i < 2; i++)
        #pragma unroll
        for (int j = 0; j < 8; j++)
            #pragma unroll
            for (int r = 0; r < 4; r++) acc[i][j][r] = 0.0f;

    int NIT = K / BK;

    auto load_st = [&](int st, int k0) {
        // A: 64 rows x 64 halves = 8 chunks/row = 512 slots, 4/thread
        #pragma unroll
        for (int i = 0; i < 4; i++) {
            int slot = tid + i * 128;
            int r = slot >> 3, c = slot & 7;
            cp16(sA + (unsigned)((st*64 + r)*PAW + c * 4)*4,
                 A + (size_t)(row0 + r) * K + k0 + c * 8);
        }
        // B: 128 rows x 64 halves = 1024 slots, 8/thread
        #pragma unroll
        for (int i = 0; i < 8; i++) {
            int slot = tid + i * 128;
            int r = slot >> 3, c = slot & 7;
            cp16(sB + (unsigned)((st*128 + r)*PAW + c * 4)*4,
                 Wt + (size_t)(col0 + r) * K + k0 + c * 8);
        }
        cp_commit();
    };

    load_st(0, 0);

    for (int it = 0; it < NIT; it++) {
        cp_wait0();
        __syncthreads();

        if (it + 1 < NIT) load_st((it + 1) & 1, (it + 1) * BK);

        int buf = it & 1;
        const unsigned* Ab = As_ + buf * 64 * PAW;
        const unsigned* Bb = Bs_ + buf * 128 * PAW;

        #pragma unroll
        for (int kk2 = 0; kk2 < 4; kk2++) {
            int kw = kk2 * 8;
            unsigned af[2][4], bf[8][2];
            #pragma unroll
            for (int mi = 0; mi < 2; mi++) {
                int m = wm * 32 + mi * 16 + gid;
                af[mi][0] = Ab[m * PAW + kw + tig];
                af[mi][1] = Ab[(m + 8) * PAW + kw + tig];
                af[mi][2] = Ab[m * PAW + kw + tig + 4];
                af[mi][3] = Ab[(m + 8) * PAW + kw + tig + 4];
            }
            #pragma unroll
            for (int ni = 0; ni < 8; ni++) {
                int n = wn * 64 + ni * 8 + gid;
                bf[ni][0] = Bb[n * PAW + kw + tig];
                bf[ni][1] = Bb[n * PAW + kw + tig + 4];
            }
            #pragma unroll
            for (int mi = 0; mi < 2; mi++)
                #pragma unroll
                for (int ni = 0; ni < 8; ni++)
                    mma_f16(acc[mi][ni][0], acc[mi][ni][1], acc[mi][ni][2], acc[mi][ni][3],
                            af[mi][0], af[mi][1], af[mi][2], af[mi][3],
                            bf[ni][0], bf[ni][1]);
        }
    }

    #pragma unroll
    for (int mi = 0; mi < 2; mi++) {
        int r0 = row0 + wm * 32 + mi * 16 + gid;
        int r1 = r0 + 8;
        #pragma unroll
        for (int ni = 0; ni < 8; ni++) {
            int c = col0 + wn * 64 + ni * 8 + tig * 2;
            float2 b2 = *(const float2*)(bias + c);
            float v00 = acc[mi][ni][0] + b2.x;
            float v01 = acc[mi][ni][1] + b2.y;
            float v10 = acc[mi][ni][2] + b2.x;
            float v11 = acc[mi][ni][3] + b2.y;
            if (RES) {
                float2 e0 = *(const float2*)(res + (size_t)r0 * N + c);
                float2 e1 = *(const float2*)(res + (size_t)r1 * N + c);
                v00 += e0.x; v01 += e0.y; v10 += e1.x; v11 += e1.y;
            }
            if (GELU) {
                v00 = v00 * 0.5f * (1.0f + erff(v00 * 0.70710678118654752f));
                v01 = v01 * 0.5f * (1.0f + erff(v01 * 0.70710678118654752f));
                v10 = v10 * 0.5f * (1.0f + erff(v10 * 0.70710678118654752f));
                v11 = v11 * 0.5f * (1.0f + erff(v11 * 0.70710678118654752f));
            }
            if (OUTH) {
                __half2* C = (__half2*)Cv;
                C[((size_t)r0 * N + c) / 2] = __floats2half2_rn(v00, v01);
                C[((size_t)r1 * N + c) / 2] = __floats2half2_rn(v10, v11);
            } else {
                float* C = (float*)Cv;
                *(float2*)(C + (size_t)r0 * N + c) = make_float2(v00, v01);
                *(float2*)(C + (size_t)r1 * N + c) = make_float2(v10, v11);
            }
        }
    }
}

template<bool GELU, bool RES, bool OUTH>
__global__ void __launch_bounds__(128, 3)
mmh_tc(const __half* __restrict__ A, const __half* __restrict__ Wt,
       const float* __restrict__ bias, const float* __restrict__ res,
       void* __restrict__ C, int N, int K) {
    extern __shared__ char smem[];
    mmh_body<GELU, RES, OUTH>(A, Wt, bias, res, C, N, K,
                              blockIdx.y * 64, blockIdx.x * 128, smem);
}

__global__ void __launch_bounds__(128, 3)
qkvh_tc(const __half* __restrict__ y,
        const __half* __restrict__ wtq, const float* __restrict__ bq, __half* __restrict__ q,
        const __half* __restrict__ wtk, const float* __restrict__ bk, __half* __restrict__ k,
        const __half* __restrict__ wtv, const float* __restrict__ bv, __half* __restrict__ v) {
    extern __shared__ char smem[];
    const __half* Wt; const float* bias; __half* C;
    if (blockIdx.z == 0)      { Wt = wtq; bias = bq; C = q; }
    else if (blockIdx.z == 1) { Wt = wtk; bias = bk; C = k; }
    else                      { Wt = wtv; bias = bv; C = v; }
    mmh_body<false, false, true>(y, Wt, bias, nullptr, C, EE, EE,
                                 blockIdx.y * 64, blockIdx.x * 128, smem);
}

// ---------------- Flash attention, fp16 MMA (unchanged from R13) -------------------
__global__ void __launch_bounds__(256, 2)
flash_h(const __half* __restrict__ q, const __half* __restrict__ k,
        const __half* __restrict__ vt, __half* __restrict__ ctx) {
    extern __shared__ char smem[];
    unsigned* Qw = (unsigned*)smem;
    unsigned* Kw = Qw + 128 * PQW;
    unsigned* Vw = Kw + FSTG * FK * PQW;
    unsigned sQ = (unsigned)__cvta_generic_to_shared(Qw);
    unsigned sK = (unsigned)__cvta_generic_to_shared(Kw);
    unsigned sV = (unsigned)__cvta_generic_to_shared(Vw);

    int bh = blockIdx.y;
    int b = bh / HH, h = bh % HH;
    int row0 = blockIdx.x * FM;
    const __half* qb  = q  + (size_t)b * SS * EE + h * DD;
    const __half* kb  = k  + (size_t)b * SS * EE + h * DD;
    const __half* vtb = vt + (size_t)bh * DD * SS;

    int tid  = threadIdx.x;
    int warp = tid >> 5, lane = tid & 31;
    int gid  = lane >> 2, tig = lane & 3;

    #pragma unroll
    for (int i = 0; i < 4; i++) {
        int slot = tid + i * 256;
        int r = slot >> 3, cw = (slot & 7) * 4;
        cp16(sQ + (unsigned)(r * PQW + cw) * 4, qb + (size_t)(row0 + r) * EE + (slot & 7) * 8);
    }
    cp_commit();

    auto load_kv = [&](int st, int k0) {
        #pragma unroll
        for (int i = 0; i < 2; i++) {
            int slot = tid + i * 256;
            int r = slot >> 3, cw = (slot & 7) * 4;
            cp16(sK + (unsigned)((st*FK + r) * PQW + cw) * 4,
                 kb + (size_t)(k0 + r) * EE + (slot & 7) * 8);
        }
        #pragma unroll
        for (int i = 0; i < 2; i++) {
            int slot = tid + i * 256;
            int r = slot >> 3, cw = (slot & 7) * 4;
            cp16(sV + (unsigned)((st*DD + r) * PQW + cw) * 4,
                 vtb + (size_t)r * SS + k0 + (slot & 7) * 8);
        }
        cp_commit();
    };
    load_kv(0, 0);
    load_kv(1, FK);

    cp_wait2();
    __syncthreads();

    int m0r = warp * 16 + gid;
    unsigned qf[4][4];
    #pragma unroll
    for (int kc = 0; kc < 4; kc++) {
        qf[kc][0] = Qw[m0r * PQW + kc*8 + tig];
        qf[kc][1] = Qw[(m0r + 8) * PQW + kc*8 + tig];
        qf[kc][2] = Qw[m0r * PQW + kc*8 + tig + 4];
        qf[kc][3] = Qw[(m0r + 8) * PQW + kc*8 + tig + 4];
    }
    __syncwarp();

    unsigned* Pw = Qw + (warp * 16) * PQW;

    float o[8][4];
    #pragma unroll
    for (int ni = 0; ni < 8; ni++)
        #pragma unroll
        for (int r = 0; r < 4; r++) o[ni][r] = 0.0f;
    float mx0 = -1e30f, mx1 = -1e30f, l0 = 0.0f, l1 = 0.0f;
    const float scale = rsqrtf((float)EE);

    const int NIT = SS / FK;   // 32
    for (int it = 0; it < NIT; it++) {
        if (it >= NIT - 2) cp_wait0(); else cp_wait1();
        __syncthreads();
        if (it + 2 < NIT) load_kv((it + 2) % FSTG, (it + 2) * FK);

        int buf = it % FSTG;
        const unsigned* Kb = Kw + buf * FK * PQW;
        const unsigned* Vb = Vw + buf * DD * PQW;

        float s[8][4];
        #pragma unroll
        for (int ni = 0; ni < 8; ni++)
            #pragma unroll
            for (int r = 0; r < 4; r++) s[ni][r] = 0.0f;

        #pragma unroll
        for (int kc = 0; kc < 4; kc++) {
            #pragma unroll
            for (int ni = 0; ni < 8; ni++) {
                int n = ni * 8 + gid;
                unsigned b0 = Kb[n * PQW + kc*8 + tig];
                unsigned b1 = Kb[n * PQW + kc*8 + tig + 4];
                mma_f16(s[ni][0], s[ni][1], s[ni][2], s[ni][3],
                        qf[kc][0], qf[kc][1], qf[kc][2], qf[kc][3], b0, b1);
            }
        }

        float rm0 = -1e30f, rm1 = -1e30f;
        #pragma unroll
        for (int ni = 0; ni < 8; ni++) {
            s[ni][0] *= scale; s[ni][1] *= scale;
            s[ni][2] *= scale; s[ni][3] *= scale;
            rm0 = fmaxf(rm0, fmaxf(s[ni][0], s[ni][1]));
            rm1 = fmaxf(rm1, fmaxf(s[ni][2], s[ni][3]));
        }
        rm0 = fmaxf(rm0, __shfl_xor_sync(0xffffffffu, rm0, 1));
        rm0 = fmaxf(rm0, __shfl_xor_sync(0xffffffffu, rm0, 2));
        rm1 = fmaxf(rm1, __shfl_xor_sync(0xffffffffu, rm1, 1));
        rm1 = fmaxf(rm1, __shfl_xor_sync(0xffffffffu, rm1, 2));

        float mn0 = fmaxf(mx0, rm0), mn1 = fmaxf(mx1, rm1);
        float f0 = __expf(mx0 - mn0), f1 = __expf(mx1 - mn1);
        mx0 = mn0; mx1 = mn1;

        float rs0 = 0.0f, rs1 = 0.0f;
        #pragma unroll
        for (int ni = 0; ni < 8; ni++) {
            float p0 = __expf(s[ni][0] - mn0);
            float p1 = __expf(s[ni][1] - mn0);
            float p2 = __expf(s[ni][2] - mn1);
            float p3 = __expf(s[ni][3] - mn1);
            rs0 += p0 + p1; rs1 += p2 + p3;
            __half2 h0 = __floats2half2_rn(p0, p1);
            __half2 h1 = __floats2half2_rn(p2, p3);
            Pw[gid * PQW + ni*4 + tig]       = *(unsigned*)&h0;
            Pw[(gid + 8) * PQW + ni*4 + tig] = *(unsigned*)&h1;
        }
        rs0 += __shfl_xor_sync(0xffffffffu, rs0, 1);
        rs0 += __shfl_xor_sync(0xffffffffu, rs0, 2);
        rs1 += __shfl_xor_sync(0xffffffffu, rs1, 1);
        rs1 += __shfl_xor_sync(0xffffffffu, rs1, 2);
        l0 = l0 * f0 + rs0;
        l1 = l1 * f1 + rs1;

        #pragma unroll
        for (int ni = 0; ni < 8; ni++) {
            o[ni][0] *= f0; o[ni][1] *= f0;
            o[ni][2] *= f1; o[ni][3] *= f1;
        }
        __syncwarp();

        #pragma unroll
        for (int kc = 0; kc < 4; kc++) {
            unsigned a0 = Pw[gid * PQW + kc*8 + tig];
            unsigned a1 = Pw[(gid + 8) * PQW + kc*8 + tig];
            unsigned a2 = Pw[gid * PQW + kc*8 + tig + 4];
            unsigned a3 = Pw[(gid + 8) * PQW + kc*8 + tig + 4];
            #pragma unroll
            for (int ni = 0; ni < 8; ni++) {
                int n = ni * 8 + gid;
                unsigned b0 = Vb[n * PQW + kc*8 + tig];
                unsigned b1 = Vb[n * PQW + kc*8 + tig + 4];
                mma_f16(o[ni][0], o[ni][1], o[ni][2], o[ni][3],
                        a0, a1, a2, a3, b0, b1);
            }
        }
        __syncwarp();
    }

    float i0 = 1.0f / l0, i1 = 1.0f / l1;
    __half2* c0row = (__half2*)(ctx + (size_t)(b * SS + row0 + m0r) * EE + h * DD);
    __half2* c1row = (__half2*)(ctx + (size_t)(b * SS + row0 + m0r + 8) * EE + h * DD);
    #pragma unroll
    for (int ni = 0; ni < 8; ni++) {
        int c2 = (ni * 8 + tig * 2) / 2;
        c0row[c2] = __floats2half2_rn(o[ni][0] * i0, o[ni][1] * i0);
        c1row[c2] = __floats2half2_rn(o[ni][2] * i1, o[ni][3] * i1);
    }
}

// ---------------- launch ------------------------------------------------------------
extern "C" void kernel_launch(void* const* d_in, const int* in_sizes, int n_in,
                              void* d_out, int out_size) {
    (void)in_sizes; (void)n_in; (void)out_size;
    const float* x     = (const float*)d_in[0];
    const float* ln1_g = (const float*)d_in[1];
    const float* ln1_b = (const float*)d_in[2];
    const float* wq    = (const float*)d_in[3];
    const float* bq    = (const float*)d_in[4];
    const float* wk    = (const float*)d_in[5];
    const float* bk    = (const float*)d_in[6];
    const float* wv    = (const float*)d_in[7];
    const float* bv    = (const float*)d_in[8];
    const float* wo    = (const float*)d_in[9];
    const float* bo    = (const float*)d_in[10];
    const float* w1    = (const float*)d_in[11];
    const float* b1    = (const float*)d_in[12];
    const float* w2    = (const float*)d_in[13];
    const float* b2    = (const float*)d_in[14];
    const float* ln2_g = (const float*)d_in[15];
    const float* ln2_b = (const float*)d_in[16];
    float* out = (float*)d_out;

    __half *y, *q, *k, *v, *vt, *ctx, *z, *hbuf;
    float *y2;
    __half *wtq, *wtk, *wtv, *wto, *wt1, *wt2;
    cudaGetSymbolAddress((void**)&y,    g_y);
    cudaGetSymbolAddress((void**)&q,    g_q);
    cudaGetSymbolAddress((void**)&k,    g_k);
    cudaGetSymbolAddress((void**)&v,    g_v);
    cudaGetSymbolAddress((void**)&vt,   g_vt);
    cudaGetSymbolAddress((void**)&ctx,  g_ctx);
    cudaGetSymbolAddress((void**)&y2,   g_y2);
    cudaGetSymbolAddress((void**)&z,    g_z);
    cudaGetSymbolAddress((void**)&hbuf, g_h);
    cudaGetSymbolAddress((void**)&wtq,  g_wtq);
    cudaGetSymbolAddress((void**)&wtk,  g_wtk);
    cudaGetSymbolAddress((void**)&wtv,  g_wtv);
    cudaGetSymbolAddress((void**)&wto,  g_wto);
    cudaGetSymbolAddress((void**)&wt1,  g_wt1);
    cudaGetSymbolAddress((void**)&wt2,  g_wt2);

    static bool attr_done = false;
    if (!attr_done) {
        cudaFuncSetAttribute((const void*)mmh_tc<false,true,false>,
                             cudaFuncAttributeMaxDynamicSharedMemorySize, SM_MMH);
        cudaFuncSetAttribute((const void*)mmh_tc<true,false,true>,
                             cudaFuncAttributeMaxDynamicSharedMemorySize, SM_MMH);
        cudaFuncSetAttribute((const void*)qkvh_tc,
                             cudaFuncAttributeMaxDynamicSharedMemorySize, SM_MMH);
        cudaFuncSetAttribute((const void*)flash_h,
                             cudaFuncAttributeMaxDynamicSharedMemorySize, SM_FLASH);
        attr_done = true;
    }

    dim3 blk128(128);
    dim3 blk256(256);
    dim3 tb(32, 8);

    // 0. convert+transpose weights to half [N][K]
    cvt_t4<<<dim3(EE/32, EE/32, 4), tb>>>(wq, wtq, wk, wtk, wv, wtv, wo, wto);
    cvt_tff<<<dim3(FF/32, FF/32, 2), tb>>>(w1, wt1, w2, wt2);

    // 1. y = LN1(x)
    ln_kernel<<<MM, blk256>>>(x, ln1_g, ln1_b, y);

    // 2. q,k,v projections
    dim3 g_qkv(EE / 128, MM / 64, 3);
    qkvh_tc<<<g_qkv, blk128, SM_MMH>>>(y, wtq, bq, q, wtk, bk, k, wtv, bv, v);

    // 2b. transpose V per head
    vtrans<<<dim3(SS/32, DD/32, BH), tb>>>(v, vt);

    // 3. flash attention (fp16)
    dim3 g_fl(SS / FM, BH);
    flash_h<<<g_fl, blk256, SM_FLASH>>>(q, k, vt, ctx);

    // 4. y2 = x + ctx @ wo + bo
    dim3 g_e(EE / 128, MM / 64);
    mmh_tc<false, true, false><<<g_e, blk128, SM_MMH>>>(ctx, wto, bo, x, y2, EE, EE);

    // 5. z = LN2(y2)
    ln_kernel<<<MM, blk256>>>(y2, ln2_g, ln2_b, z);

    // 6. h = gelu(z @ w1 + b1)
    dim3 g_ff(FF / 128, MM / 64);
    mmh_tc<true, false, true><<<g_ff, blk128, SM_MMH>>>(z, wt1, b1, nullptr, hbuf, FF, EE);

    // 7. out = y2 + h @ w2 + b2
    mmh_tc<false, true, false><<<g_e, blk128, SM_MMH>>>(hbuf, wt2, b2, y2, out, EE, FF);
}